// round 3
// baseline (speedup 1.0000x reference)
#include <cuda_runtime.h>
#include <cstdint>

#define BATCH 2
#define SEQ   2048
#define EMB   2048
#define HQ    16
#define HKV   4
#define HD    128
#define KVW   (HKV * HD)        // 512
#define MROWS (BATCH * SEQ)     // 4096

// ---------------------------------------------------------------------------
// Scratch (no cudaMalloc allowed — __device__ globals are the sanctioned path)
// ---------------------------------------------------------------------------
__device__ float g_q[(size_t)MROWS * EMB];   // 32 MB
__device__ float g_k[(size_t)MROWS * KVW];   // 8 MB
__device__ float g_v[(size_t)MROWS * KVW];   // 8 MB
__device__ float g_o[(size_t)MROWS * EMB];   // 32 MB

// ---------------------------------------------------------------------------
// SGEMM: C[M,N] = A[M,K] @ B[K,N] (+ bias[N]) ; 128x128 tile, BK=8,
// 256 threads, 8x8 per thread. Split-column mapping keeps smem conflicts <=2-way
// and global stores coalesced.
// ---------------------------------------------------------------------------
__global__ __launch_bounds__(256) void sgemm_bias_kernel(
    const float* __restrict__ A, const float* __restrict__ B,
    const float* __restrict__ bias, float* __restrict__ C,
    int M, int N, int K)
{
    __shared__ float As[8][128];   // transposed A tile: As[k][m]
    __shared__ float Bs[8][128];   // Bs[k][n]

    const int tid   = threadIdx.x;
    const int mBase = blockIdx.y * 128;
    const int nBase = blockIdx.x * 128;
    const int tRow  = tid >> 4;        // 0..15 -> 8 M rows
    const int tCol  = tid & 15;        // 0..15 -> cols tCol*4 and 64+tCol*4

    const int aRow = tid >> 1;         // 0..127
    const int aCol = (tid & 1) << 2;   // 0 or 4
    const int bRow = tid >> 5;         // 0..7
    const int bCol = (tid & 31) << 2;  // 0..124

    const float* Aptr = A + (size_t)(mBase + aRow) * K + aCol;
    const float* Bptr = B + (size_t)bRow * N + nBase + bCol;

    float acc[8][8];
#pragma unroll
    for (int i = 0; i < 8; i++)
#pragma unroll
        for (int j = 0; j < 8; j++) acc[i][j] = 0.f;

    for (int k0 = 0; k0 < K; k0 += 8) {
        float4 a  = *(const float4*)(Aptr + k0);
        float4 bb = *(const float4*)(Bptr + (size_t)k0 * N);
        As[aCol + 0][aRow] = a.x;
        As[aCol + 1][aRow] = a.y;
        As[aCol + 2][aRow] = a.z;
        As[aCol + 3][aRow] = a.w;
        *(float4*)&Bs[bRow][bCol] = bb;
        __syncthreads();

#pragma unroll
        for (int kk = 0; kk < 8; kk++) {
            float ar[8], br[8];
            *(float4*)&ar[0] = *(const float4*)&As[kk][tRow * 8];
            *(float4*)&ar[4] = *(const float4*)&As[kk][tRow * 8 + 4];
            *(float4*)&br[0] = *(const float4*)&Bs[kk][tCol * 4];
            *(float4*)&br[4] = *(const float4*)&Bs[kk][64 + tCol * 4];
#pragma unroll
            for (int i = 0; i < 8; i++)
#pragma unroll
                for (int j = 0; j < 8; j++)
                    acc[i][j] = fmaf(ar[i], br[j], acc[i][j]);
        }
        __syncthreads();
    }

    float b0[4] = {0.f, 0.f, 0.f, 0.f}, b1[4] = {0.f, 0.f, 0.f, 0.f};
    if (bias != nullptr) {
        float4 t0 = *(const float4*)&bias[nBase + tCol * 4];
        float4 t1 = *(const float4*)&bias[nBase + 64 + tCol * 4];
        b0[0] = t0.x; b0[1] = t0.y; b0[2] = t0.z; b0[3] = t0.w;
        b1[0] = t1.x; b1[1] = t1.y; b1[2] = t1.z; b1[3] = t1.w;
    }

#pragma unroll
    for (int i = 0; i < 8; i++) {
        float* cp = C + (size_t)(mBase + tRow * 8 + i) * N + nBase;
        float4 o0 = make_float4(acc[i][0] + b0[0], acc[i][1] + b0[1],
                                acc[i][2] + b0[2], acc[i][3] + b0[3]);
        float4 o1 = make_float4(acc[i][4] + b1[0], acc[i][5] + b1[1],
                                acc[i][6] + b1[2], acc[i][7] + b1[3]);
        *(float4*)&cp[tCol * 4]      = o0;
        *(float4*)&cp[64 + tCol * 4] = o1;
    }
}

// ---------------------------------------------------------------------------
// Flash attention (non-causal, full softmax), fp32.
// BM = BN = 64, d = 128, 256 threads (16x16), 4x4 S microtile per thread.
// P tile aliases the K tile (K is dead after S) -> 99 KB smem -> 2 CTAs/SM.
// ---------------------------------------------------------------------------
#define QSTR 132                       // padded row stride (floats), 2-way max
#define PSTR 68
#define FA_SMEM_BYTES (3 * 64 * QSTR * 4)   // 101376 B

__global__ __launch_bounds__(256, 2) void flash_attn_kernel(
    const float* __restrict__ q, const float* __restrict__ k,
    const float* __restrict__ v, float* __restrict__ o)
{
    extern __shared__ float sm[];
    float* Qs = sm;                  // 64 x QSTR
    float* Ks = sm + 64 * QSTR;      // 64 x QSTR
    float* Vs = sm + 2 * 64 * QSTR;  // 64 x QSTR
    float* Ps = Ks;                  // alias: P overwrites K after S

    const int tid = threadIdx.x;
    const int ty  = tid >> 4;        // 0..15 -> 4 Q rows
    const int tx  = tid & 15;        // 0..15 -> 4 K cols / 8 d cols (split)
    const int q0  = blockIdx.x * 64;
    const int h   = blockIdx.y;
    const int b   = blockIdx.z;
    const int g   = h >> 2;          // kv head

    const float scale = 0.088388347648318447f;  // 1/sqrt(128)

    const float* qbase = q + (size_t)b * SEQ * EMB + (size_t)h * HD;
    const float* kbase = k + (size_t)b * SEQ * KVW + (size_t)g * HD;
    const float* vbase = v + (size_t)b * SEQ * KVW + (size_t)g * HD;

    // Load Q tile (pre-scaled)
    for (int idx = tid; idx < 64 * 32; idx += 256) {
        int r  = idx >> 5;
        int c4 = (idx & 31) << 2;
        float4 val = *(const float4*)(qbase + (size_t)(q0 + r) * EMB + c4);
        val.x *= scale; val.y *= scale; val.z *= scale; val.w *= scale;
        *(float4*)&Qs[r * QSTR + c4] = val;
    }

    float m_i[4], l_i[4], oacc[4][8];
#pragma unroll
    for (int r = 0; r < 4; r++) {
        m_i[r] = -1e30f; l_i[r] = 0.f;
#pragma unroll
        for (int c = 0; c < 8; c++) oacc[r][c] = 0.f;
    }

    for (int kt = 0; kt < SEQ / 64; kt++) {
        __syncthreads();   // prior iter's P/V reads complete before overwrite
        const int kr0 = kt * 64;
        for (int idx = tid; idx < 64 * 32; idx += 256) {
            int r  = idx >> 5;
            int c4 = (idx & 31) << 2;
            *(float4*)&Ks[r * QSTR + c4] =
                *(const float4*)(kbase + (size_t)(kr0 + r) * KVW + c4);
            *(float4*)&Vs[r * QSTR + c4] =
                *(const float4*)(vbase + (size_t)(kr0 + r) * KVW + c4);
        }
        __syncthreads();

        // S = Qs @ Ks^T  (4x4 per thread)
        float s[4][4];
#pragma unroll
        for (int r = 0; r < 4; r++)
#pragma unroll
            for (int c = 0; c < 4; c++) s[r][c] = 0.f;

#pragma unroll 4
        for (int d = 0; d < HD; d += 4) {
            float qr[4][4], kr[4][4];
#pragma unroll
            for (int r = 0; r < 4; r++)
                *(float4*)qr[r] = *(const float4*)&Qs[(ty * 4 + r) * QSTR + d];
#pragma unroll
            for (int c = 0; c < 4; c++)
                *(float4*)kr[c] = *(const float4*)&Ks[(tx * 4 + c) * QSTR + d];
#pragma unroll
            for (int r = 0; r < 4; r++)
#pragma unroll
                for (int c = 0; c < 4; c++) {
                    s[r][c] = fmaf(qr[r][0], kr[c][0], s[r][c]);
                    s[r][c] = fmaf(qr[r][1], kr[c][1], s[r][c]);
                    s[r][c] = fmaf(qr[r][2], kr[c][2], s[r][c]);
                    s[r][c] = fmaf(qr[r][3], kr[c][3], s[r][c]);
                }
        }

        __syncthreads();   // all threads done reading Ks -> safe to write Ps

        // Online softmax + store P
#pragma unroll
        for (int r = 0; r < 4; r++) {
            float mx = fmaxf(fmaxf(s[r][0], s[r][1]), fmaxf(s[r][2], s[r][3]));
#pragma unroll
            for (int off = 8; off >= 1; off >>= 1)
                mx = fmaxf(mx, __shfl_xor_sync(0xffffffffu, mx, off));
            float mnew  = fmaxf(m_i[r], mx);
            float alpha = __expf(m_i[r] - mnew);
            m_i[r] = mnew;
            float rs = 0.f;
#pragma unroll
            for (int c = 0; c < 4; c++) {
                s[r][c] = __expf(s[r][c] - mnew);
                rs += s[r][c];
            }
#pragma unroll
            for (int off = 8; off >= 1; off >>= 1)
                rs += __shfl_xor_sync(0xffffffffu, rs, off);
            l_i[r] = l_i[r] * alpha + rs;
#pragma unroll
            for (int c = 0; c < 8; c++) oacc[r][c] *= alpha;
            *(float4*)&Ps[(ty * 4 + r) * PSTR + tx * 4] =
                make_float4(s[r][0], s[r][1], s[r][2], s[r][3]);
        }
        __syncthreads();   // P visible to all

        // O += P @ V  (columns tx*4..+3 and 64+tx*4..+3)
#pragma unroll 2
        for (int j = 0; j < 64; j += 4) {
            float pr[4][4];
#pragma unroll
            for (int r = 0; r < 4; r++)
                *(float4*)pr[r] = *(const float4*)&Ps[(ty * 4 + r) * PSTR + j];
#pragma unroll
            for (int jj = 0; jj < 4; jj++) {
                float4 v0 = *(const float4*)&Vs[(j + jj) * QSTR + tx * 4];
                float4 v1 = *(const float4*)&Vs[(j + jj) * QSTR + 64 + tx * 4];
#pragma unroll
                for (int r = 0; r < 4; r++) {
                    float pw = pr[r][jj];
                    oacc[r][0] = fmaf(pw, v0.x, oacc[r][0]);
                    oacc[r][1] = fmaf(pw, v0.y, oacc[r][1]);
                    oacc[r][2] = fmaf(pw, v0.z, oacc[r][2]);
                    oacc[r][3] = fmaf(pw, v0.w, oacc[r][3]);
                    oacc[r][4] = fmaf(pw, v1.x, oacc[r][4]);
                    oacc[r][5] = fmaf(pw, v1.y, oacc[r][5]);
                    oacc[r][6] = fmaf(pw, v1.z, oacc[r][6]);
                    oacc[r][7] = fmaf(pw, v1.w, oacc[r][7]);
                }
            }
        }
    }

    // Finalize and write out
#pragma unroll
    for (int r = 0; r < 4; r++) {
        float inv = 1.0f / l_i[r];
        float* orow = o + (size_t)(b * SEQ + q0 + ty * 4 + r) * EMB + h * HD;
        float4 o0 = make_float4(oacc[r][0] * inv, oacc[r][1] * inv,
                                oacc[r][2] * inv, oacc[r][3] * inv);
        float4 o1 = make_float4(oacc[r][4] * inv, oacc[r][5] * inv,
                                oacc[r][6] * inv, oacc[r][7] * inv);
        *(float4*)&orow[tx * 4]      = o0;
        *(float4*)&orow[64 + tx * 4] = o1;
    }
}

// ---------------------------------------------------------------------------
// kernel_launch: qkv GEMMs -> flash attention -> output GEMM
// ---------------------------------------------------------------------------
extern "C" void kernel_launch(void* const* d_in, const int* in_sizes, int n_in,
                              void* d_out, int out_size)
{
    const float* x  = (const float*)d_in[0];
    const float* Wq = (const float*)d_in[1];
    const float* bq = (const float*)d_in[2];
    const float* Wk = (const float*)d_in[3];
    const float* bk = (const float*)d_in[4];
    const float* Wv = (const float*)d_in[5];
    const float* bv = (const float*)d_in[6];
    const float* Wo = (const float*)d_in[7];
    float* out = (float*)d_out;

    float *pq, *pk, *pv, *po;
    cudaGetSymbolAddress((void**)&pq, g_q);
    cudaGetSymbolAddress((void**)&pk, g_k);
    cudaGetSymbolAddress((void**)&pv, g_v);
    cudaGetSymbolAddress((void**)&po, g_o);

    cudaFuncSetAttribute(flash_attn_kernel,
                         cudaFuncAttributeMaxDynamicSharedMemorySize,
                         FA_SMEM_BYTES);

    dim3 blk(256);

    // QKV projections
    sgemm_bias_kernel<<<dim3(EMB / 128, MROWS / 128), blk>>>(
        x, Wq, bq, pq, MROWS, EMB, EMB);
    sgemm_bias_kernel<<<dim3(KVW / 128, MROWS / 128), blk>>>(
        x, Wk, bk, pk, MROWS, KVW, EMB);
    sgemm_bias_kernel<<<dim3(KVW / 128, MROWS / 128), blk>>>(
        x, Wv, bv, pv, MROWS, KVW, EMB);

    // Attention
    flash_attn_kernel<<<dim3(SEQ / 64, HQ, BATCH), blk, FA_SMEM_BYTES>>>(
        pq, pk, pv, po);

    // Output projection (no bias)
    sgemm_bias_kernel<<<dim3(EMB / 128, MROWS / 128), blk>>>(
        po, Wo, (const float*)nullptr, out, MROWS, EMB, EMB);
}

// round 5
// speedup vs baseline: 1.4347x; 1.4347x over previous
#include <cuda_runtime.h>
#include <cuda_bf16.h>
#include <cstdint>

#define BATCH 2
#define SEQ   2048
#define EMB   2048
#define HQ    16
#define HKV   4
#define HD    128
#define KVW   (HKV * HD)        // 512
#define MROWS (BATCH * SEQ)     // 4096

// ---------------------------------------------------------------------------
// PTX helpers — ONLY non-arch-suffixed instructions (compute_103-safe):
// cp.async (sm_80), ldmatrix (sm_75), mma.sync bf16 (sm_80).
// ---------------------------------------------------------------------------
__device__ __forceinline__ uint32_t smem_u32(const void* p) {
    uint32_t a;
    asm("{ .reg .u64 t; cvta.to.shared.u64 t, %1; cvt.u32.u64 %0, t; }"
        : "=r"(a) : "l"(p));
    return a;
}

__device__ __forceinline__ void cp16(uint32_t saddr, const void* gaddr) {
    asm volatile("cp.async.cg.shared.global [%0], [%1], 16;"
                 :: "r"(saddr), "l"(gaddr));
}

__device__ __forceinline__ void ldmx4(uint32_t* r, uint32_t addr) {
    asm volatile("ldmatrix.sync.aligned.m8n8.x4.shared.b16 {%0,%1,%2,%3}, [%4];"
                 : "=r"(r[0]), "=r"(r[1]), "=r"(r[2]), "=r"(r[3]) : "r"(addr));
}

__device__ __forceinline__ void mma16816(float* c, const uint32_t* a,
                                         const uint32_t* b) {
    asm volatile(
        "mma.sync.aligned.m16n8k16.row.col.f32.bf16.bf16.f32 "
        "{%0,%1,%2,%3}, {%4,%5,%6,%7}, {%8,%9}, {%0,%1,%2,%3};"
        : "+f"(c[0]), "+f"(c[1]), "+f"(c[2]), "+f"(c[3])
        : "r"(a[0]), "r"(a[1]), "r"(a[2]), "r"(a[3]), "r"(b[0]), "r"(b[1]));
}

// ---------------------------------------------------------------------------
// Device scratch (no cudaMalloc allowed)
// ---------------------------------------------------------------------------
__device__ float g_q[(size_t)MROWS * EMB];   // 32 MB
__device__ float g_k[(size_t)MROWS * KVW];   // 8 MB
__device__ float g_v[(size_t)MROWS * KVW];   // 8 MB
__device__ float g_o[(size_t)MROWS * EMB];   // 32 MB

__device__ __nv_bfloat16 g_xhi[(size_t)MROWS * EMB];
__device__ __nv_bfloat16 g_xlo[(size_t)MROWS * EMB];
__device__ __nv_bfloat16 g_ohi[(size_t)MROWS * EMB];
__device__ __nv_bfloat16 g_olo[(size_t)MROWS * EMB];
__device__ __nv_bfloat16 g_wqh[(size_t)EMB * EMB];
__device__ __nv_bfloat16 g_wql[(size_t)EMB * EMB];
__device__ __nv_bfloat16 g_wkh[(size_t)KVW * EMB];
__device__ __nv_bfloat16 g_wkl[(size_t)KVW * EMB];
__device__ __nv_bfloat16 g_wvh[(size_t)KVW * EMB];
__device__ __nv_bfloat16 g_wvl[(size_t)KVW * EMB];
__device__ __nv_bfloat16 g_woh[(size_t)EMB * EMB];
__device__ __nv_bfloat16 g_wol[(size_t)EMB * EMB];

// ---------------------------------------------------------------------------
// fp32 -> bf16 hi/lo split (elementwise)
// ---------------------------------------------------------------------------
__global__ __launch_bounds__(256) void split_kernel(
    const float* __restrict__ x, __nv_bfloat16* __restrict__ hi,
    __nv_bfloat16* __restrict__ lo, int n)
{
    int i = (blockIdx.x * 256 + threadIdx.x) * 4;
    if (i >= n) return;
    float4 v = *(const float4*)(x + i);
    __nv_bfloat16 h[4], l[4];
    float vv[4] = {v.x, v.y, v.z, v.w};
#pragma unroll
    for (int j = 0; j < 4; j++) {
        h[j] = __float2bfloat16(vv[j]);
        l[j] = __float2bfloat16(vv[j] - __bfloat162float(h[j]));
    }
    *(uint2*)(hi + i) = *(uint2*)h;
    *(uint2*)(lo + i) = *(uint2*)l;
}

// ---------------------------------------------------------------------------
// Transpose + split: W [K,N] fp32 -> Thi/Tlo [N,K] bf16
// ---------------------------------------------------------------------------
__global__ __launch_bounds__(256) void transpose_split_kernel(
    const float* __restrict__ W, __nv_bfloat16* __restrict__ Thi,
    __nv_bfloat16* __restrict__ Tlo, int K, int N)
{
    __shared__ float tile[32][33];
    const int tx = threadIdx.x, ty = threadIdx.y;
    const int nBase = blockIdx.x * 32, kBase = blockIdx.y * 32;
#pragma unroll
    for (int i = 0; i < 4; i++)
        tile[ty + 8 * i][tx] = W[(size_t)(kBase + ty + 8 * i) * N + nBase + tx];
    __syncthreads();
#pragma unroll
    for (int i = 0; i < 4; i++) {
        float v = tile[tx][ty + 8 * i];
        __nv_bfloat16 h = __float2bfloat16(v);
        __nv_bfloat16 l = __float2bfloat16(v - __bfloat162float(h));
        size_t idx = (size_t)(nBase + ty + 8 * i) * K + kBase + tx;
        Thi[idx] = h;
        Tlo[idx] = l;
    }
}

// ---------------------------------------------------------------------------
// Tensor-core GEMM via mma.sync (HMMA):
//   C[M,N] fp32 = (Ahi+Alo)[M,K] @ (Bhi+Blo)[N,K]^T (+ bias)
// CTA tile 128x128, 8 warps (2Mx4N), warp tile 64x32, K-chunk 64 bf16,
// SW128-swizzled smem, double-buffered cp.async.
// ---------------------------------------------------------------------------
#define GT_STAGE_BYTES 65536                    // 4 tiles x 128 x 128B
#define GT_SMEM_BYTES  (2 * GT_STAGE_BYTES)     // 131072

__global__ __launch_bounds__(256) void gemm_mma_kernel(
    const __nv_bfloat16* __restrict__ Ahi, const __nv_bfloat16* __restrict__ Alo,
    const __nv_bfloat16* __restrict__ Bhi, const __nv_bfloat16* __restrict__ Blo,
    const float* __restrict__ bias, float* __restrict__ C,
    int M, int N, int K)
{
    extern __shared__ char gsm[];
    const uint32_t sb = smem_u32(gsm);

    const int tid   = threadIdx.x;
    const int wid   = tid >> 5;
    const int lane  = tid & 31;
    const int warpM = wid & 1;            // 0..1 -> 64 rows each
    const int warpN = wid >> 1;           // 0..3 -> 32 cols each
    const int mBase = blockIdx.y * 128;
    const int nBase = blockIdx.x * 128;
    const int nCh   = K >> 6;             // chunks of 64 bf16

    // ldmatrix per-lane offsets (within a 16x16 b16 tile, 128B rows)
    const int aRowOff = lane & 15;                          // rows m..m+15
    const int aKOff   = (lane >> 4) << 4;                   // 0 / 16 bytes
    const int bRowOff = (lane & 7) + ((lane >> 4) << 3);    // n..n+15
    const int bKOff   = ((lane >> 3) & 1) << 4;             // 0 / 16 bytes

    auto swz = [](uint32_t off) { return off ^ ((off >> 3) & 0x70); };

    auto load_chunk = [&](int ci, int buf) {
        const int k0 = ci << 6;                     // bf16 elements
        const uint32_t sbase = sb + (uint32_t)buf * GT_STAGE_BYTES;
#pragma unroll
        for (int t = 0; t < 4; t++) {
            int idx = tid + t * 256;                // 0..1023
            int row = idx >> 3;                     // 0..127
            int gr  = idx & 7;                      // 16B granule
            uint32_t off = (uint32_t)(row * 128 + gr * 16);
            uint32_t sw  = off ^ ((off >> 3) & 0x70);
            size_t aoff = (size_t)(mBase + row) * K + k0 + gr * 8;
            size_t boff = (size_t)(nBase + row) * K + k0 + gr * 8;
            cp16(sbase +         sw, Ahi + aoff);
            cp16(sbase + 16384 + sw, Alo + aoff);
            cp16(sbase + 32768 + sw, Bhi + boff);
            cp16(sbase + 49152 + sw, Blo + boff);
        }
        asm volatile("cp.async.commit_group;" ::: "memory");
    };

    float acc[4][4][4];
#pragma unroll
    for (int mt = 0; mt < 4; mt++)
#pragma unroll
        for (int nt = 0; nt < 4; nt++)
#pragma unroll
            for (int i = 0; i < 4; i++) acc[mt][nt][i] = 0.f;

    load_chunk(0, 0);
    load_chunk(1, 1);

    for (int ci = 0; ci < nCh; ci++) {
        const int buf = ci & 1;
        if (ci + 1 < nCh)
            asm volatile("cp.async.wait_group 1;" ::: "memory");
        else
            asm volatile("cp.async.wait_group 0;" ::: "memory");
        __syncthreads();

        const uint32_t sbase = sb + (uint32_t)buf * GT_STAGE_BYTES;
        const uint32_t ahB = sbase;
        const uint32_t alB = sbase + 16384;
        const uint32_t bhB = sbase + 32768;
        const uint32_t blB = sbase + 49152;

#pragma unroll
        for (int ks = 0; ks < 4; ks++) {
            const int kByte = ks * 32;
            uint32_t ah[4][4], al[4][4];
#pragma unroll
            for (int mt = 0; mt < 4; mt++) {
                uint32_t off = (uint32_t)((warpM * 64 + mt * 16 + aRowOff) * 128
                                          + kByte + aKOff);
                uint32_t s = swz(off);
                ldmx4(ah[mt], ahB + s);
                ldmx4(al[mt], alB + s);
            }
            uint32_t bh[2][4], bl[2][4];
#pragma unroll
            for (int p = 0; p < 2; p++) {
                uint32_t off = (uint32_t)((warpN * 32 + p * 16 + bRowOff) * 128
                                          + kByte + bKOff);
                uint32_t s = swz(off);
                ldmx4(bh[p], bhB + s);
                ldmx4(bl[p], blB + s);
            }
#pragma unroll
            for (int mt = 0; mt < 4; mt++)
#pragma unroll
                for (int nt = 0; nt < 4; nt++) {
                    const uint32_t* bhf = &bh[nt >> 1][(nt & 1) * 2];
                    const uint32_t* blf = &bl[nt >> 1][(nt & 1) * 2];
                    mma16816(acc[mt][nt], ah[mt], bhf);   // hi*hi
                    mma16816(acc[mt][nt], ah[mt], blf);   // hi*lo
                    mma16816(acc[mt][nt], al[mt], bhf);   // lo*hi
                }
        }
        __syncthreads();   // done reading buf before refilling it
        if (ci + 2 < nCh) load_chunk(ci + 2, buf);
    }

    // Epilogue: registers -> gmem (+bias), float2 stores
    const int mW = mBase + warpM * 64;
    const int nW = nBase + warpN * 32;
#pragma unroll
    for (int mt = 0; mt < 4; mt++) {
#pragma unroll
        for (int nt = 0; nt < 4; nt++) {
            int r0 = mW + mt * 16 + (lane >> 2);
            int c  = nW + nt * 8 + (lane & 3) * 2;
            float bx = 0.f, by = 0.f;
            if (bias != nullptr) {
                float2 bv = *(const float2*)(bias + c);
                bx = bv.x; by = bv.y;
            }
            *(float2*)(C + (size_t)r0 * N + c) =
                make_float2(acc[mt][nt][0] + bx, acc[mt][nt][1] + by);
            *(float2*)(C + (size_t)(r0 + 8) * N + c) =
                make_float2(acc[mt][nt][2] + bx, acc[mt][nt][3] + by);
        }
    }
}

// ---------------------------------------------------------------------------
// Flash attention (byte-identical to R3's passing version)
// ---------------------------------------------------------------------------
#define QSTR 132
#define PSTR 68
#define FA_SMEM_BYTES (3 * 64 * QSTR * 4)   // 101376 B

__global__ __launch_bounds__(256, 2) void flash_attn_kernel(
    const float* __restrict__ q, const float* __restrict__ k,
    const float* __restrict__ v, float* __restrict__ o)
{
    extern __shared__ float sm[];
    float* Qs = sm;
    float* Ks = sm + 64 * QSTR;
    float* Vs = sm + 2 * 64 * QSTR;
    float* Ps = Ks;

    const int tid = threadIdx.x;
    const int ty  = tid >> 4;
    const int tx  = tid & 15;
    const int q0  = blockIdx.x * 64;
    const int h   = blockIdx.y;
    const int b   = blockIdx.z;
    const int g   = h >> 2;

    const float scale = 0.088388347648318447f;

    const float* qbase = q + (size_t)b * SEQ * EMB + (size_t)h * HD;
    const float* kbase = k + (size_t)b * SEQ * KVW + (size_t)g * HD;
    const float* vbase = v + (size_t)b * SEQ * KVW + (size_t)g * HD;

    for (int idx = tid; idx < 64 * 32; idx += 256) {
        int r  = idx >> 5;
        int c4 = (idx & 31) << 2;
        float4 val = *(const float4*)(qbase + (size_t)(q0 + r) * EMB + c4);
        val.x *= scale; val.y *= scale; val.z *= scale; val.w *= scale;
        *(float4*)&Qs[r * QSTR + c4] = val;
    }

    float m_i[4], l_i[4], oacc[4][8];
#pragma unroll
    for (int r = 0; r < 4; r++) {
        m_i[r] = -1e30f; l_i[r] = 0.f;
#pragma unroll
        for (int c = 0; c < 8; c++) oacc[r][c] = 0.f;
    }

    for (int kt = 0; kt < SEQ / 64; kt++) {
        __syncthreads();
        const int kr0 = kt * 64;
        for (int idx = tid; idx < 64 * 32; idx += 256) {
            int r  = idx >> 5;
            int c4 = (idx & 31) << 2;
            *(float4*)&Ks[r * QSTR + c4] =
                *(const float4*)(kbase + (size_t)(kr0 + r) * KVW + c4);
            *(float4*)&Vs[r * QSTR + c4] =
                *(const float4*)(vbase + (size_t)(kr0 + r) * KVW + c4);
        }
        __syncthreads();

        float s[4][4];
#pragma unroll
        for (int r = 0; r < 4; r++)
#pragma unroll
            for (int c = 0; c < 4; c++) s[r][c] = 0.f;

#pragma unroll 4
        for (int d = 0; d < HD; d += 4) {
            float qr[4][4], kr[4][4];
#pragma unroll
            for (int r = 0; r < 4; r++)
                *(float4*)qr[r] = *(const float4*)&Qs[(ty * 4 + r) * QSTR + d];
#pragma unroll
            for (int c = 0; c < 4; c++)
                *(float4*)kr[c] = *(const float4*)&Ks[(tx * 4 + c) * QSTR + d];
#pragma unroll
            for (int r = 0; r < 4; r++)
#pragma unroll
                for (int c = 0; c < 4; c++) {
                    s[r][c] = fmaf(qr[r][0], kr[c][0], s[r][c]);
                    s[r][c] = fmaf(qr[r][1], kr[c][1], s[r][c]);
                    s[r][c] = fmaf(qr[r][2], kr[c][2], s[r][c]);
                    s[r][c] = fmaf(qr[r][3], kr[c][3], s[r][c]);
                }
        }

        __syncthreads();

#pragma unroll
        for (int r = 0; r < 4; r++) {
            float mx = fmaxf(fmaxf(s[r][0], s[r][1]), fmaxf(s[r][2], s[r][3]));
#pragma unroll
            for (int off = 8; off >= 1; off >>= 1)
                mx = fmaxf(mx, __shfl_xor_sync(0xffffffffu, mx, off));
            float mnew  = fmaxf(m_i[r], mx);
            float alpha = __expf(m_i[r] - mnew);
            m_i[r] = mnew;
            float rs = 0.f;
#pragma unroll
            for (int c = 0; c < 4; c++) {
                s[r][c] = __expf(s[r][c] - mnew);
                rs += s[r][c];
            }
#pragma unroll
            for (int off = 8; off >= 1; off >>= 1)
                rs += __shfl_xor_sync(0xffffffffu, rs, off);
            l_i[r] = l_i[r] * alpha + rs;
#pragma unroll
            for (int c = 0; c < 8; c++) oacc[r][c] *= alpha;
            *(float4*)&Ps[(ty * 4 + r) * PSTR + tx * 4] =
                make_float4(s[r][0], s[r][1], s[r][2], s[r][3]);
        }
        __syncthreads();

#pragma unroll 2
        for (int j = 0; j < 64; j += 4) {
            float pr[4][4];
#pragma unroll
            for (int r = 0; r < 4; r++)
                *(float4*)pr[r] = *(const float4*)&Ps[(ty * 4 + r) * PSTR + j];
#pragma unroll
            for (int jj = 0; jj < 4; jj++) {
                float4 v0 = *(const float4*)&Vs[(j + jj) * QSTR + tx * 4];
                float4 v1 = *(const float4*)&Vs[(j + jj) * QSTR + 64 + tx * 4];
#pragma unroll
                for (int r = 0; r < 4; r++) {
                    float pw = pr[r][jj];
                    oacc[r][0] = fmaf(pw, v0.x, oacc[r][0]);
                    oacc[r][1] = fmaf(pw, v0.y, oacc[r][1]);
                    oacc[r][2] = fmaf(pw, v0.z, oacc[r][2]);
                    oacc[r][3] = fmaf(pw, v0.w, oacc[r][3]);
                    oacc[r][4] = fmaf(pw, v1.x, oacc[r][4]);
                    oacc[r][5] = fmaf(pw, v1.y, oacc[r][5]);
                    oacc[r][6] = fmaf(pw, v1.z, oacc[r][6]);
                    oacc[r][7] = fmaf(pw, v1.w, oacc[r][7]);
                }
            }
        }
    }

#pragma unroll
    for (int r = 0; r < 4; r++) {
        float inv = 1.0f / l_i[r];
        float* orow = o + (size_t)(b * SEQ + q0 + ty * 4 + r) * EMB + h * HD;
        float4 o0 = make_float4(oacc[r][0] * inv, oacc[r][1] * inv,
                                oacc[r][2] * inv, oacc[r][3] * inv);
        float4 o1 = make_float4(oacc[r][4] * inv, oacc[r][5] * inv,
                                oacc[r][6] * inv, oacc[r][7] * inv);
        *(float4*)&orow[tx * 4]      = o0;
        *(float4*)&orow[64 + tx * 4] = o1;
    }
}

// ---------------------------------------------------------------------------
// kernel_launch
// ---------------------------------------------------------------------------
extern "C" void kernel_launch(void* const* d_in, const int* in_sizes, int n_in,
                              void* d_out, int out_size)
{
    const float* x  = (const float*)d_in[0];
    const float* Wq = (const float*)d_in[1];
    const float* bq = (const float*)d_in[2];
    const float* Wk = (const float*)d_in[3];
    const float* bk = (const float*)d_in[4];
    const float* Wv = (const float*)d_in[5];
    const float* bv = (const float*)d_in[6];
    const float* Wo = (const float*)d_in[7];
    float* out = (float*)d_out;

    float *pq, *pk, *pv, *po;
    __nv_bfloat16 *pxh, *pxl, *poh, *pol;
    __nv_bfloat16 *pwqh, *pwql, *pwkh, *pwkl, *pwvh, *pwvl, *pwoh, *pwol;
    cudaGetSymbolAddress((void**)&pq,  g_q);
    cudaGetSymbolAddress((void**)&pk,  g_k);
    cudaGetSymbolAddress((void**)&pv,  g_v);
    cudaGetSymbolAddress((void**)&po,  g_o);
    cudaGetSymbolAddress((void**)&pxh, g_xhi);
    cudaGetSymbolAddress((void**)&pxl, g_xlo);
    cudaGetSymbolAddress((void**)&poh, g_ohi);
    cudaGetSymbolAddress((void**)&pol, g_olo);
    cudaGetSymbolAddress((void**)&pwqh, g_wqh);
    cudaGetSymbolAddress((void**)&pwql, g_wql);
    cudaGetSymbolAddress((void**)&pwkh, g_wkh);
    cudaGetSymbolAddress((void**)&pwkl, g_wkl);
    cudaGetSymbolAddress((void**)&pwvh, g_wvh);
    cudaGetSymbolAddress((void**)&pwvl, g_wvl);
    cudaGetSymbolAddress((void**)&pwoh, g_woh);
    cudaGetSymbolAddress((void**)&pwol, g_wol);

    cudaFuncSetAttribute(flash_attn_kernel,
                         cudaFuncAttributeMaxDynamicSharedMemorySize, FA_SMEM_BYTES);
    cudaFuncSetAttribute(gemm_mma_kernel,
                         cudaFuncAttributeMaxDynamicSharedMemorySize, GT_SMEM_BYTES);

    const int nx = MROWS * EMB;   // 8,388,608

    // 1) split x into bf16 hi/lo
    split_kernel<<<nx / (4 * 256), 256>>>(x, pxh, pxl, nx);

    // 2) transpose + split weights: W[K,N] -> Wt[N,K] bf16 hi/lo
    dim3 tb(32, 8);
    transpose_split_kernel<<<dim3(EMB / 32, EMB / 32), tb>>>(Wq, pwqh, pwql, EMB, EMB);
    transpose_split_kernel<<<dim3(KVW / 32, EMB / 32), tb>>>(Wk, pwkh, pwkl, EMB, KVW);
    transpose_split_kernel<<<dim3(KVW / 32, EMB / 32), tb>>>(Wv, pwvh, pwvl, EMB, KVW);
    transpose_split_kernel<<<dim3(EMB / 32, EMB / 32), tb>>>(Wo, pwoh, pwol, EMB, EMB);

    // 3) QKV projections (tensor cores via mma.sync)
    gemm_mma_kernel<<<dim3(EMB / 128, MROWS / 128), 256, GT_SMEM_BYTES>>>(
        pxh, pxl, pwqh, pwql, bq, pq, MROWS, EMB, EMB);
    gemm_mma_kernel<<<dim3(KVW / 128, MROWS / 128), 256, GT_SMEM_BYTES>>>(
        pxh, pxl, pwkh, pwkl, bk, pk, MROWS, KVW, EMB);
    gemm_mma_kernel<<<dim3(KVW / 128, MROWS / 128), 256, GT_SMEM_BYTES>>>(
        pxh, pxl, pwvh, pwvl, bv, pv, MROWS, KVW, EMB);

    // 4) attention (fp32, unchanged)
    flash_attn_kernel<<<dim3(SEQ / 64, HQ, BATCH), 256, FA_SMEM_BYTES>>>(
        pq, pk, pv, po);

    // 5) split attention output, then output projection
    split_kernel<<<nx / (4 * 256), 256>>>(po, poh, pol, nx);
    gemm_mma_kernel<<<dim3(EMB / 128, MROWS / 128), 256, GT_SMEM_BYTES>>>(
        poh, pol, pwoh, pwol, (const float*)nullptr, out, MROWS, EMB, EMB);
}

// round 6
// speedup vs baseline: 4.1268x; 2.8765x over previous
#include <cuda_runtime.h>
#include <cuda_bf16.h>
#include <cstdint>

#define BATCH 2
#define SEQ   2048
#define EMB   2048
#define HQ    16
#define HKV   4
#define HD    128
#define KVW   (HKV * HD)        // 512
#define MROWS (BATCH * SEQ)     // 4096

// ---------------------------------------------------------------------------
// PTX helpers — ONLY non-arch-suffixed instructions (compute_103-safe)
// ---------------------------------------------------------------------------
__device__ __forceinline__ uint32_t smem_u32(const void* p) {
    uint32_t a;
    asm("{ .reg .u64 t; cvta.to.shared.u64 t, %1; cvt.u32.u64 %0, t; }"
        : "=r"(a) : "l"(p));
    return a;
}

__device__ __forceinline__ void cp16(uint32_t saddr, const void* gaddr) {
    asm volatile("cp.async.cg.shared.global [%0], [%1], 16;"
                 :: "r"(saddr), "l"(gaddr));
}

__device__ __forceinline__ void ldmx4(uint32_t* r, uint32_t addr) {
    asm volatile("ldmatrix.sync.aligned.m8n8.x4.shared.b16 {%0,%1,%2,%3}, [%4];"
                 : "=r"(r[0]), "=r"(r[1]), "=r"(r[2]), "=r"(r[3]) : "r"(addr));
}

__device__ __forceinline__ void ldmx4t(uint32_t* r, uint32_t addr) {
    asm volatile("ldmatrix.sync.aligned.m8n8.x4.trans.shared.b16 {%0,%1,%2,%3}, [%4];"
                 : "=r"(r[0]), "=r"(r[1]), "=r"(r[2]), "=r"(r[3]) : "r"(addr));
}

__device__ __forceinline__ void mma16816(float* c, const uint32_t* a,
                                         const uint32_t* b) {
    asm volatile(
        "mma.sync.aligned.m16n8k16.row.col.f32.bf16.bf16.f32 "
        "{%0,%1,%2,%3}, {%4,%5,%6,%7}, {%8,%9}, {%0,%1,%2,%3};"
        : "+f"(c[0]), "+f"(c[1]), "+f"(c[2]), "+f"(c[3])
        : "r"(a[0]), "r"(a[1]), "r"(a[2]), "r"(a[3]), "r"(b[0]), "r"(b[1]));
}

__device__ __forceinline__ uint32_t pack_bf16(float a, float b) {
    __nv_bfloat162 t = __floats2bfloat162_rn(a, b);   // .x=a (low), .y=b
    return *(uint32_t*)&t;
}

// ---------------------------------------------------------------------------
// Device scratch (no cudaMalloc allowed)
// ---------------------------------------------------------------------------
__device__ __nv_bfloat16 g_xhi[(size_t)MROWS * EMB];
__device__ __nv_bfloat16 g_xlo[(size_t)MROWS * EMB];
__device__ __nv_bfloat16 g_qh[(size_t)MROWS * EMB];
__device__ __nv_bfloat16 g_ql[(size_t)MROWS * EMB];
__device__ __nv_bfloat16 g_kh[(size_t)MROWS * KVW];
__device__ __nv_bfloat16 g_kl[(size_t)MROWS * KVW];
__device__ __nv_bfloat16 g_vh[(size_t)MROWS * KVW];
__device__ __nv_bfloat16 g_vl[(size_t)MROWS * KVW];
__device__ __nv_bfloat16 g_ohi[(size_t)MROWS * EMB];
__device__ __nv_bfloat16 g_olo[(size_t)MROWS * EMB];
__device__ __nv_bfloat16 g_wqh[(size_t)EMB * EMB];
__device__ __nv_bfloat16 g_wql[(size_t)EMB * EMB];
__device__ __nv_bfloat16 g_wkh[(size_t)KVW * EMB];
__device__ __nv_bfloat16 g_wkl[(size_t)KVW * EMB];
__device__ __nv_bfloat16 g_wvh[(size_t)KVW * EMB];
__device__ __nv_bfloat16 g_wvl[(size_t)KVW * EMB];
__device__ __nv_bfloat16 g_woh[(size_t)EMB * EMB];
__device__ __nv_bfloat16 g_wol[(size_t)EMB * EMB];

// ---------------------------------------------------------------------------
// fp32 -> bf16 hi/lo split (elementwise)
// ---------------------------------------------------------------------------
__global__ __launch_bounds__(256) void split_kernel(
    const float* __restrict__ x, __nv_bfloat16* __restrict__ hi,
    __nv_bfloat16* __restrict__ lo, int n)
{
    int i = (blockIdx.x * 256 + threadIdx.x) * 4;
    if (i >= n) return;
    float4 v = *(const float4*)(x + i);
    __nv_bfloat16 h[4], l[4];
    float vv[4] = {v.x, v.y, v.z, v.w};
#pragma unroll
    for (int j = 0; j < 4; j++) {
        h[j] = __float2bfloat16(vv[j]);
        l[j] = __float2bfloat16(vv[j] - __bfloat162float(h[j]));
    }
    *(uint2*)(hi + i) = *(uint2*)h;
    *(uint2*)(lo + i) = *(uint2*)l;
}

// ---------------------------------------------------------------------------
// Transpose + split: W [K,N] fp32 -> Thi/Tlo [N,K] bf16
// ---------------------------------------------------------------------------
__global__ __launch_bounds__(256) void transpose_split_kernel(
    const float* __restrict__ W, __nv_bfloat16* __restrict__ Thi,
    __nv_bfloat16* __restrict__ Tlo, int K, int N)
{
    __shared__ float tile[32][33];
    const int tx = threadIdx.x, ty = threadIdx.y;
    const int nBase = blockIdx.x * 32, kBase = blockIdx.y * 32;
#pragma unroll
    for (int i = 0; i < 4; i++)
        tile[ty + 8 * i][tx] = W[(size_t)(kBase + ty + 8 * i) * N + nBase + tx];
    __syncthreads();
#pragma unroll
    for (int i = 0; i < 4; i++) {
        float v = tile[tx][ty + 8 * i];
        __nv_bfloat16 h = __float2bfloat16(v);
        __nv_bfloat16 l = __float2bfloat16(v - __bfloat162float(h));
        size_t idx = (size_t)(nBase + ty + 8 * i) * K + kBase + tx;
        Thi[idx] = h;
        Tlo[idx] = l;
    }
}

// ---------------------------------------------------------------------------
// Tensor-core GEMM via mma.sync (HMMA), hi/lo bf16 split (3 products):
//   C[M,N] = ((Ahi+Alo)[M,K] @ (Bhi+Blo)[N,K]^T + bias) * scale
// Output either fp32 (Cf) or bf16 hi/lo (Ch/Cl).
// ---------------------------------------------------------------------------
#define GT_STAGE_BYTES 65536
#define GT_SMEM_BYTES  (2 * GT_STAGE_BYTES)

__global__ __launch_bounds__(256) void gemm_mma_kernel(
    const __nv_bfloat16* __restrict__ Ahi, const __nv_bfloat16* __restrict__ Alo,
    const __nv_bfloat16* __restrict__ Bhi, const __nv_bfloat16* __restrict__ Blo,
    const float* __restrict__ bias, float* __restrict__ Cf,
    __nv_bfloat16* __restrict__ Ch, __nv_bfloat16* __restrict__ Cl,
    float scale, int M, int N, int K)
{
    extern __shared__ char gsm[];
    const uint32_t sb = smem_u32(gsm);

    const int tid   = threadIdx.x;
    const int wid   = tid >> 5;
    const int lane  = tid & 31;
    const int warpM = wid & 1;
    const int warpN = wid >> 1;
    const int mBase = blockIdx.y * 128;
    const int nBase = blockIdx.x * 128;
    const int nCh   = K >> 6;

    const int aRowOff = lane & 15;
    const int aKOff   = (lane >> 4) << 4;
    const int bRowOff = (lane & 7) + ((lane >> 4) << 3);
    const int bKOff   = ((lane >> 3) & 1) << 4;

    auto swz = [](uint32_t off) { return off ^ ((off >> 3) & 0x70); };

    auto load_chunk = [&](int ci, int buf) {
        const int k0 = ci << 6;
        const uint32_t sbase = sb + (uint32_t)buf * GT_STAGE_BYTES;
#pragma unroll
        for (int t = 0; t < 4; t++) {
            int idx = tid + t * 256;
            int row = idx >> 3;
            int gr  = idx & 7;
            uint32_t off = (uint32_t)(row * 128 + gr * 16);
            uint32_t sw  = off ^ ((off >> 3) & 0x70);
            size_t aoff = (size_t)(mBase + row) * K + k0 + gr * 8;
            size_t boff = (size_t)(nBase + row) * K + k0 + gr * 8;
            cp16(sbase +         sw, Ahi + aoff);
            cp16(sbase + 16384 + sw, Alo + aoff);
            cp16(sbase + 32768 + sw, Bhi + boff);
            cp16(sbase + 49152 + sw, Blo + boff);
        }
        asm volatile("cp.async.commit_group;" ::: "memory");
    };

    float acc[4][4][4];
#pragma unroll
    for (int mt = 0; mt < 4; mt++)
#pragma unroll
        for (int nt = 0; nt < 4; nt++)
#pragma unroll
            for (int i = 0; i < 4; i++) acc[mt][nt][i] = 0.f;

    load_chunk(0, 0);
    load_chunk(1, 1);

    for (int ci = 0; ci < nCh; ci++) {
        const int buf = ci & 1;
        if (ci + 1 < nCh)
            asm volatile("cp.async.wait_group 1;" ::: "memory");
        else
            asm volatile("cp.async.wait_group 0;" ::: "memory");
        __syncthreads();

        const uint32_t sbase = sb + (uint32_t)buf * GT_STAGE_BYTES;
        const uint32_t ahB = sbase;
        const uint32_t alB = sbase + 16384;
        const uint32_t bhB = sbase + 32768;
        const uint32_t blB = sbase + 49152;

#pragma unroll
        for (int ks = 0; ks < 4; ks++) {
            const int kByte = ks * 32;
            uint32_t ah[4][4], al[4][4];
#pragma unroll
            for (int mt = 0; mt < 4; mt++) {
                uint32_t off = (uint32_t)((warpM * 64 + mt * 16 + aRowOff) * 128
                                          + kByte + aKOff);
                uint32_t s = swz(off);
                ldmx4(ah[mt], ahB + s);
                ldmx4(al[mt], alB + s);
            }
            uint32_t bh[2][4], bl[2][4];
#pragma unroll
            for (int p = 0; p < 2; p++) {
                uint32_t off = (uint32_t)((warpN * 32 + p * 16 + bRowOff) * 128
                                          + kByte + bKOff);
                uint32_t s = swz(off);
                ldmx4(bh[p], bhB + s);
                ldmx4(bl[p], blB + s);
            }
#pragma unroll
            for (int mt = 0; mt < 4; mt++)
#pragma unroll
                for (int nt = 0; nt < 4; nt++) {
                    const uint32_t* bhf = &bh[nt >> 1][(nt & 1) * 2];
                    const uint32_t* blf = &bl[nt >> 1][(nt & 1) * 2];
                    mma16816(acc[mt][nt], ah[mt], bhf);
                    mma16816(acc[mt][nt], ah[mt], blf);
                    mma16816(acc[mt][nt], al[mt], bhf);
                }
        }
        __syncthreads();
        if (ci + 2 < nCh) load_chunk(ci + 2, buf);
    }

    // Epilogue
    const int mW = mBase + warpM * 64;
    const int nW = nBase + warpN * 32;
#pragma unroll
    for (int mt = 0; mt < 4; mt++) {
#pragma unroll
        for (int nt = 0; nt < 4; nt++) {
            int r0 = mW + mt * 16 + (lane >> 2);
            int c  = nW + nt * 8 + (lane & 3) * 2;
            float bx = 0.f, by = 0.f;
            if (bias != nullptr) {
                float2 bv = *(const float2*)(bias + c);
                bx = bv.x; by = bv.y;
            }
            float v0 = (acc[mt][nt][0] + bx) * scale;
            float v1 = (acc[mt][nt][1] + by) * scale;
            float v2 = (acc[mt][nt][2] + bx) * scale;
            float v3 = (acc[mt][nt][3] + by) * scale;
            if (Cf != nullptr) {
                *(float2*)(Cf + (size_t)r0 * N + c)       = make_float2(v0, v1);
                *(float2*)(Cf + (size_t)(r0 + 8) * N + c) = make_float2(v2, v3);
            } else {
                float h0 = __bfloat162float(__float2bfloat16(v0));
                float h1 = __bfloat162float(__float2bfloat16(v1));
                float h2 = __bfloat162float(__float2bfloat16(v2));
                float h3 = __bfloat162float(__float2bfloat16(v3));
                *(uint32_t*)(Ch + (size_t)r0 * N + c)       = pack_bf16(h0, h1);
                *(uint32_t*)(Ch + (size_t)(r0 + 8) * N + c) = pack_bf16(h2, h3);
                *(uint32_t*)(Cl + (size_t)r0 * N + c)       = pack_bf16(v0 - h0, v1 - h1);
                *(uint32_t*)(Cl + (size_t)(r0 + 8) * N + c) = pack_bf16(v2 - h2, v3 - h3);
            }
        }
    }
}

// ---------------------------------------------------------------------------
// Flash attention on tensor cores (mma.sync bf16 hi/lo, fp32 softmax).
// BM=128, BN=64, HD=128, 8 warps. Q resident in smem (64KB);
// K/V hi/lo double-buffered (2 x 64KB). Each warp owns 16 q-rows.
// ---------------------------------------------------------------------------
#define FA_SMEM_BYTES (65536 + 2 * 65536)   // 196608

__global__ __launch_bounds__(256, 1) void flash_mma_kernel(
    const __nv_bfloat16* __restrict__ qh, const __nv_bfloat16* __restrict__ ql,
    const __nv_bfloat16* __restrict__ kh, const __nv_bfloat16* __restrict__ kl,
    const __nv_bfloat16* __restrict__ vh, const __nv_bfloat16* __restrict__ vl,
    __nv_bfloat16* __restrict__ oh, __nv_bfloat16* __restrict__ ol)
{
    extern __shared__ char fsm[];
    const uint32_t sb  = smem_u32(fsm);
    const int tid  = threadIdx.x;
    const int wid  = tid >> 5;
    const int lane = tid & 31;
    const int q0 = blockIdx.x * 128;
    const int h  = blockIdx.y;
    const int b  = blockIdx.z;
    const int g  = h >> 2;

    const uint32_t QH0 = sb;            // Q hi: 2 blocks of [128 x 128B]
    const uint32_t QL0 = sb + 32768;    // Q lo
    const uint32_t STG = sb + 65536;    // KV stages (64KB each)

    const size_t qrow0 = (size_t)b * SEQ + q0;

    // Load Q hi/lo (once)
#pragma unroll
    for (int t = 0; t < 8; t++) {
        int idx = tid + t * 256;        // 0..2047
        int row = idx >> 4;             // 0..127
        int gr  = idx & 15;             // 16B granule within 256B row
        int blk = gr >> 3;
        uint32_t off = (uint32_t)(row * 128 + (gr & 7) * 16);
        uint32_t sw  = off ^ ((off >> 3) & 0x70);
        size_t go = (qrow0 + row) * EMB + (size_t)h * HD + gr * 8;
        cp16(QH0 + blk * 16384 + sw, qh + go);
        cp16(QL0 + blk * 16384 + sw, ql + go);
    }
    asm volatile("cp.async.commit_group;" ::: "memory");

    auto load_stage = [&](int ci, int buf) {
        const uint32_t s0 = STG + (uint32_t)buf * 65536u;
        const int kr0 = ci * 64;
#pragma unroll
        for (int t = 0; t < 16; t++) {
            int arr = t >> 2;                       // 0..3: kh,kl,vh,vl
            int idx = tid + (t & 3) * 256;          // 0..1023
            int row = idx >> 4;                     // 0..63
            int gr  = idx & 15;
            int blk = gr >> 3;
            uint32_t off = (uint32_t)(row * 128 + (gr & 7) * 16);
            uint32_t sw  = off ^ ((off >> 3) & 0x70);
            uint32_t dst = s0 + (uint32_t)arr * 16384u + (uint32_t)blk * 8192u + sw;
            size_t go = (size_t)(b * SEQ + kr0 + row) * KVW + (size_t)g * HD + gr * 8;
            const __nv_bfloat16* src = (arr == 0) ? kh : (arr == 1) ? kl
                                     : (arr == 2) ? vh : vl;
            cp16(dst, src + go);
        }
        asm volatile("cp.async.commit_group;" ::: "memory");
    };

    load_stage(0, 0);
    load_stage(1, 1);

    const int gid = lane >> 2, tig = lane & 3;
    const int qrw = wid * 16;

    // ldmatrix lane offsets
    const int aRow = lane & 15;
    const int aCol = (lane >> 4) << 4;
    const int bRow = (lane & 7) + ((lane >> 4) << 3);
    const int bCol = ((lane >> 3) & 1) << 4;
    const int vRow = (lane & 7) + (((lane >> 3) & 1) << 3);
    const int vCol = (lane >> 4) << 4;

    float m0 = -1e30f, m1 = -1e30f, l0 = 0.f, l1 = 0.f;
    float o[16][4];
#pragma unroll
    for (int t = 0; t < 16; t++)
#pragma unroll
        for (int i = 0; i < 4; i++) o[t][i] = 0.f;

    for (int ci = 0; ci < SEQ / 64; ci++) {
        const int buf = ci & 1;
        if (ci + 1 < SEQ / 64)
            asm volatile("cp.async.wait_group 1;" ::: "memory");
        else
            asm volatile("cp.async.wait_group 0;" ::: "memory");
        __syncthreads();

        const uint32_t s0 = STG + (uint32_t)buf * 65536u;
        const uint32_t KH = s0, KL = s0 + 16384, VH = s0 + 32768, VL = s0 + 49152;

        // ---- S = Q @ K^T (hi/lo, 3 products) ----
        float s[8][4];
#pragma unroll
        for (int t = 0; t < 8; t++)
#pragma unroll
            for (int i = 0; i < 4; i++) s[t][i] = 0.f;

#pragma unroll
        for (int ks = 0; ks < 8; ks++) {
            const int blk = ks >> 2;
            const int kb  = (ks & 3) * 32;
            uint32_t qa[4], qb[4];
            uint32_t offq = (uint32_t)((qrw + aRow) * 128 + kb + aCol);
            uint32_t swq  = offq ^ ((offq >> 3) & 0x70);
            ldmx4(qa, QH0 + blk * 16384 + swq);
            ldmx4(qb, QL0 + blk * 16384 + swq);
#pragma unroll
            for (int nb = 0; nb < 4; nb++) {
                uint32_t kh4[4], kl4[4];
                uint32_t offk = (uint32_t)((nb * 16 + bRow) * 128 + kb + bCol);
                uint32_t swk  = offk ^ ((offk >> 3) & 0x70);
                ldmx4(kh4, KH + blk * 8192 + swk);
                ldmx4(kl4, KL + blk * 8192 + swk);
                mma16816(s[2 * nb],     qa, &kh4[0]);
                mma16816(s[2 * nb],     qa, &kl4[0]);
                mma16816(s[2 * nb],     qb, &kh4[0]);
                mma16816(s[2 * nb + 1], qa, &kh4[2]);
                mma16816(s[2 * nb + 1], qa, &kl4[2]);
                mma16816(s[2 * nb + 1], qb, &kh4[2]);
            }
        }

        // ---- online softmax (rows gid, gid+8; quad = same row) ----
        float mx0 = -1e30f, mx1 = -1e30f;
#pragma unroll
        for (int t = 0; t < 8; t++) {
            mx0 = fmaxf(mx0, fmaxf(s[t][0], s[t][1]));
            mx1 = fmaxf(mx1, fmaxf(s[t][2], s[t][3]));
        }
        mx0 = fmaxf(mx0, __shfl_xor_sync(0xffffffffu, mx0, 1));
        mx0 = fmaxf(mx0, __shfl_xor_sync(0xffffffffu, mx0, 2));
        mx1 = fmaxf(mx1, __shfl_xor_sync(0xffffffffu, mx1, 1));
        mx1 = fmaxf(mx1, __shfl_xor_sync(0xffffffffu, mx1, 2));

        float mn0 = fmaxf(m0, mx0), mn1 = fmaxf(m1, mx1);
        float a0 = __expf(m0 - mn0), a1 = __expf(m1 - mn1);
        m0 = mn0; m1 = mn1;

        float rs0 = 0.f, rs1 = 0.f;
        uint32_t pah[4][4], pal[4][4];
#pragma unroll
        for (int t = 0; t < 8; t++) {
            float p0 = __expf(s[t][0] - mn0);
            float p1 = __expf(s[t][1] - mn0);
            float p2 = __expf(s[t][2] - mn1);
            float p3 = __expf(s[t][3] - mn1);
            rs0 += p0 + p1;
            rs1 += p2 + p3;
            float h0 = __bfloat162float(__float2bfloat16(p0));
            float h1 = __bfloat162float(__float2bfloat16(p1));
            float h2 = __bfloat162float(__float2bfloat16(p2));
            float h3 = __bfloat162float(__float2bfloat16(p3));
            int j = t >> 1, sl = (t & 1) * 2;
            pah[j][sl]     = pack_bf16(h0, h1);
            pah[j][sl + 1] = pack_bf16(h2, h3);
            pal[j][sl]     = pack_bf16(p0 - h0, p1 - h1);
            pal[j][sl + 1] = pack_bf16(p2 - h2, p3 - h3);
        }
        rs0 += __shfl_xor_sync(0xffffffffu, rs0, 1);
        rs0 += __shfl_xor_sync(0xffffffffu, rs0, 2);
        rs1 += __shfl_xor_sync(0xffffffffu, rs1, 1);
        rs1 += __shfl_xor_sync(0xffffffffu, rs1, 2);
        l0 = l0 * a0 + rs0;
        l1 = l1 * a1 + rs1;

#pragma unroll
        for (int t = 0; t < 16; t++) {
            o[t][0] *= a0; o[t][1] *= a0;
            o[t][2] *= a1; o[t][3] *= a1;
        }

        // ---- O += P @ V (hi/lo, 3 products; V via ldmatrix.trans) ----
#pragma unroll
        for (int j = 0; j < 4; j++) {
#pragma unroll
            for (int tp = 0; tp < 8; tp++) {
                const int blk = tp >> 2;
                const int cb  = (tp & 3) * 32 + vCol;
                uint32_t offv = (uint32_t)((j * 16 + vRow) * 128 + cb);
                uint32_t swv  = offv ^ ((offv >> 3) & 0x70);
                uint32_t vh4[4], vl4[4];
                ldmx4t(vh4, VH + blk * 8192 + swv);
                ldmx4t(vl4, VL + blk * 8192 + swv);
                mma16816(o[2 * tp],     pah[j], &vh4[0]);
                mma16816(o[2 * tp],     pah[j], &vl4[0]);
                mma16816(o[2 * tp],     pal[j], &vh4[0]);
                mma16816(o[2 * tp + 1], pah[j], &vh4[2]);
                mma16816(o[2 * tp + 1], pah[j], &vl4[2]);
                mma16816(o[2 * tp + 1], pal[j], &vh4[2]);
            }
        }

        __syncthreads();
        if (ci + 2 < SEQ / 64) load_stage(ci + 2, buf);
    }

    // ---- epilogue: normalize, split hi/lo, store bf16 ----
    float i0 = 1.0f / l0, i1 = 1.0f / l1;
    size_t r0 = (qrow0 + qrw + gid) * EMB + (size_t)h * HD;
    size_t r1 = (qrow0 + qrw + gid + 8) * EMB + (size_t)h * HD;
#pragma unroll
    for (int t = 0; t < 16; t++) {
        int c = t * 8 + tig * 2;
        float v0 = o[t][0] * i0, v1 = o[t][1] * i0;
        float v2 = o[t][2] * i1, v3 = o[t][3] * i1;
        float h0 = __bfloat162float(__float2bfloat16(v0));
        float h1 = __bfloat162float(__float2bfloat16(v1));
        float h2 = __bfloat162float(__float2bfloat16(v2));
        float h3 = __bfloat162float(__float2bfloat16(v3));
        *(uint32_t*)(oh + r0 + c) = pack_bf16(h0, h1);
        *(uint32_t*)(oh + r1 + c) = pack_bf16(h2, h3);
        *(uint32_t*)(ol + r0 + c) = pack_bf16(v0 - h0, v1 - h1);
        *(uint32_t*)(ol + r1 + c) = pack_bf16(v2 - h2, v3 - h3);
    }
}

// ---------------------------------------------------------------------------
// kernel_launch
// ---------------------------------------------------------------------------
extern "C" void kernel_launch(void* const* d_in, const int* in_sizes, int n_in,
                              void* d_out, int out_size)
{
    const float* x  = (const float*)d_in[0];
    const float* Wq = (const float*)d_in[1];
    const float* bq = (const float*)d_in[2];
    const float* Wk = (const float*)d_in[3];
    const float* bk = (const float*)d_in[4];
    const float* Wv = (const float*)d_in[5];
    const float* bv = (const float*)d_in[6];
    const float* Wo = (const float*)d_in[7];
    float* out = (float*)d_out;

    __nv_bfloat16 *pxh, *pxl, *pqh, *pql, *pkh, *pkl, *pvh, *pvl, *poh, *pol;
    __nv_bfloat16 *pwqh, *pwql, *pwkh, *pwkl, *pwvh, *pwvl, *pwoh, *pwol;
    cudaGetSymbolAddress((void**)&pxh, g_xhi);
    cudaGetSymbolAddress((void**)&pxl, g_xlo);
    cudaGetSymbolAddress((void**)&pqh, g_qh);
    cudaGetSymbolAddress((void**)&pql, g_ql);
    cudaGetSymbolAddress((void**)&pkh, g_kh);
    cudaGetSymbolAddress((void**)&pkl, g_kl);
    cudaGetSymbolAddress((void**)&pvh, g_vh);
    cudaGetSymbolAddress((void**)&pvl, g_vl);
    cudaGetSymbolAddress((void**)&poh, g_ohi);
    cudaGetSymbolAddress((void**)&pol, g_olo);
    cudaGetSymbolAddress((void**)&pwqh, g_wqh);
    cudaGetSymbolAddress((void**)&pwql, g_wql);
    cudaGetSymbolAddress((void**)&pwkh, g_wkh);
    cudaGetSymbolAddress((void**)&pwkl, g_wkl);
    cudaGetSymbolAddress((void**)&pwvh, g_wvh);
    cudaGetSymbolAddress((void**)&pwvl, g_wvl);
    cudaGetSymbolAddress((void**)&pwoh, g_woh);
    cudaGetSymbolAddress((void**)&pwol, g_wol);

    cudaFuncSetAttribute(gemm_mma_kernel,
                         cudaFuncAttributeMaxDynamicSharedMemorySize, GT_SMEM_BYTES);
    cudaFuncSetAttribute(flash_mma_kernel,
                         cudaFuncAttributeMaxDynamicSharedMemorySize, FA_SMEM_BYTES);

    const int nx = MROWS * EMB;
    const float qscale = 0.088388347648318447f;   // 1/sqrt(128)

    // 1) split x into bf16 hi/lo
    split_kernel<<<nx / (4 * 256), 256>>>(x, pxh, pxl, nx);

    // 2) transpose + split weights
    dim3 tb(32, 8);
    transpose_split_kernel<<<dim3(EMB / 32, EMB / 32), tb>>>(Wq, pwqh, pwql, EMB, EMB);
    transpose_split_kernel<<<dim3(KVW / 32, EMB / 32), tb>>>(Wk, pwkh, pwkl, EMB, KVW);
    transpose_split_kernel<<<dim3(KVW / 32, EMB / 32), tb>>>(Wv, pwvh, pwvl, EMB, KVW);
    transpose_split_kernel<<<dim3(EMB / 32, EMB / 32), tb>>>(Wo, pwoh, pwol, EMB, EMB);

    // 3) QKV projections -> bf16 hi/lo outputs (Q pre-scaled by 1/sqrt(HD))
    gemm_mma_kernel<<<dim3(EMB / 128, MROWS / 128), 256, GT_SMEM_BYTES>>>(
        pxh, pxl, pwqh, pwql, bq, nullptr, pqh, pql, qscale, MROWS, EMB, EMB);
    gemm_mma_kernel<<<dim3(KVW / 128, MROWS / 128), 256, GT_SMEM_BYTES>>>(
        pxh, pxl, pwkh, pwkl, bk, nullptr, pkh, pkl, 1.0f, MROWS, KVW, EMB);
    gemm_mma_kernel<<<dim3(KVW / 128, MROWS / 128), 256, GT_SMEM_BYTES>>>(
        pxh, pxl, pwvh, pwvl, bv, nullptr, pvh, pvl, 1.0f, MROWS, KVW, EMB);

    // 4) flash attention on tensor cores -> bf16 hi/lo output
    flash_mma_kernel<<<dim3(SEQ / 128, HQ, BATCH), 256, FA_SMEM_BYTES>>>(
        pqh, pql, pkh, pkl, pvh, pvl, poh, pol);

    // 5) output projection -> fp32
    gemm_mma_kernel<<<dim3(EMB / 128, MROWS / 128), 256, GT_SMEM_BYTES>>>(
        poh, pol, pwoh, pwol, (const float*)nullptr, out, nullptr, nullptr,
        1.0f, MROWS, EMB, EMB);
}

// round 7
// speedup vs baseline: 5.3238x; 1.2901x over previous
#include <cuda_runtime.h>
#include <cuda_bf16.h>
#include <cuda_fp16.h>
#include <cstdint>

#define BATCH 2
#define SEQ   2048
#define EMB   2048
#define HQ    16
#define HKV   4
#define HD    128
#define KVW   (HKV * HD)        // 512
#define MROWS (BATCH * SEQ)     // 4096
#define QKVW  (EMB + 2 * KVW)   // 3072

// ---------------------------------------------------------------------------
// PTX helpers — ONLY non-arch-suffixed instructions (compute_103-safe)
// ---------------------------------------------------------------------------
__device__ __forceinline__ uint32_t smem_u32(const void* p) {
    uint32_t a;
    asm("{ .reg .u64 t; cvta.to.shared.u64 t, %1; cvt.u32.u64 %0, t; }"
        : "=r"(a) : "l"(p));
    return a;
}

__device__ __forceinline__ void cp16(uint32_t saddr, const void* gaddr) {
    asm volatile("cp.async.cg.shared.global [%0], [%1], 16;"
                 :: "r"(saddr), "l"(gaddr));
}

__device__ __forceinline__ void ldmx4(uint32_t* r, uint32_t addr) {
    asm volatile("ldmatrix.sync.aligned.m8n8.x4.shared.b16 {%0,%1,%2,%3}, [%4];"
                 : "=r"(r[0]), "=r"(r[1]), "=r"(r[2]), "=r"(r[3]) : "r"(addr));
}

__device__ __forceinline__ void ldmx4t(uint32_t* r, uint32_t addr) {
    asm volatile("ldmatrix.sync.aligned.m8n8.x4.trans.shared.b16 {%0,%1,%2,%3}, [%4];"
                 : "=r"(r[0]), "=r"(r[1]), "=r"(r[2]), "=r"(r[3]) : "r"(addr));
}

// bf16 mma
__device__ __forceinline__ void mma16816(float* c, const uint32_t* a,
                                         const uint32_t* b) {
    asm volatile(
        "mma.sync.aligned.m16n8k16.row.col.f32.bf16.bf16.f32 "
        "{%0,%1,%2,%3}, {%4,%5,%6,%7}, {%8,%9}, {%0,%1,%2,%3};"
        : "+f"(c[0]), "+f"(c[1]), "+f"(c[2]), "+f"(c[3])
        : "r"(a[0]), "r"(a[1]), "r"(a[2]), "r"(a[3]), "r"(b[0]), "r"(b[1]));
}

// fp16 mma
__device__ __forceinline__ void mma16816h(float* c, const uint32_t* a,
                                          const uint32_t* b) {
    asm volatile(
        "mma.sync.aligned.m16n8k16.row.col.f32.f16.f16.f32 "
        "{%0,%1,%2,%3}, {%4,%5,%6,%7}, {%8,%9}, {%0,%1,%2,%3};"
        : "+f"(c[0]), "+f"(c[1]), "+f"(c[2]), "+f"(c[3])
        : "r"(a[0]), "r"(a[1]), "r"(a[2]), "r"(a[3]), "r"(b[0]), "r"(b[1]));
}

__device__ __forceinline__ uint32_t pack_bf16(float a, float b) {
    __nv_bfloat162 t = __floats2bfloat162_rn(a, b);
    return *(uint32_t*)&t;
}

// ---------------------------------------------------------------------------
// Device scratch (no cudaMalloc allowed)
// ---------------------------------------------------------------------------
__device__ __nv_bfloat16 g_xhi[(size_t)MROWS * EMB];
__device__ __nv_bfloat16 g_xlo[(size_t)MROWS * EMB];
__device__ __half        g_qkv[(size_t)MROWS * QKVW];     // fused q|k|v fp16
__device__ __nv_bfloat16 g_ohi[(size_t)MROWS * EMB];
__device__ __nv_bfloat16 g_olo[(size_t)MROWS * EMB];
__device__ __nv_bfloat16 g_wch[(size_t)QKVW * EMB];       // concat Wq|Wk|Wv ^T hi
__device__ __nv_bfloat16 g_wcl[(size_t)QKVW * EMB];       // concat lo
__device__ __nv_bfloat16 g_woh[(size_t)EMB * EMB];
__device__ __nv_bfloat16 g_wol[(size_t)EMB * EMB];
__device__ float         g_bias[QKVW];                     // concat bq|bk|bv

// ---------------------------------------------------------------------------
// fp32 -> bf16 hi/lo split (elementwise)
// ---------------------------------------------------------------------------
__global__ __launch_bounds__(256) void split_kernel(
    const float* __restrict__ x, __nv_bfloat16* __restrict__ hi,
    __nv_bfloat16* __restrict__ lo, int n)
{
    int i = (blockIdx.x * 256 + threadIdx.x) * 4;
    if (i >= n) return;
    float4 v = *(const float4*)(x + i);
    __nv_bfloat16 h[4], l[4];
    float vv[4] = {v.x, v.y, v.z, v.w};
#pragma unroll
    for (int j = 0; j < 4; j++) {
        h[j] = __float2bfloat16(vv[j]);
        l[j] = __float2bfloat16(vv[j] - __bfloat162float(h[j]));
    }
    *(uint2*)(hi + i) = *(uint2*)h;
    *(uint2*)(lo + i) = *(uint2*)l;
}

// ---------------------------------------------------------------------------
// Transpose + split: W [K,N] fp32 -> Thi/Tlo [N,K] bf16
// ---------------------------------------------------------------------------
__global__ __launch_bounds__(256) void transpose_split_kernel(
    const float* __restrict__ W, __nv_bfloat16* __restrict__ Thi,
    __nv_bfloat16* __restrict__ Tlo, int K, int N)
{
    __shared__ float tile[32][33];
    const int tx = threadIdx.x, ty = threadIdx.y;
    const int nBase = blockIdx.x * 32, kBase = blockIdx.y * 32;
#pragma unroll
    for (int i = 0; i < 4; i++)
        tile[ty + 8 * i][tx] = W[(size_t)(kBase + ty + 8 * i) * N + nBase + tx];
    __syncthreads();
#pragma unroll
    for (int i = 0; i < 4; i++) {
        float v = tile[tx][ty + 8 * i];
        __nv_bfloat16 h = __float2bfloat16(v);
        __nv_bfloat16 l = __float2bfloat16(v - __bfloat162float(h));
        size_t idx = (size_t)(nBase + ty + 8 * i) * K + kBase + tx;
        Thi[idx] = h;
        Tlo[idx] = l;
    }
}

// ---------------------------------------------------------------------------
// Tensor-core GEMM (HMMA bf16 hi/lo, 3 products):
//   C[M,N] = ((Ahi+Alo) @ (Bhi+Blo)^T + bias) * scale
// OMODE 0: fp32 out.  OMODE 1: fp16 out, scale=qsc for cols < qcols else 1.
// ---------------------------------------------------------------------------
#define GT_STAGE_BYTES 65536
#define GT_SMEM_BYTES  (2 * GT_STAGE_BYTES)

template <int OMODE>
__global__ __launch_bounds__(256) void gemm_mma_kernel(
    const __nv_bfloat16* __restrict__ Ahi, const __nv_bfloat16* __restrict__ Alo,
    const __nv_bfloat16* __restrict__ Bhi, const __nv_bfloat16* __restrict__ Blo,
    const float* __restrict__ bias, float* __restrict__ Cf,
    __half* __restrict__ Ch, float qsc, int qcols,
    int M, int N, int K)
{
    extern __shared__ char gsm[];
    const uint32_t sb = smem_u32(gsm);

    const int tid   = threadIdx.x;
    const int wid   = tid >> 5;
    const int lane  = tid & 31;
    const int warpM = wid & 1;
    const int warpN = wid >> 1;
    const int mBase = blockIdx.y * 128;
    const int nBase = blockIdx.x * 128;
    const int nCh   = K >> 6;

    const int aRowOff = lane & 15;
    const int aKOff   = (lane >> 4) << 4;
    const int bRowOff = (lane & 7) + ((lane >> 4) << 3);
    const int bKOff   = ((lane >> 3) & 1) << 4;

    auto swz = [](uint32_t off) { return off ^ ((off >> 3) & 0x70); };

    auto load_chunk = [&](int ci, int buf) {
        const int k0 = ci << 6;
        const uint32_t sbase = sb + (uint32_t)buf * GT_STAGE_BYTES;
#pragma unroll
        for (int t = 0; t < 4; t++) {
            int idx = tid + t * 256;
            int row = idx >> 3;
            int gr  = idx & 7;
            uint32_t off = (uint32_t)(row * 128 + gr * 16);
            uint32_t sw  = off ^ ((off >> 3) & 0x70);
            size_t aoff = (size_t)(mBase + row) * K + k0 + gr * 8;
            size_t boff = (size_t)(nBase + row) * K + k0 + gr * 8;
            cp16(sbase +         sw, Ahi + aoff);
            cp16(sbase + 16384 + sw, Alo + aoff);
            cp16(sbase + 32768 + sw, Bhi + boff);
            cp16(sbase + 49152 + sw, Blo + boff);
        }
        asm volatile("cp.async.commit_group;" ::: "memory");
    };

    float acc[4][4][4];
#pragma unroll
    for (int mt = 0; mt < 4; mt++)
#pragma unroll
        for (int nt = 0; nt < 4; nt++)
#pragma unroll
            for (int i = 0; i < 4; i++) acc[mt][nt][i] = 0.f;

    load_chunk(0, 0);
    load_chunk(1, 1);

    for (int ci = 0; ci < nCh; ci++) {
        const int buf = ci & 1;
        if (ci + 1 < nCh)
            asm volatile("cp.async.wait_group 1;" ::: "memory");
        else
            asm volatile("cp.async.wait_group 0;" ::: "memory");
        __syncthreads();

        const uint32_t sbase = sb + (uint32_t)buf * GT_STAGE_BYTES;
        const uint32_t ahB = sbase;
        const uint32_t alB = sbase + 16384;
        const uint32_t bhB = sbase + 32768;
        const uint32_t blB = sbase + 49152;

#pragma unroll
        for (int ks = 0; ks < 4; ks++) {
            const int kByte = ks * 32;
            uint32_t ah[4][4], al[4][4];
#pragma unroll
            for (int mt = 0; mt < 4; mt++) {
                uint32_t off = (uint32_t)((warpM * 64 + mt * 16 + aRowOff) * 128
                                          + kByte + aKOff);
                uint32_t s = swz(off);
                ldmx4(ah[mt], ahB + s);
                ldmx4(al[mt], alB + s);
            }
            uint32_t bh[2][4], bl[2][4];
#pragma unroll
            for (int p = 0; p < 2; p++) {
                uint32_t off = (uint32_t)((warpN * 32 + p * 16 + bRowOff) * 128
                                          + kByte + bKOff);
                uint32_t s = swz(off);
                ldmx4(bh[p], bhB + s);
                ldmx4(bl[p], blB + s);
            }
#pragma unroll
            for (int mt = 0; mt < 4; mt++)
#pragma unroll
                for (int nt = 0; nt < 4; nt++) {
                    const uint32_t* bhf = &bh[nt >> 1][(nt & 1) * 2];
                    const uint32_t* blf = &bl[nt >> 1][(nt & 1) * 2];
                    mma16816(acc[mt][nt], ah[mt], bhf);
                    mma16816(acc[mt][nt], ah[mt], blf);
                    mma16816(acc[mt][nt], al[mt], bhf);
                }
        }
        __syncthreads();
        if (ci + 2 < nCh) load_chunk(ci + 2, buf);
    }

    // Epilogue
    const int mW = mBase + warpM * 64;
    const int nW = nBase + warpN * 32;
#pragma unroll
    for (int mt = 0; mt < 4; mt++) {
#pragma unroll
        for (int nt = 0; nt < 4; nt++) {
            int r0 = mW + mt * 16 + (lane >> 2);
            int c  = nW + nt * 8 + (lane & 3) * 2;
            float bx = 0.f, by = 0.f;
            if (bias != nullptr) {
                float2 bv = *(const float2*)(bias + c);
                bx = bv.x; by = bv.y;
            }
            float sc = 1.f;
            if (OMODE == 1) sc = (c < qcols) ? qsc : 1.f;
            float v0 = (acc[mt][nt][0] + bx) * sc;
            float v1 = (acc[mt][nt][1] + by) * sc;
            float v2 = (acc[mt][nt][2] + bx) * sc;
            float v3 = (acc[mt][nt][3] + by) * sc;
            if (OMODE == 0) {
                *(float2*)(Cf + (size_t)r0 * N + c)       = make_float2(v0, v1);
                *(float2*)(Cf + (size_t)(r0 + 8) * N + c) = make_float2(v2, v3);
            } else {
                __half2 h01 = __floats2half2_rn(v0, v1);
                __half2 h23 = __floats2half2_rn(v2, v3);
                *(uint32_t*)(Ch + (size_t)r0 * N + c)       = *(uint32_t*)&h01;
                *(uint32_t*)(Ch + (size_t)(r0 + 8) * N + c) = *(uint32_t*)&h23;
            }
        }
    }
}

// ---------------------------------------------------------------------------
// Flash attention, fp16 single-product mma. BM=128, BN=64, 8 warps.
// Q resident (32KB); K/V double-buffered (2 x 32KB). Reads fused qkv buffer.
// ---------------------------------------------------------------------------
#define FA_SMEM_BYTES (32768 + 2 * 32768)   // 98304

__global__ __launch_bounds__(256, 1) void flash_mma_kernel(
    const __half* __restrict__ qkv,
    __nv_bfloat16* __restrict__ oh, __nv_bfloat16* __restrict__ ol)
{
    extern __shared__ char fsm[];
    const uint32_t sb  = smem_u32(fsm);
    const int tid  = threadIdx.x;
    const int wid  = tid >> 5;
    const int lane = tid & 31;
    const int q0 = blockIdx.x * 128;
    const int h  = blockIdx.y;
    const int b  = blockIdx.z;
    const int g  = h >> 2;

    const uint32_t QS  = sb;            // Q: 2 blocks of [128 x 128B]
    const uint32_t STG = sb + 32768;    // stages: K(16KB)+V(16KB) each

    const size_t qrow0 = (size_t)b * SEQ + q0;
    const int qcol = h * HD;
    const int kcol = EMB + g * HD;
    const int vcol = EMB + KVW + g * HD;

    // Load Q (once)
#pragma unroll
    for (int t = 0; t < 8; t++) {
        int idx = tid + t * 256;        // 0..2047
        int row = idx >> 4;             // 0..127
        int gr  = idx & 15;
        int blk = gr >> 3;
        uint32_t off = (uint32_t)(row * 128 + (gr & 7) * 16);
        uint32_t sw  = off ^ ((off >> 3) & 0x70);
        size_t go = (qrow0 + row) * QKVW + qcol + gr * 8;
        cp16(QS + blk * 16384 + sw, qkv + go);
    }
    asm volatile("cp.async.commit_group;" ::: "memory");

    auto load_stage = [&](int ci, int buf) {
        const uint32_t s0 = STG + (uint32_t)buf * 32768u;
        const int kr0 = ci * 64;
#pragma unroll
        for (int t = 0; t < 8; t++) {
            int arr = t >> 2;                   // 0=K, 1=V
            int idx = tid + (t & 3) * 256;      // 0..1023
            int row = idx >> 4;                 // 0..63
            int gr  = idx & 15;
            int blk = gr >> 3;
            uint32_t off = (uint32_t)(row * 128 + (gr & 7) * 16);
            uint32_t sw  = off ^ ((off >> 3) & 0x70);
            uint32_t dst = s0 + (uint32_t)arr * 16384u + (uint32_t)blk * 8192u + sw;
            int col = (arr == 0) ? kcol : vcol;
            size_t go = (size_t)(b * SEQ + kr0 + row) * QKVW + col + gr * 8;
            cp16(dst, qkv + go);
        }
        asm volatile("cp.async.commit_group;" ::: "memory");
    };

    load_stage(0, 0);
    load_stage(1, 1);

    const int gid = lane >> 2, tig = lane & 3;
    const int qrw = wid * 16;

    const int aRow = lane & 15;
    const int aCol = (lane >> 4) << 4;
    const int bRow = (lane & 7) + ((lane >> 4) << 3);
    const int bCol = ((lane >> 3) & 1) << 4;
    const int vRow = (lane & 7) + (((lane >> 3) & 1) << 3);
    const int vCol = (lane >> 4) << 4;

    float m0 = -1e30f, m1 = -1e30f, l0 = 0.f, l1 = 0.f;
    float o[16][4];
#pragma unroll
    for (int t = 0; t < 16; t++)
#pragma unroll
        for (int i = 0; i < 4; i++) o[t][i] = 0.f;

    for (int ci = 0; ci < SEQ / 64; ci++) {
        const int buf = ci & 1;
        if (ci + 1 < SEQ / 64)
            asm volatile("cp.async.wait_group 1;" ::: "memory");
        else
            asm volatile("cp.async.wait_group 0;" ::: "memory");
        __syncthreads();

        const uint32_t s0 = STG + (uint32_t)buf * 32768u;
        const uint32_t KB = s0, VB = s0 + 16384;

        // ---- S = Q @ K^T (single fp16 product) ----
        float s[8][4];
#pragma unroll
        for (int t = 0; t < 8; t++)
#pragma unroll
            for (int i = 0; i < 4; i++) s[t][i] = 0.f;

#pragma unroll
        for (int ks = 0; ks < 8; ks++) {
            const int blk = ks >> 2;
            const int kb  = (ks & 3) * 32;
            uint32_t qa[4];
            uint32_t offq = (uint32_t)((qrw + aRow) * 128 + kb + aCol);
            uint32_t swq  = offq ^ ((offq >> 3) & 0x70);
            ldmx4(qa, QS + blk * 16384 + swq);
#pragma unroll
            for (int nb = 0; nb < 4; nb++) {
                uint32_t kf[4];
                uint32_t offk = (uint32_t)((nb * 16 + bRow) * 128 + kb + bCol);
                uint32_t swk  = offk ^ ((offk >> 3) & 0x70);
                ldmx4(kf, KB + blk * 8192 + swk);
                mma16816h(s[2 * nb],     qa, &kf[0]);
                mma16816h(s[2 * nb + 1], qa, &kf[2]);
            }
        }

        // ---- online softmax ----
        float mx0 = -1e30f, mx1 = -1e30f;
#pragma unroll
        for (int t = 0; t < 8; t++) {
            mx0 = fmaxf(mx0, fmaxf(s[t][0], s[t][1]));
            mx1 = fmaxf(mx1, fmaxf(s[t][2], s[t][3]));
        }
        mx0 = fmaxf(mx0, __shfl_xor_sync(0xffffffffu, mx0, 1));
        mx0 = fmaxf(mx0, __shfl_xor_sync(0xffffffffu, mx0, 2));
        mx1 = fmaxf(mx1, __shfl_xor_sync(0xffffffffu, mx1, 1));
        mx1 = fmaxf(mx1, __shfl_xor_sync(0xffffffffu, mx1, 2));

        float mn0 = fmaxf(m0, mx0), mn1 = fmaxf(m1, mx1);
        float a0 = __expf(m0 - mn0), a1 = __expf(m1 - mn1);
        m0 = mn0; m1 = mn1;

        float rs0 = 0.f, rs1 = 0.f;
        uint32_t pa[4][4];
#pragma unroll
        for (int t = 0; t < 8; t++) {
            float p0 = __expf(s[t][0] - mn0);
            float p1 = __expf(s[t][1] - mn0);
            float p2 = __expf(s[t][2] - mn1);
            float p3 = __expf(s[t][3] - mn1);
            __half2 h01 = __floats2half2_rn(p0, p1);
            __half2 h23 = __floats2half2_rn(p2, p3);
            // sum the ROUNDED values so normalization matches the numerator
            float2 f01 = __half22float2(h01);
            float2 f23 = __half22float2(h23);
            rs0 += f01.x + f01.y;
            rs1 += f23.x + f23.y;
            int j = t >> 1, sl = (t & 1) * 2;
            pa[j][sl]     = *(uint32_t*)&h01;
            pa[j][sl + 1] = *(uint32_t*)&h23;
        }
        rs0 += __shfl_xor_sync(0xffffffffu, rs0, 1);
        rs0 += __shfl_xor_sync(0xffffffffu, rs0, 2);
        rs1 += __shfl_xor_sync(0xffffffffu, rs1, 1);
        rs1 += __shfl_xor_sync(0xffffffffu, rs1, 2);
        l0 = l0 * a0 + rs0;
        l1 = l1 * a1 + rs1;

#pragma unroll
        for (int t = 0; t < 16; t++) {
            o[t][0] *= a0; o[t][1] *= a0;
            o[t][2] *= a1; o[t][3] *= a1;
        }

        // ---- O += P @ V (single fp16 product; V via ldmatrix.trans) ----
#pragma unroll
        for (int j = 0; j < 4; j++) {
#pragma unroll
            for (int tp = 0; tp < 8; tp++) {
                const int blk = tp >> 2;
                const int cb  = (tp & 3) * 32 + vCol;
                uint32_t offv = (uint32_t)((j * 16 + vRow) * 128 + cb);
                uint32_t swv  = offv ^ ((offv >> 3) & 0x70);
                uint32_t vf[4];
                ldmx4t(vf, VB + blk * 8192 + swv);
                mma16816h(o[2 * tp],     pa[j], &vf[0]);
                mma16816h(o[2 * tp + 1], pa[j], &vf[2]);
            }
        }

        __syncthreads();
        if (ci + 2 < SEQ / 64) load_stage(ci + 2, buf);
    }

    // ---- epilogue: normalize, split hi/lo, store bf16 ----
    float i0 = 1.0f / l0, i1 = 1.0f / l1;
    size_t r0 = (qrow0 + qrw + gid) * EMB + (size_t)h * HD;
    size_t r1 = (qrow0 + qrw + gid + 8) * EMB + (size_t)h * HD;
#pragma unroll
    for (int t = 0; t < 16; t++) {
        int c = t * 8 + tig * 2;
        float v0 = o[t][0] * i0, v1 = o[t][1] * i0;
        float v2 = o[t][2] * i1, v3 = o[t][3] * i1;
        float h0 = __bfloat162float(__float2bfloat16(v0));
        float h1 = __bfloat162float(__float2bfloat16(v1));
        float h2 = __bfloat162float(__float2bfloat16(v2));
        float h3 = __bfloat162float(__float2bfloat16(v3));
        *(uint32_t*)(oh + r0 + c) = pack_bf16(h0, h1);
        *(uint32_t*)(oh + r1 + c) = pack_bf16(h2, h3);
        *(uint32_t*)(ol + r0 + c) = pack_bf16(v0 - h0, v1 - h1);
        *(uint32_t*)(ol + r1 + c) = pack_bf16(v2 - h2, v3 - h3);
    }
}

// ---------------------------------------------------------------------------
// kernel_launch
// ---------------------------------------------------------------------------
extern "C" void kernel_launch(void* const* d_in, const int* in_sizes, int n_in,
                              void* d_out, int out_size)
{
    const float* x  = (const float*)d_in[0];
    const float* Wq = (const float*)d_in[1];
    const float* bq = (const float*)d_in[2];
    const float* Wk = (const float*)d_in[3];
    const float* bk = (const float*)d_in[4];
    const float* Wv = (const float*)d_in[5];
    const float* bv = (const float*)d_in[6];
    const float* Wo = (const float*)d_in[7];
    float* out = (float*)d_out;

    __nv_bfloat16 *pxh, *pxl, *poh, *pol, *pwch, *pwcl, *pwoh, *pwol;
    __half* pqkv;
    float* pbias;
    cudaGetSymbolAddress((void**)&pxh,  g_xhi);
    cudaGetSymbolAddress((void**)&pxl,  g_xlo);
    cudaGetSymbolAddress((void**)&pqkv, g_qkv);
    cudaGetSymbolAddress((void**)&poh,  g_ohi);
    cudaGetSymbolAddress((void**)&pol,  g_olo);
    cudaGetSymbolAddress((void**)&pwch, g_wch);
    cudaGetSymbolAddress((void**)&pwcl, g_wcl);
    cudaGetSymbolAddress((void**)&pwoh, g_woh);
    cudaGetSymbolAddress((void**)&pwol, g_wol);
    cudaGetSymbolAddress((void**)&pbias, g_bias);

    cudaFuncSetAttribute(gemm_mma_kernel<0>,
                         cudaFuncAttributeMaxDynamicSharedMemorySize, GT_SMEM_BYTES);
    cudaFuncSetAttribute(gemm_mma_kernel<1>,
                         cudaFuncAttributeMaxDynamicSharedMemorySize, GT_SMEM_BYTES);
    cudaFuncSetAttribute(flash_mma_kernel,
                         cudaFuncAttributeMaxDynamicSharedMemorySize, FA_SMEM_BYTES);

    const int nx = MROWS * EMB;
    const float qscale = 0.088388347648318447f;   // 1/sqrt(128)

    // 1) split x into bf16 hi/lo
    split_kernel<<<nx / (4 * 256), 256>>>(x, pxh, pxl, nx);

    // 2) transpose + split weights into concat buffer; concat biases (D2D copies)
    dim3 tb(32, 8);
    transpose_split_kernel<<<dim3(EMB / 32, EMB / 32), tb>>>(
        Wq, pwch, pwcl, EMB, EMB);
    transpose_split_kernel<<<dim3(KVW / 32, EMB / 32), tb>>>(
        Wk, pwch + (size_t)EMB * EMB, pwcl + (size_t)EMB * EMB, EMB, KVW);
    transpose_split_kernel<<<dim3(KVW / 32, EMB / 32), tb>>>(
        Wv, pwch + (size_t)(EMB + KVW) * EMB, pwcl + (size_t)(EMB + KVW) * EMB,
        EMB, KVW);
    transpose_split_kernel<<<dim3(EMB / 32, EMB / 32), tb>>>(
        Wo, pwoh, pwol, EMB, EMB);
    cudaMemcpyAsync(pbias,             bq, EMB * sizeof(float), cudaMemcpyDeviceToDevice);
    cudaMemcpyAsync(pbias + EMB,       bk, KVW * sizeof(float), cudaMemcpyDeviceToDevice);
    cudaMemcpyAsync(pbias + EMB + KVW, bv, KVW * sizeof(float), cudaMemcpyDeviceToDevice);

    // 3) fused QKV projection -> fp16 (Q columns pre-scaled by 1/sqrt(HD))
    gemm_mma_kernel<1><<<dim3(QKVW / 128, MROWS / 128), 256, GT_SMEM_BYTES>>>(
        pxh, pxl, pwch, pwcl, pbias, nullptr, pqkv, qscale, EMB,
        MROWS, QKVW, EMB);

    // 4) flash attention (fp16 single-product) -> bf16 hi/lo output
    flash_mma_kernel<<<dim3(SEQ / 128, HQ, BATCH), 256, FA_SMEM_BYTES>>>(
        pqkv, poh, pol);

    // 5) output projection -> fp32
    gemm_mma_kernel<0><<<dim3(EMB / 128, MROWS / 128), 256, GT_SMEM_BYTES>>>(
        poh, pol, pwoh, pwol, (const float*)nullptr, out, nullptr, 1.0f, 0,
        MROWS, EMB, EMB);
}

// round 8
// speedup vs baseline: 7.3172x; 1.3744x over previous
#include <cuda_runtime.h>
#include <cuda_bf16.h>
#include <cuda_fp16.h>
#include <cstdint>

#define BATCH 2
#define SEQ   2048
#define EMB   2048
#define HQ    16
#define HKV   4
#define HD    128
#define KVW   (HKV * HD)        // 512
#define MROWS (BATCH * SEQ)     // 4096
#define QKVW  (EMB + 2 * KVW)   // 3072

// ---------------------------------------------------------------------------
// PTX helpers — ONLY non-arch-suffixed instructions (compute_103-safe)
// ---------------------------------------------------------------------------
__device__ __forceinline__ uint32_t smem_u32(const void* p) {
    uint32_t a;
    asm("{ .reg .u64 t; cvta.to.shared.u64 t, %1; cvt.u32.u64 %0, t; }"
        : "=r"(a) : "l"(p));
    return a;
}

__device__ __forceinline__ void cp16(uint32_t saddr, const void* gaddr) {
    asm volatile("cp.async.cg.shared.global [%0], [%1], 16;"
                 :: "r"(saddr), "l"(gaddr));
}

__device__ __forceinline__ void ldmx4(uint32_t* r, uint32_t addr) {
    asm volatile("ldmatrix.sync.aligned.m8n8.x4.shared.b16 {%0,%1,%2,%3}, [%4];"
                 : "=r"(r[0]), "=r"(r[1]), "=r"(r[2]), "=r"(r[3]) : "r"(addr));
}

__device__ __forceinline__ void ldmx4t(uint32_t* r, uint32_t addr) {
    asm volatile("ldmatrix.sync.aligned.m8n8.x4.trans.shared.b16 {%0,%1,%2,%3}, [%4];"
                 : "=r"(r[0]), "=r"(r[1]), "=r"(r[2]), "=r"(r[3]) : "r"(addr));
}

// bf16 mma
__device__ __forceinline__ void mma16816(float* c, const uint32_t* a,
                                         const uint32_t* b) {
    asm volatile(
        "mma.sync.aligned.m16n8k16.row.col.f32.bf16.bf16.f32 "
        "{%0,%1,%2,%3}, {%4,%5,%6,%7}, {%8,%9}, {%0,%1,%2,%3};"
        : "+f"(c[0]), "+f"(c[1]), "+f"(c[2]), "+f"(c[3])
        : "r"(a[0]), "r"(a[1]), "r"(a[2]), "r"(a[3]), "r"(b[0]), "r"(b[1]));
}

// fp16 mma
__device__ __forceinline__ void mma16816h(float* c, const uint32_t* a,
                                          const uint32_t* b) {
    asm volatile(
        "mma.sync.aligned.m16n8k16.row.col.f32.f16.f16.f32 "
        "{%0,%1,%2,%3}, {%4,%5,%6,%7}, {%8,%9}, {%0,%1,%2,%3};"
        : "+f"(c[0]), "+f"(c[1]), "+f"(c[2]), "+f"(c[3])
        : "r"(a[0]), "r"(a[1]), "r"(a[2]), "r"(a[3]), "r"(b[0]), "r"(b[1]));
}

__device__ __forceinline__ uint32_t pack_bf16(float a, float b) {
    __nv_bfloat162 t = __floats2bfloat162_rn(a, b);
    return *(uint32_t*)&t;
}

// ---------------------------------------------------------------------------
// Device scratch (no cudaMalloc allowed)
// ---------------------------------------------------------------------------
__device__ __half        g_xh[(size_t)MROWS * EMB];       // x fp16
__device__ __half        g_qkv[(size_t)MROWS * QKVW];     // fused q|k|v fp16
__device__ __nv_bfloat16 g_ohi[(size_t)MROWS * EMB];
__device__ __nv_bfloat16 g_olo[(size_t)MROWS * EMB];
__device__ __half        g_wc[(size_t)QKVW * EMB];        // concat Wq|Wk|Wv ^T fp16
__device__ __nv_bfloat16 g_woh[(size_t)EMB * EMB];
__device__ __nv_bfloat16 g_wol[(size_t)EMB * EMB];
__device__ float         g_bias[QKVW];                     // concat bq|bk|bv

// ---------------------------------------------------------------------------
// fp32 -> fp16 convert (elementwise)
// ---------------------------------------------------------------------------
__global__ __launch_bounds__(256) void to_half_kernel(
    const float* __restrict__ x, __half* __restrict__ y, int n)
{
    int i = (blockIdx.x * 256 + threadIdx.x) * 4;
    if (i >= n) return;
    float4 v = *(const float4*)(x + i);
    __half2 h0 = __floats2half2_rn(v.x, v.y);
    __half2 h1 = __floats2half2_rn(v.z, v.w);
    uint2 o = make_uint2(*(uint32_t*)&h0, *(uint32_t*)&h1);
    *(uint2*)(y + i) = o;
}

// ---------------------------------------------------------------------------
// Transpose: W [K,N] fp32 -> T [N,K] fp16
// ---------------------------------------------------------------------------
__global__ __launch_bounds__(256) void transpose_half_kernel(
    const float* __restrict__ W, __half* __restrict__ T, int K, int N)
{
    __shared__ float tile[32][33];
    const int tx = threadIdx.x, ty = threadIdx.y;
    const int nBase = blockIdx.x * 32, kBase = blockIdx.y * 32;
#pragma unroll
    for (int i = 0; i < 4; i++)
        tile[ty + 8 * i][tx] = W[(size_t)(kBase + ty + 8 * i) * N + nBase + tx];
    __syncthreads();
#pragma unroll
    for (int i = 0; i < 4; i++) {
        float v = tile[tx][ty + 8 * i];
        T[(size_t)(nBase + ty + 8 * i) * K + kBase + tx] = __float2half(v);
    }
}

// ---------------------------------------------------------------------------
// Transpose + split: W [K,N] fp32 -> Thi/Tlo [N,K] bf16
// ---------------------------------------------------------------------------
__global__ __launch_bounds__(256) void transpose_split_kernel(
    const float* __restrict__ W, __nv_bfloat16* __restrict__ Thi,
    __nv_bfloat16* __restrict__ Tlo, int K, int N)
{
    __shared__ float tile[32][33];
    const int tx = threadIdx.x, ty = threadIdx.y;
    const int nBase = blockIdx.x * 32, kBase = blockIdx.y * 32;
#pragma unroll
    for (int i = 0; i < 4; i++)
        tile[ty + 8 * i][tx] = W[(size_t)(kBase + ty + 8 * i) * N + nBase + tx];
    __syncthreads();
#pragma unroll
    for (int i = 0; i < 4; i++) {
        float v = tile[tx][ty + 8 * i];
        __nv_bfloat16 h = __float2bfloat16(v);
        __nv_bfloat16 l = __float2bfloat16(v - __bfloat162float(h));
        size_t idx = (size_t)(nBase + ty + 8 * i) * K + kBase + tx;
        Thi[idx] = h;
        Tlo[idx] = l;
    }
}

// ---------------------------------------------------------------------------
// Single-product fp16 GEMM (for QKV projection):
//   C[M,N] fp16 = (A[M,K] @ B[N,K]^T + bias) * (c < qcols ? qsc : 1)
// CTA tile 128x128, 8 warps (2Mx4N), K-chunk 64, 3-stage cp.async pipeline.
// ---------------------------------------------------------------------------
#define GH_STAGE_BYTES 32768                 // A 16KB + B 16KB
#define GH_SMEM_BYTES  (3 * GH_STAGE_BYTES)  // 98304

__global__ __launch_bounds__(256) void gemm_f16_kernel(
    const __half* __restrict__ A, const __half* __restrict__ B,
    const float* __restrict__ bias, __half* __restrict__ C,
    float qsc, int qcols, int M, int N, int K)
{
    extern __shared__ char gsm[];
    const uint32_t sb = smem_u32(gsm);

    const int tid   = threadIdx.x;
    const int wid   = tid >> 5;
    const int lane  = tid & 31;
    const int warpM = wid & 1;
    const int warpN = wid >> 1;
    const int mBase = blockIdx.y * 128;
    const int nBase = blockIdx.x * 128;
    const int nCh   = K >> 6;

    const int aRowOff = lane & 15;
    const int aKOff   = (lane >> 4) << 4;
    const int bRowOff = (lane & 7) + ((lane >> 4) << 3);
    const int bKOff   = ((lane >> 3) & 1) << 4;

    auto swz = [](uint32_t off) { return off ^ ((off >> 3) & 0x70); };

    auto load_chunk = [&](int ci, int buf) {
        const int k0 = ci << 6;
        const uint32_t sbase = sb + (uint32_t)buf * GH_STAGE_BYTES;
#pragma unroll
        for (int t = 0; t < 8; t++) {
            int idx = tid + t * 256;            // 0..2047
            int ab  = idx >> 10;                // 0 = A, 1 = B
            int row = (idx >> 3) & 127;
            int gr  = idx & 7;
            uint32_t off = (uint32_t)(row * 128 + gr * 16);
            uint32_t sw  = off ^ ((off >> 3) & 0x70);
            if (ab == 0)
                cp16(sbase + sw, A + (size_t)(mBase + row) * K + k0 + gr * 8);
            else
                cp16(sbase + 16384 + sw,
                     B + (size_t)(nBase + row) * K + k0 + gr * 8);
        }
        asm volatile("cp.async.commit_group;" ::: "memory");
    };

    float acc[4][4][4];
#pragma unroll
    for (int mt = 0; mt < 4; mt++)
#pragma unroll
        for (int nt = 0; nt < 4; nt++)
#pragma unroll
            for (int i = 0; i < 4; i++) acc[mt][nt][i] = 0.f;

    load_chunk(0, 0);
    load_chunk(1, 1);
    load_chunk(2, 2);

    for (int ci = 0; ci < nCh; ci++) {
        const int buf = ci % 3;
        const int rem = nCh - 1 - ci;           // groups issued beyond ci
        if (rem >= 2)
            asm volatile("cp.async.wait_group 2;" ::: "memory");
        else if (rem == 1)
            asm volatile("cp.async.wait_group 1;" ::: "memory");
        else
            asm volatile("cp.async.wait_group 0;" ::: "memory");
        __syncthreads();

        const uint32_t sbase = sb + (uint32_t)buf * GH_STAGE_BYTES;
        const uint32_t aB = sbase;
        const uint32_t bB = sbase + 16384;

#pragma unroll
        for (int ks = 0; ks < 4; ks++) {
            const int kByte = ks * 32;
            uint32_t af[4][4];
#pragma unroll
            for (int mt = 0; mt < 4; mt++) {
                uint32_t off = (uint32_t)((warpM * 64 + mt * 16 + aRowOff) * 128
                                          + kByte + aKOff);
                ldmx4(af[mt], aB + swz(off));
            }
            uint32_t bf[2][4];
#pragma unroll
            for (int p = 0; p < 2; p++) {
                uint32_t off = (uint32_t)((warpN * 32 + p * 16 + bRowOff) * 128
                                          + kByte + bKOff);
                ldmx4(bf[p], bB + swz(off));
            }
#pragma unroll
            for (int mt = 0; mt < 4; mt++)
#pragma unroll
                for (int nt = 0; nt < 4; nt++)
                    mma16816h(acc[mt][nt], af[mt], &bf[nt >> 1][(nt & 1) * 2]);
        }
        __syncthreads();
        if (ci + 3 < nCh) load_chunk(ci + 3, buf);
    }

    // Epilogue: fp16 out, +bias, per-column scale
    const int mW = mBase + warpM * 64;
    const int nW = nBase + warpN * 32;
#pragma unroll
    for (int mt = 0; mt < 4; mt++) {
#pragma unroll
        for (int nt = 0; nt < 4; nt++) {
            int r0 = mW + mt * 16 + (lane >> 2);
            int c  = nW + nt * 8 + (lane & 3) * 2;
            float2 bv = *(const float2*)(bias + c);
            float sc = (c < qcols) ? qsc : 1.f;
            float v0 = (acc[mt][nt][0] + bv.x) * sc;
            float v1 = (acc[mt][nt][1] + bv.y) * sc;
            float v2 = (acc[mt][nt][2] + bv.x) * sc;
            float v3 = (acc[mt][nt][3] + bv.y) * sc;
            __half2 h01 = __floats2half2_rn(v0, v1);
            __half2 h23 = __floats2half2_rn(v2, v3);
            *(uint32_t*)(C + (size_t)r0 * N + c)       = *(uint32_t*)&h01;
            *(uint32_t*)(C + (size_t)(r0 + 8) * N + c) = *(uint32_t*)&h23;
        }
    }
}

// ---------------------------------------------------------------------------
// Tensor-core GEMM (HMMA bf16 hi/lo, 3 products) — out projection, fp32 out.
// ---------------------------------------------------------------------------
#define GT_STAGE_BYTES 65536
#define GT_SMEM_BYTES  (2 * GT_STAGE_BYTES)

__global__ __launch_bounds__(256) void gemm_mma_kernel(
    const __nv_bfloat16* __restrict__ Ahi, const __nv_bfloat16* __restrict__ Alo,
    const __nv_bfloat16* __restrict__ Bhi, const __nv_bfloat16* __restrict__ Blo,
    float* __restrict__ Cf, int M, int N, int K)
{
    extern __shared__ char gsm[];
    const uint32_t sb = smem_u32(gsm);

    const int tid   = threadIdx.x;
    const int wid   = tid >> 5;
    const int lane  = tid & 31;
    const int warpM = wid & 1;
    const int warpN = wid >> 1;
    const int mBase = blockIdx.y * 128;
    const int nBase = blockIdx.x * 128;
    const int nCh   = K >> 6;

    const int aRowOff = lane & 15;
    const int aKOff   = (lane >> 4) << 4;
    const int bRowOff = (lane & 7) + ((lane >> 4) << 3);
    const int bKOff   = ((lane >> 3) & 1) << 4;

    auto swz = [](uint32_t off) { return off ^ ((off >> 3) & 0x70); };

    auto load_chunk = [&](int ci, int buf) {
        const int k0 = ci << 6;
        const uint32_t sbase = sb + (uint32_t)buf * GT_STAGE_BYTES;
#pragma unroll
        for (int t = 0; t < 4; t++) {
            int idx = tid + t * 256;
            int row = idx >> 3;
            int gr  = idx & 7;
            uint32_t off = (uint32_t)(row * 128 + gr * 16);
            uint32_t sw  = off ^ ((off >> 3) & 0x70);
            size_t aoff = (size_t)(mBase + row) * K + k0 + gr * 8;
            size_t boff = (size_t)(nBase + row) * K + k0 + gr * 8;
            cp16(sbase +         sw, Ahi + aoff);
            cp16(sbase + 16384 + sw, Alo + aoff);
            cp16(sbase + 32768 + sw, Bhi + boff);
            cp16(sbase + 49152 + sw, Blo + boff);
        }
        asm volatile("cp.async.commit_group;" ::: "memory");
    };

    float acc[4][4][4];
#pragma unroll
    for (int mt = 0; mt < 4; mt++)
#pragma unroll
        for (int nt = 0; nt < 4; nt++)
#pragma unroll
            for (int i = 0; i < 4; i++) acc[mt][nt][i] = 0.f;

    load_chunk(0, 0);
    load_chunk(1, 1);

    for (int ci = 0; ci < nCh; ci++) {
        const int buf = ci & 1;
        if (ci + 1 < nCh)
            asm volatile("cp.async.wait_group 1;" ::: "memory");
        else
            asm volatile("cp.async.wait_group 0;" ::: "memory");
        __syncthreads();

        const uint32_t sbase = sb + (uint32_t)buf * GT_STAGE_BYTES;
        const uint32_t ahB = sbase;
        const uint32_t alB = sbase + 16384;
        const uint32_t bhB = sbase + 32768;
        const uint32_t blB = sbase + 49152;

#pragma unroll
        for (int ks = 0; ks < 4; ks++) {
            const int kByte = ks * 32;
            uint32_t ah[4][4], al[4][4];
#pragma unroll
            for (int mt = 0; mt < 4; mt++) {
                uint32_t off = (uint32_t)((warpM * 64 + mt * 16 + aRowOff) * 128
                                          + kByte + aKOff);
                uint32_t s = swz(off);
                ldmx4(ah[mt], ahB + s);
                ldmx4(al[mt], alB + s);
            }
            uint32_t bh[2][4], bl[2][4];
#pragma unroll
            for (int p = 0; p < 2; p++) {
                uint32_t off = (uint32_t)((warpN * 32 + p * 16 + bRowOff) * 128
                                          + kByte + bKOff);
                uint32_t s = swz(off);
                ldmx4(bh[p], bhB + s);
                ldmx4(bl[p], blB + s);
            }
#pragma unroll
            for (int mt = 0; mt < 4; mt++)
#pragma unroll
                for (int nt = 0; nt < 4; nt++) {
                    const uint32_t* bhf = &bh[nt >> 1][(nt & 1) * 2];
                    const uint32_t* blf = &bl[nt >> 1][(nt & 1) * 2];
                    mma16816(acc[mt][nt], ah[mt], bhf);
                    mma16816(acc[mt][nt], ah[mt], blf);
                    mma16816(acc[mt][nt], al[mt], bhf);
                }
        }
        __syncthreads();
        if (ci + 2 < nCh) load_chunk(ci + 2, buf);
    }

    const int mW = mBase + warpM * 64;
    const int nW = nBase + warpN * 32;
#pragma unroll
    for (int mt = 0; mt < 4; mt++) {
#pragma unroll
        for (int nt = 0; nt < 4; nt++) {
            int r0 = mW + mt * 16 + (lane >> 2);
            int c  = nW + nt * 8 + (lane & 3) * 2;
            *(float2*)(Cf + (size_t)r0 * N + c) =
                make_float2(acc[mt][nt][0], acc[mt][nt][1]);
            *(float2*)(Cf + (size_t)(r0 + 8) * N + c) =
                make_float2(acc[mt][nt][2], acc[mt][nt][3]);
        }
    }
}

// ---------------------------------------------------------------------------
// Flash attention, fp16 single-product mma (byte-identical to R7).
// ---------------------------------------------------------------------------
#define FA_SMEM_BYTES (32768 + 2 * 32768)   // 98304

__global__ __launch_bounds__(256, 1) void flash_mma_kernel(
    const __half* __restrict__ qkv,
    __nv_bfloat16* __restrict__ oh, __nv_bfloat16* __restrict__ ol)
{
    extern __shared__ char fsm[];
    const uint32_t sb  = smem_u32(fsm);
    const int tid  = threadIdx.x;
    const int wid  = tid >> 5;
    const int lane = tid & 31;
    const int q0 = blockIdx.x * 128;
    const int h  = blockIdx.y;
    const int b  = blockIdx.z;
    const int g  = h >> 2;

    const uint32_t QS  = sb;
    const uint32_t STG = sb + 32768;

    const size_t qrow0 = (size_t)b * SEQ + q0;
    const int qcol = h * HD;
    const int kcol = EMB + g * HD;
    const int vcol = EMB + KVW + g * HD;

#pragma unroll
    for (int t = 0; t < 8; t++) {
        int idx = tid + t * 256;
        int row = idx >> 4;
        int gr  = idx & 15;
        int blk = gr >> 3;
        uint32_t off = (uint32_t)(row * 128 + (gr & 7) * 16);
        uint32_t sw  = off ^ ((off >> 3) & 0x70);
        size_t go = (qrow0 + row) * QKVW + qcol + gr * 8;
        cp16(QS + blk * 16384 + sw, qkv + go);
    }
    asm volatile("cp.async.commit_group;" ::: "memory");

    auto load_stage = [&](int ci, int buf) {
        const uint32_t s0 = STG + (uint32_t)buf * 32768u;
        const int kr0 = ci * 64;
#pragma unroll
        for (int t = 0; t < 8; t++) {
            int arr = t >> 2;
            int idx = tid + (t & 3) * 256;
            int row = idx >> 4;
            int gr  = idx & 15;
            int blk = gr >> 3;
            uint32_t off = (uint32_t)(row * 128 + (gr & 7) * 16);
            uint32_t sw  = off ^ ((off >> 3) & 0x70);
            uint32_t dst = s0 + (uint32_t)arr * 16384u + (uint32_t)blk * 8192u + sw;
            int col = (arr == 0) ? kcol : vcol;
            size_t go = (size_t)(b * SEQ + kr0 + row) * QKVW + col + gr * 8;
            cp16(dst, qkv + go);
        }
        asm volatile("cp.async.commit_group;" ::: "memory");
    };

    load_stage(0, 0);
    load_stage(1, 1);

    const int gid = lane >> 2, tig = lane & 3;
    const int qrw = wid * 16;

    const int aRow = lane & 15;
    const int aCol = (lane >> 4) << 4;
    const int bRow = (lane & 7) + ((lane >> 4) << 3);
    const int bCol = ((lane >> 3) & 1) << 4;
    const int vRow = (lane & 7) + (((lane >> 3) & 1) << 3);
    const int vCol = (lane >> 4) << 4;

    float m0 = -1e30f, m1 = -1e30f, l0 = 0.f, l1 = 0.f;
    float o[16][4];
#pragma unroll
    for (int t = 0; t < 16; t++)
#pragma unroll
        for (int i = 0; i < 4; i++) o[t][i] = 0.f;

    for (int ci = 0; ci < SEQ / 64; ci++) {
        const int buf = ci & 1;
        if (ci + 1 < SEQ / 64)
            asm volatile("cp.async.wait_group 1;" ::: "memory");
        else
            asm volatile("cp.async.wait_group 0;" ::: "memory");
        __syncthreads();

        const uint32_t s0 = STG + (uint32_t)buf * 32768u;
        const uint32_t KB = s0, VB = s0 + 16384;

        float s[8][4];
#pragma unroll
        for (int t = 0; t < 8; t++)
#pragma unroll
            for (int i = 0; i < 4; i++) s[t][i] = 0.f;

#pragma unroll
        for (int ks = 0; ks < 8; ks++) {
            const int blk = ks >> 2;
            const int kb  = (ks & 3) * 32;
            uint32_t qa[4];
            uint32_t offq = (uint32_t)((qrw + aRow) * 128 + kb + aCol);
            uint32_t swq  = offq ^ ((offq >> 3) & 0x70);
            ldmx4(qa, QS + blk * 16384 + swq);
#pragma unroll
            for (int nb = 0; nb < 4; nb++) {
                uint32_t kf[4];
                uint32_t offk = (uint32_t)((nb * 16 + bRow) * 128 + kb + bCol);
                uint32_t swk  = offk ^ ((offk >> 3) & 0x70);
                ldmx4(kf, KB + blk * 8192 + swk);
                mma16816h(s[2 * nb],     qa, &kf[0]);
                mma16816h(s[2 * nb + 1], qa, &kf[2]);
            }
        }

        float mx0 = -1e30f, mx1 = -1e30f;
#pragma unroll
        for (int t = 0; t < 8; t++) {
            mx0 = fmaxf(mx0, fmaxf(s[t][0], s[t][1]));
            mx1 = fmaxf(mx1, fmaxf(s[t][2], s[t][3]));
        }
        mx0 = fmaxf(mx0, __shfl_xor_sync(0xffffffffu, mx0, 1));
        mx0 = fmaxf(mx0, __shfl_xor_sync(0xffffffffu, mx0, 2));
        mx1 = fmaxf(mx1, __shfl_xor_sync(0xffffffffu, mx1, 1));
        mx1 = fmaxf(mx1, __shfl_xor_sync(0xffffffffu, mx1, 2));

        float mn0 = fmaxf(m0, mx0), mn1 = fmaxf(m1, mx1);
        float a0 = __expf(m0 - mn0), a1 = __expf(m1 - mn1);
        m0 = mn0; m1 = mn1;

        float rs0 = 0.f, rs1 = 0.f;
        uint32_t pa[4][4];
#pragma unroll
        for (int t = 0; t < 8; t++) {
            float p0 = __expf(s[t][0] - mn0);
            float p1 = __expf(s[t][1] - mn0);
            float p2 = __expf(s[t][2] - mn1);
            float p3 = __expf(s[t][3] - mn1);
            __half2 h01 = __floats2half2_rn(p0, p1);
            __half2 h23 = __floats2half2_rn(p2, p3);
            float2 f01 = __half22float2(h01);
            float2 f23 = __half22float2(h23);
            rs0 += f01.x + f01.y;
            rs1 += f23.x + f23.y;
            int j = t >> 1, sl = (t & 1) * 2;
            pa[j][sl]     = *(uint32_t*)&h01;
            pa[j][sl + 1] = *(uint32_t*)&h23;
        }
        rs0 += __shfl_xor_sync(0xffffffffu, rs0, 1);
        rs0 += __shfl_xor_sync(0xffffffffu, rs0, 2);
        rs1 += __shfl_xor_sync(0xffffffffu, rs1, 1);
        rs1 += __shfl_xor_sync(0xffffffffu, rs1, 2);
        l0 = l0 * a0 + rs0;
        l1 = l1 * a1 + rs1;

#pragma unroll
        for (int t = 0; t < 16; t++) {
            o[t][0] *= a0; o[t][1] *= a0;
            o[t][2] *= a1; o[t][3] *= a1;
        }

#pragma unroll
        for (int j = 0; j < 4; j++) {
#pragma unroll
            for (int tp = 0; tp < 8; tp++) {
                const int blk = tp >> 2;
                const int cb  = (tp & 3) * 32 + vCol;
                uint32_t offv = (uint32_t)((j * 16 + vRow) * 128 + cb);
                uint32_t swv  = offv ^ ((offv >> 3) & 0x70);
                uint32_t vf[4];
                ldmx4t(vf, VB + blk * 8192 + swv);
                mma16816h(o[2 * tp],     pa[j], &vf[0]);
                mma16816h(o[2 * tp + 1], pa[j], &vf[2]);
            }
        }

        __syncthreads();
        if (ci + 2 < SEQ / 64) load_stage(ci + 2, buf);
    }

    float i0 = 1.0f / l0, i1 = 1.0f / l1;
    size_t r0 = (qrow0 + qrw + gid) * EMB + (size_t)h * HD;
    size_t r1 = (qrow0 + qrw + gid + 8) * EMB + (size_t)h * HD;
#pragma unroll
    for (int t = 0; t < 16; t++) {
        int c = t * 8 + tig * 2;
        float v0 = o[t][0] * i0, v1 = o[t][1] * i0;
        float v2 = o[t][2] * i1, v3 = o[t][3] * i1;
        float h0 = __bfloat162float(__float2bfloat16(v0));
        float h1 = __bfloat162float(__float2bfloat16(v1));
        float h2 = __bfloat162float(__float2bfloat16(v2));
        float h3 = __bfloat162float(__float2bfloat16(v3));
        *(uint32_t*)(oh + r0 + c) = pack_bf16(h0, h1);
        *(uint32_t*)(oh + r1 + c) = pack_bf16(h2, h3);
        *(uint32_t*)(ol + r0 + c) = pack_bf16(v0 - h0, v1 - h1);
        *(uint32_t*)(ol + r1 + c) = pack_bf16(v2 - h2, v3 - h3);
    }
}

// ---------------------------------------------------------------------------
// kernel_launch
// ---------------------------------------------------------------------------
extern "C" void kernel_launch(void* const* d_in, const int* in_sizes, int n_in,
                              void* d_out, int out_size)
{
    const float* x  = (const float*)d_in[0];
    const float* Wq = (const float*)d_in[1];
    const float* bq = (const float*)d_in[2];
    const float* Wk = (const float*)d_in[3];
    const float* bk = (const float*)d_in[4];
    const float* Wv = (const float*)d_in[5];
    const float* bv = (const float*)d_in[6];
    const float* Wo = (const float*)d_in[7];
    float* out = (float*)d_out;

    __half *pxh, *pqkv, *pwc;
    __nv_bfloat16 *poh, *pol, *pwoh, *pwol;
    float* pbias;
    cudaGetSymbolAddress((void**)&pxh,  g_xh);
    cudaGetSymbolAddress((void**)&pqkv, g_qkv);
    cudaGetSymbolAddress((void**)&pwc,  g_wc);
    cudaGetSymbolAddress((void**)&poh,  g_ohi);
    cudaGetSymbolAddress((void**)&pol,  g_olo);
    cudaGetSymbolAddress((void**)&pwoh, g_woh);
    cudaGetSymbolAddress((void**)&pwol, g_wol);
    cudaGetSymbolAddress((void**)&pbias, g_bias);

    cudaFuncSetAttribute(gemm_f16_kernel,
                         cudaFuncAttributeMaxDynamicSharedMemorySize, GH_SMEM_BYTES);
    cudaFuncSetAttribute(gemm_mma_kernel,
                         cudaFuncAttributeMaxDynamicSharedMemorySize, GT_SMEM_BYTES);
    cudaFuncSetAttribute(flash_mma_kernel,
                         cudaFuncAttributeMaxDynamicSharedMemorySize, FA_SMEM_BYTES);

    const int nx = MROWS * EMB;
    const float qscale = 0.088388347648318447f;   // 1/sqrt(128)

    // 1) x -> fp16
    to_half_kernel<<<nx / (4 * 256), 256>>>(x, pxh, nx);

    // 2) transpose weights: QKV -> concat fp16 [3072,2048]; Wo -> bf16 hi/lo
    dim3 tb(32, 8);
    transpose_half_kernel<<<dim3(EMB / 32, EMB / 32), tb>>>(Wq, pwc, EMB, EMB);
    transpose_half_kernel<<<dim3(KVW / 32, EMB / 32), tb>>>(
        Wk, pwc + (size_t)EMB * EMB, EMB, KVW);
    transpose_half_kernel<<<dim3(KVW / 32, EMB / 32), tb>>>(
        Wv, pwc + (size_t)(EMB + KVW) * EMB, EMB, KVW);
    transpose_split_kernel<<<dim3(EMB / 32, EMB / 32), tb>>>(
        Wo, pwoh, pwol, EMB, EMB);
    cudaMemcpyAsync(pbias,             bq, EMB * sizeof(float), cudaMemcpyDeviceToDevice);
    cudaMemcpyAsync(pbias + EMB,       bk, KVW * sizeof(float), cudaMemcpyDeviceToDevice);
    cudaMemcpyAsync(pbias + EMB + KVW, bv, KVW * sizeof(float), cudaMemcpyDeviceToDevice);

    // 3) fused QKV projection, single-product fp16 (Q cols pre-scaled)
    gemm_f16_kernel<<<dim3(QKVW / 128, MROWS / 128), 256, GH_SMEM_BYTES>>>(
        pxh, pwc, pbias, pqkv, qscale, EMB, MROWS, QKVW, EMB);

    // 4) flash attention (fp16 single-product) -> bf16 hi/lo output
    flash_mma_kernel<<<dim3(SEQ / 128, HQ, BATCH), 256, FA_SMEM_BYTES>>>(
        pqkv, poh, pol);

    // 5) output projection (bf16 hi/lo, 3 products) -> fp32
    gemm_mma_kernel<<<dim3(EMB / 128, MROWS / 128), 256, GT_SMEM_BYTES>>>(
        poh, pol, pwoh, pwol, out, MROWS, EMB, EMB);
}

// round 9
// speedup vs baseline: 7.5441x; 1.0310x over previous
#include <cuda_runtime.h>
#include <cuda_bf16.h>
#include <cuda_fp16.h>
#include <cstdint>

#define BATCH 2
#define SEQ   2048
#define EMB   2048
#define HQ    16
#define HKV   4
#define HD    128
#define KVW   (HKV * HD)        // 512
#define MROWS (BATCH * SEQ)     // 4096
#define QKVW  (EMB + 2 * KVW)   // 3072

// ---------------------------------------------------------------------------
// PTX helpers — ONLY non-arch-suffixed instructions (compute_103-safe)
// ---------------------------------------------------------------------------
__device__ __forceinline__ uint32_t smem_u32(const void* p) {
    uint32_t a;
    asm("{ .reg .u64 t; cvta.to.shared.u64 t, %1; cvt.u32.u64 %0, t; }"
        : "=r"(a) : "l"(p));
    return a;
}

__device__ __forceinline__ void cp16(uint32_t saddr, const void* gaddr) {
    asm volatile("cp.async.cg.shared.global [%0], [%1], 16;"
                 :: "r"(saddr), "l"(gaddr));
}

__device__ __forceinline__ void ldmx4(uint32_t* r, uint32_t addr) {
    asm volatile("ldmatrix.sync.aligned.m8n8.x4.shared.b16 {%0,%1,%2,%3}, [%4];"
                 : "=r"(r[0]), "=r"(r[1]), "=r"(r[2]), "=r"(r[3]) : "r"(addr));
}

__device__ __forceinline__ void ldmx4t(uint32_t* r, uint32_t addr) {
    asm volatile("ldmatrix.sync.aligned.m8n8.x4.trans.shared.b16 {%0,%1,%2,%3}, [%4];"
                 : "=r"(r[0]), "=r"(r[1]), "=r"(r[2]), "=r"(r[3]) : "r"(addr));
}

// bf16 mma
__device__ __forceinline__ void mma16816(float* c, const uint32_t* a,
                                         const uint32_t* b) {
    asm volatile(
        "mma.sync.aligned.m16n8k16.row.col.f32.bf16.bf16.f32 "
        "{%0,%1,%2,%3}, {%4,%5,%6,%7}, {%8,%9}, {%0,%1,%2,%3};"
        : "+f"(c[0]), "+f"(c[1]), "+f"(c[2]), "+f"(c[3])
        : "r"(a[0]), "r"(a[1]), "r"(a[2]), "r"(a[3]), "r"(b[0]), "r"(b[1]));
}

// fp16 mma
__device__ __forceinline__ void mma16816h(float* c, const uint32_t* a,
                                          const uint32_t* b) {
    asm volatile(
        "mma.sync.aligned.m16n8k16.row.col.f32.f16.f16.f32 "
        "{%0,%1,%2,%3}, {%4,%5,%6,%7}, {%8,%9}, {%0,%1,%2,%3};"
        : "+f"(c[0]), "+f"(c[1]), "+f"(c[2]), "+f"(c[3])
        : "r"(a[0]), "r"(a[1]), "r"(a[2]), "r"(a[3]), "r"(b[0]), "r"(b[1]));
}

__device__ __forceinline__ float ex2(float x) {
    float y;
    asm("ex2.approx.f32 %0, %1;" : "=f"(y) : "f"(x));
    return y;
}

__device__ __forceinline__ uint32_t pack_bf16(float a, float b) {
    __nv_bfloat162 t = __floats2bfloat162_rn(a, b);
    return *(uint32_t*)&t;
}

// ---------------------------------------------------------------------------
// Device scratch (no cudaMalloc allowed)
// ---------------------------------------------------------------------------
__device__ __half        g_xh[(size_t)MROWS * EMB];       // x fp16
__device__ __half        g_qkv[(size_t)MROWS * QKVW];     // fused q|k|v fp16
__device__ __nv_bfloat16 g_ohi[(size_t)MROWS * EMB];
__device__ __nv_bfloat16 g_olo[(size_t)MROWS * EMB];
__device__ __half        g_wc[(size_t)QKVW * EMB];        // concat Wq|Wk|Wv ^T fp16
__device__ __nv_bfloat16 g_woh[(size_t)EMB * EMB];
__device__ __nv_bfloat16 g_wol[(size_t)EMB * EMB];
__device__ float         g_bias[QKVW];                     // concat bq|bk|bv

// ---------------------------------------------------------------------------
// fp32 -> fp16 convert (elementwise)
// ---------------------------------------------------------------------------
__global__ __launch_bounds__(256) void to_half_kernel(
    const float* __restrict__ x, __half* __restrict__ y, int n)
{
    int i = (blockIdx.x * 256 + threadIdx.x) * 4;
    if (i >= n) return;
    float4 v = *(const float4*)(x + i);
    __half2 h0 = __floats2half2_rn(v.x, v.y);
    __half2 h1 = __floats2half2_rn(v.z, v.w);
    uint2 o = make_uint2(*(uint32_t*)&h0, *(uint32_t*)&h1);
    *(uint2*)(y + i) = o;
}

// ---------------------------------------------------------------------------
// Transpose: W [K,N] fp32 -> T [N,K] fp16
// ---------------------------------------------------------------------------
__global__ __launch_bounds__(256) void transpose_half_kernel(
    const float* __restrict__ W, __half* __restrict__ T, int K, int N)
{
    __shared__ float tile[32][33];
    const int tx = threadIdx.x, ty = threadIdx.y;
    const int nBase = blockIdx.x * 32, kBase = blockIdx.y * 32;
#pragma unroll
    for (int i = 0; i < 4; i++)
        tile[ty + 8 * i][tx] = W[(size_t)(kBase + ty + 8 * i) * N + nBase + tx];
    __syncthreads();
#pragma unroll
    for (int i = 0; i < 4; i++) {
        float v = tile[tx][ty + 8 * i];
        T[(size_t)(nBase + ty + 8 * i) * K + kBase + tx] = __float2half(v);
    }
}

// ---------------------------------------------------------------------------
// Transpose + split: W [K,N] fp32 -> Thi/Tlo [N,K] bf16
// ---------------------------------------------------------------------------
__global__ __launch_bounds__(256) void transpose_split_kernel(
    const float* __restrict__ W, __nv_bfloat16* __restrict__ Thi,
    __nv_bfloat16* __restrict__ Tlo, int K, int N)
{
    __shared__ float tile[32][33];
    const int tx = threadIdx.x, ty = threadIdx.y;
    const int nBase = blockIdx.x * 32, kBase = blockIdx.y * 32;
#pragma unroll
    for (int i = 0; i < 4; i++)
        tile[ty + 8 * i][tx] = W[(size_t)(kBase + ty + 8 * i) * N + nBase + tx];
    __syncthreads();
#pragma unroll
    for (int i = 0; i < 4; i++) {
        float v = tile[tx][ty + 8 * i];
        __nv_bfloat16 h = __float2bfloat16(v);
        __nv_bfloat16 l = __float2bfloat16(v - __bfloat162float(h));
        size_t idx = (size_t)(nBase + ty + 8 * i) * K + kBase + tx;
        Thi[idx] = h;
        Tlo[idx] = l;
    }
}

// ---------------------------------------------------------------------------
// Single-product fp16 GEMM (QKV projection), 3-stage cp.async pipeline.
// ---------------------------------------------------------------------------
#define GH_STAGE_BYTES 32768                 // A 16KB + B 16KB
#define GH_SMEM_BYTES  (3 * GH_STAGE_BYTES)  // 98304

__global__ __launch_bounds__(256) void gemm_f16_kernel(
    const __half* __restrict__ A, const __half* __restrict__ B,
    const float* __restrict__ bias, __half* __restrict__ C,
    float qsc, int qcols, int M, int N, int K)
{
    extern __shared__ char gsm[];
    const uint32_t sb = smem_u32(gsm);

    const int tid   = threadIdx.x;
    const int wid   = tid >> 5;
    const int lane  = tid & 31;
    const int warpM = wid & 1;
    const int warpN = wid >> 1;
    const int mBase = blockIdx.y * 128;
    const int nBase = blockIdx.x * 128;
    const int nCh   = K >> 6;

    const int aRowOff = lane & 15;
    const int aKOff   = (lane >> 4) << 4;
    const int bRowOff = (lane & 7) + ((lane >> 4) << 3);
    const int bKOff   = ((lane >> 3) & 1) << 4;

    auto swz = [](uint32_t off) { return off ^ ((off >> 3) & 0x70); };

    auto load_chunk = [&](int ci, int buf) {
        const int k0 = ci << 6;
        const uint32_t sbase = sb + (uint32_t)buf * GH_STAGE_BYTES;
#pragma unroll
        for (int t = 0; t < 8; t++) {
            int idx = tid + t * 256;
            int ab  = idx >> 10;
            int row = (idx >> 3) & 127;
            int gr  = idx & 7;
            uint32_t off = (uint32_t)(row * 128 + gr * 16);
            uint32_t sw  = off ^ ((off >> 3) & 0x70);
            if (ab == 0)
                cp16(sbase + sw, A + (size_t)(mBase + row) * K + k0 + gr * 8);
            else
                cp16(sbase + 16384 + sw,
                     B + (size_t)(nBase + row) * K + k0 + gr * 8);
        }
        asm volatile("cp.async.commit_group;" ::: "memory");
    };

    float acc[4][4][4];
#pragma unroll
    for (int mt = 0; mt < 4; mt++)
#pragma unroll
        for (int nt = 0; nt < 4; nt++)
#pragma unroll
            for (int i = 0; i < 4; i++) acc[mt][nt][i] = 0.f;

    load_chunk(0, 0);
    load_chunk(1, 1);
    load_chunk(2, 2);

    for (int ci = 0; ci < nCh; ci++) {
        const int buf = ci % 3;
        const int rem = nCh - 1 - ci;
        if (rem >= 2)
            asm volatile("cp.async.wait_group 2;" ::: "memory");
        else if (rem == 1)
            asm volatile("cp.async.wait_group 1;" ::: "memory");
        else
            asm volatile("cp.async.wait_group 0;" ::: "memory");
        __syncthreads();

        const uint32_t sbase = sb + (uint32_t)buf * GH_STAGE_BYTES;
        const uint32_t aB = sbase;
        const uint32_t bB = sbase + 16384;

#pragma unroll
        for (int ks = 0; ks < 4; ks++) {
            const int kByte = ks * 32;
            uint32_t af[4][4];
#pragma unroll
            for (int mt = 0; mt < 4; mt++) {
                uint32_t off = (uint32_t)((warpM * 64 + mt * 16 + aRowOff) * 128
                                          + kByte + aKOff);
                ldmx4(af[mt], aB + swz(off));
            }
            uint32_t bf[2][4];
#pragma unroll
            for (int p = 0; p < 2; p++) {
                uint32_t off = (uint32_t)((warpN * 32 + p * 16 + bRowOff) * 128
                                          + kByte + bKOff);
                ldmx4(bf[p], bB + swz(off));
            }
#pragma unroll
            for (int mt = 0; mt < 4; mt++)
#pragma unroll
                for (int nt = 0; nt < 4; nt++)
                    mma16816h(acc[mt][nt], af[mt], &bf[nt >> 1][(nt & 1) * 2]);
        }
        __syncthreads();
        if (ci + 3 < nCh) load_chunk(ci + 3, buf);
    }

    const int mW = mBase + warpM * 64;
    const int nW = nBase + warpN * 32;
#pragma unroll
    for (int mt = 0; mt < 4; mt++) {
#pragma unroll
        for (int nt = 0; nt < 4; nt++) {
            int r0 = mW + mt * 16 + (lane >> 2);
            int c  = nW + nt * 8 + (lane & 3) * 2;
            float2 bv = *(const float2*)(bias + c);
            float sc = (c < qcols) ? qsc : 1.f;
            float v0 = (acc[mt][nt][0] + bv.x) * sc;
            float v1 = (acc[mt][nt][1] + bv.y) * sc;
            float v2 = (acc[mt][nt][2] + bv.x) * sc;
            float v3 = (acc[mt][nt][3] + bv.y) * sc;
            __half2 h01 = __floats2half2_rn(v0, v1);
            __half2 h23 = __floats2half2_rn(v2, v3);
            *(uint32_t*)(C + (size_t)r0 * N + c)       = *(uint32_t*)&h01;
            *(uint32_t*)(C + (size_t)(r0 + 8) * N + c) = *(uint32_t*)&h23;
        }
    }
}

// ---------------------------------------------------------------------------
// Out projection: HMMA bf16 hi/lo (3 products), fp32 out, 3-stage pipeline.
// ---------------------------------------------------------------------------
#define GT_STAGE_BYTES 65536
#define GT_SMEM_BYTES  (3 * GT_STAGE_BYTES)   // 196608

__global__ __launch_bounds__(256) void gemm_mma_kernel(
    const __nv_bfloat16* __restrict__ Ahi, const __nv_bfloat16* __restrict__ Alo,
    const __nv_bfloat16* __restrict__ Bhi, const __nv_bfloat16* __restrict__ Blo,
    float* __restrict__ Cf, int M, int N, int K)
{
    extern __shared__ char gsm[];
    const uint32_t sb = smem_u32(gsm);

    const int tid   = threadIdx.x;
    const int wid   = tid >> 5;
    const int lane  = tid & 31;
    const int warpM = wid & 1;
    const int warpN = wid >> 1;
    const int mBase = blockIdx.y * 128;
    const int nBase = blockIdx.x * 128;
    const int nCh   = K >> 6;

    const int aRowOff = lane & 15;
    const int aKOff   = (lane >> 4) << 4;
    const int bRowOff = (lane & 7) + ((lane >> 4) << 3);
    const int bKOff   = ((lane >> 3) & 1) << 4;

    auto swz = [](uint32_t off) { return off ^ ((off >> 3) & 0x70); };

    auto load_chunk = [&](int ci, int buf) {
        const int k0 = ci << 6;
        const uint32_t sbase = sb + (uint32_t)buf * GT_STAGE_BYTES;
#pragma unroll
        for (int t = 0; t < 4; t++) {
            int idx = tid + t * 256;
            int row = idx >> 3;
            int gr  = idx & 7;
            uint32_t off = (uint32_t)(row * 128 + gr * 16);
            uint32_t sw  = off ^ ((off >> 3) & 0x70);
            size_t aoff = (size_t)(mBase + row) * K + k0 + gr * 8;
            size_t boff = (size_t)(nBase + row) * K + k0 + gr * 8;
            cp16(sbase +         sw, Ahi + aoff);
            cp16(sbase + 16384 + sw, Alo + aoff);
            cp16(sbase + 32768 + sw, Bhi + boff);
            cp16(sbase + 49152 + sw, Blo + boff);
        }
        asm volatile("cp.async.commit_group;" ::: "memory");
    };

    float acc[4][4][4];
#pragma unroll
    for (int mt = 0; mt < 4; mt++)
#pragma unroll
        for (int nt = 0; nt < 4; nt++)
#pragma unroll
            for (int i = 0; i < 4; i++) acc[mt][nt][i] = 0.f;

    load_chunk(0, 0);
    load_chunk(1, 1);
    load_chunk(2, 2);

    for (int ci = 0; ci < nCh; ci++) {
        const int buf = ci % 3;
        const int rem = nCh - 1 - ci;
        if (rem >= 2)
            asm volatile("cp.async.wait_group 2;" ::: "memory");
        else if (rem == 1)
            asm volatile("cp.async.wait_group 1;" ::: "memory");
        else
            asm volatile("cp.async.wait_group 0;" ::: "memory");
        __syncthreads();

        const uint32_t sbase = sb + (uint32_t)buf * GT_STAGE_BYTES;
        const uint32_t ahB = sbase;
        const uint32_t alB = sbase + 16384;
        const uint32_t bhB = sbase + 32768;
        const uint32_t blB = sbase + 49152;

#pragma unroll
        for (int ks = 0; ks < 4; ks++) {
            const int kByte = ks * 32;
            uint32_t ah[4][4], al[4][4];
#pragma unroll
            for (int mt = 0; mt < 4; mt++) {
                uint32_t off = (uint32_t)((warpM * 64 + mt * 16 + aRowOff) * 128
                                          + kByte + aKOff);
                uint32_t s = swz(off);
                ldmx4(ah[mt], ahB + s);
                ldmx4(al[mt], alB + s);
            }
            uint32_t bh[2][4], bl[2][4];
#pragma unroll
            for (int p = 0; p < 2; p++) {
                uint32_t off = (uint32_t)((warpN * 32 + p * 16 + bRowOff) * 128
                                          + kByte + bKOff);
                uint32_t s = swz(off);
                ldmx4(bh[p], bhB + s);
                ldmx4(bl[p], blB + s);
            }
#pragma unroll
            for (int mt = 0; mt < 4; mt++)
#pragma unroll
                for (int nt = 0; nt < 4; nt++) {
                    const uint32_t* bhf = &bh[nt >> 1][(nt & 1) * 2];
                    const uint32_t* blf = &bl[nt >> 1][(nt & 1) * 2];
                    mma16816(acc[mt][nt], ah[mt], bhf);
                    mma16816(acc[mt][nt], ah[mt], blf);
                    mma16816(acc[mt][nt], al[mt], bhf);
                }
        }
        __syncthreads();
        if (ci + 3 < nCh) load_chunk(ci + 3, buf);
    }

    const int mW = mBase + warpM * 64;
    const int nW = nBase + warpN * 32;
#pragma unroll
    for (int mt = 0; mt < 4; mt++) {
#pragma unroll
        for (int nt = 0; nt < 4; nt++) {
            int r0 = mW + mt * 16 + (lane >> 2);
            int c  = nW + nt * 8 + (lane & 3) * 2;
            *(float2*)(Cf + (size_t)r0 * N + c) =
                make_float2(acc[mt][nt][0], acc[mt][nt][1]);
            *(float2*)(Cf + (size_t)(r0 + 8) * N + c) =
                make_float2(acc[mt][nt][2], acc[mt][nt][3]);
        }
    }
}

// ---------------------------------------------------------------------------
// Flash attention, fp16 single-product mma.
// Q fragments hoisted to registers; 3-stage K/V pipeline aliasing Q smem.
// Stage s lives at sb + ((s+1)%3)*32KB. q pre-scaled by log2e/sqrt(HD),
// softmax uses ex2.approx.
// ---------------------------------------------------------------------------
#define FA_SMEM_BYTES (3 * 32768)   // 98304

__global__ __launch_bounds__(256, 1) void flash_mma_kernel(
    const __half* __restrict__ qkv,
    __nv_bfloat16* __restrict__ oh, __nv_bfloat16* __restrict__ ol)
{
    extern __shared__ char fsm[];
    const uint32_t sb  = smem_u32(fsm);
    const int tid  = threadIdx.x;
    const int wid  = tid >> 5;
    const int lane = tid & 31;
    const int q0 = blockIdx.x * 128;
    const int h  = blockIdx.y;
    const int b  = blockIdx.z;
    const int g  = h >> 2;

    const size_t qrow0 = (size_t)b * SEQ + q0;
    const int qcol = h * HD;
    const int kcol = EMB + g * HD;
    const int vcol = EMB + KVW + g * HD;

    // --- Q into smem region [sb, sb+32KB) (group 0) ---
#pragma unroll
    for (int t = 0; t < 8; t++) {
        int idx = tid + t * 256;
        int row = idx >> 4;
        int gr  = idx & 15;
        int blk = gr >> 3;
        uint32_t off = (uint32_t)(row * 128 + (gr & 7) * 16);
        uint32_t sw  = off ^ ((off >> 3) & 0x70);
        size_t go = (qrow0 + row) * QKVW + qcol + gr * 8;
        cp16(sb + blk * 16384 + sw, qkv + go);
    }
    asm volatile("cp.async.commit_group;" ::: "memory");

    auto stage_base = [&](int s) -> uint32_t {
        return sb + (uint32_t)(((s + 1) % 3) * 32768);
    };

    auto load_stage = [&](int ci) {
        const uint32_t s0 = stage_base(ci);
        const int kr0 = ci * 64;
#pragma unroll
        for (int t = 0; t < 8; t++) {
            int arr = t >> 2;                   // 0=K, 1=V
            int idx = tid + (t & 3) * 256;
            int row = idx >> 4;
            int gr  = idx & 15;
            int blk = gr >> 3;
            uint32_t off = (uint32_t)(row * 128 + (gr & 7) * 16);
            uint32_t sw  = off ^ ((off >> 3) & 0x70);
            uint32_t dst = s0 + (uint32_t)arr * 16384u + (uint32_t)blk * 8192u + sw;
            int col = (arr == 0) ? kcol : vcol;
            size_t go = (size_t)(b * SEQ + kr0 + row) * QKVW + col + gr * 8;
            cp16(dst, qkv + go);
        }
        asm volatile("cp.async.commit_group;" ::: "memory");
    };

    load_stage(0);      // -> sb+32KB
    load_stage(1);      // -> sb+64KB

    const int gid = lane >> 2, tig = lane & 3;
    const int qrw = wid * 16;

    const int aRow = lane & 15;
    const int aCol = (lane >> 4) << 4;
    const int bRow = (lane & 7) + ((lane >> 4) << 3);
    const int bCol = ((lane >> 3) & 1) << 4;
    const int vRow = (lane & 7) + (((lane >> 3) & 1) << 3);
    const int vCol = (lane >> 4) << 4;

    // --- hoist Q fragments to registers (wait Q; S0/S1 may stay pending) ---
    asm volatile("cp.async.wait_group 2;" ::: "memory");
    __syncthreads();
    uint32_t qreg[8][4];
#pragma unroll
    for (int ks = 0; ks < 8; ks++) {
        const int blk = ks >> 2;
        const int kb  = (ks & 3) * 32;
        uint32_t offq = (uint32_t)((qrw + aRow) * 128 + kb + aCol);
        uint32_t swq  = offq ^ ((offq >> 3) & 0x70);
        ldmx4(qreg[ks], sb + blk * 16384 + swq);
    }
    __syncthreads();    // all warps done reading Q smem
    load_stage(2);      // -> sb (aliases freed Q region)

    float m0 = -1e30f, m1 = -1e30f, l0 = 0.f, l1 = 0.f;
    float o[16][4];
#pragma unroll
    for (int t = 0; t < 16; t++)
#pragma unroll
        for (int i = 0; i < 4; i++) o[t][i] = 0.f;

    for (int ci = 0; ci < SEQ / 64; ci++) {
        if (ci < SEQ / 64 - 2)
            asm volatile("cp.async.wait_group 2;" ::: "memory");
        else if (ci == SEQ / 64 - 2)
            asm volatile("cp.async.wait_group 1;" ::: "memory");
        else
            asm volatile("cp.async.wait_group 0;" ::: "memory");
        __syncthreads();

        const uint32_t s0 = stage_base(ci);
        const uint32_t KB = s0, VB = s0 + 16384;

        // ---- S = Q @ K^T (Q from registers) ----
        float s[8][4];
#pragma unroll
        for (int t = 0; t < 8; t++)
#pragma unroll
            for (int i = 0; i < 4; i++) s[t][i] = 0.f;

#pragma unroll
        for (int ks = 0; ks < 8; ks++) {
            const int blk = ks >> 2;
            const int kb  = (ks & 3) * 32;
#pragma unroll
            for (int nb = 0; nb < 4; nb++) {
                uint32_t kf[4];
                uint32_t offk = (uint32_t)((nb * 16 + bRow) * 128 + kb + bCol);
                uint32_t swk  = offk ^ ((offk >> 3) & 0x70);
                ldmx4(kf, KB + blk * 8192 + swk);
                mma16816h(s[2 * nb],     qreg[ks], &kf[0]);
                mma16816h(s[2 * nb + 1], qreg[ks], &kf[2]);
            }
        }

        // ---- online softmax (log2 domain; q pre-scaled by log2e/sqrt(d)) ----
        float mx0 = -1e30f, mx1 = -1e30f;
#pragma unroll
        for (int t = 0; t < 8; t++) {
            mx0 = fmaxf(mx0, fmaxf(s[t][0], s[t][1]));
            mx1 = fmaxf(mx1, fmaxf(s[t][2], s[t][3]));
        }
        mx0 = fmaxf(mx0, __shfl_xor_sync(0xffffffffu, mx0, 1));
        mx0 = fmaxf(mx0, __shfl_xor_sync(0xffffffffu, mx0, 2));
        mx1 = fmaxf(mx1, __shfl_xor_sync(0xffffffffu, mx1, 1));
        mx1 = fmaxf(mx1, __shfl_xor_sync(0xffffffffu, mx1, 2));

        float mn0 = fmaxf(m0, mx0), mn1 = fmaxf(m1, mx1);
        float a0 = ex2(m0 - mn0), a1 = ex2(m1 - mn1);
        m0 = mn0; m1 = mn1;

        float rs0 = 0.f, rs1 = 0.f;
        uint32_t pa[4][4];
#pragma unroll
        for (int t = 0; t < 8; t++) {
            float p0 = ex2(s[t][0] - mn0);
            float p1 = ex2(s[t][1] - mn0);
            float p2 = ex2(s[t][2] - mn1);
            float p3 = ex2(s[t][3] - mn1);
            __half2 h01 = __floats2half2_rn(p0, p1);
            __half2 h23 = __floats2half2_rn(p2, p3);
            float2 f01 = __half22float2(h01);
            float2 f23 = __half22float2(h23);
            rs0 += f01.x + f01.y;
            rs1 += f23.x + f23.y;
            int j = t >> 1, sl = (t & 1) * 2;
            pa[j][sl]     = *(uint32_t*)&h01;
            pa[j][sl + 1] = *(uint32_t*)&h23;
        }
        rs0 += __shfl_xor_sync(0xffffffffu, rs0, 1);
        rs0 += __shfl_xor_sync(0xffffffffu, rs0, 2);
        rs1 += __shfl_xor_sync(0xffffffffu, rs1, 1);
        rs1 += __shfl_xor_sync(0xffffffffu, rs1, 2);
        l0 = l0 * a0 + rs0;
        l1 = l1 * a1 + rs1;

#pragma unroll
        for (int t = 0; t < 16; t++) {
            o[t][0] *= a0; o[t][1] *= a0;
            o[t][2] *= a1; o[t][3] *= a1;
        }

        // ---- O += P @ V ----
#pragma unroll
        for (int j = 0; j < 4; j++) {
#pragma unroll
            for (int tp = 0; tp < 8; tp++) {
                const int blk = tp >> 2;
                const int cb  = (tp & 3) * 32 + vCol;
                uint32_t offv = (uint32_t)((j * 16 + vRow) * 128 + cb);
                uint32_t swv  = offv ^ ((offv >> 3) & 0x70);
                uint32_t vf[4];
                ldmx4t(vf, VB + blk * 8192 + swv);
                mma16816h(o[2 * tp],     pa[j], &vf[0]);
                mma16816h(o[2 * tp + 1], pa[j], &vf[2]);
            }
        }

        __syncthreads();
        if (ci + 3 < SEQ / 64) load_stage(ci + 3);
    }

    // ---- epilogue: normalize, split hi/lo, store bf16 ----
    float i0 = 1.0f / l0, i1 = 1.0f / l1;
    size_t r0 = (qrow0 + qrw + gid) * EMB + (size_t)h * HD;
    size_t r1 = (qrow0 + qrw + gid + 8) * EMB + (size_t)h * HD;
#pragma unroll
    for (int t = 0; t < 16; t++) {
        int c = t * 8 + tig * 2;
        float v0 = o[t][0] * i0, v1 = o[t][1] * i0;
        float v2 = o[t][2] * i1, v3 = o[t][3] * i1;
        float h0 = __bfloat162float(__float2bfloat16(v0));
        float h1 = __bfloat162float(__float2bfloat16(v1));
        float h2 = __bfloat162float(__float2bfloat16(v2));
        float h3 = __bfloat162float(__float2bfloat16(v3));
        *(uint32_t*)(oh + r0 + c) = pack_bf16(h0, h1);
        *(uint32_t*)(oh + r1 + c) = pack_bf16(h2, h3);
        *(uint32_t*)(ol + r0 + c) = pack_bf16(v0 - h0, v1 - h1);
        *(uint32_t*)(ol + r1 + c) = pack_bf16(v2 - h2, v3 - h3);
    }
}

// ---------------------------------------------------------------------------
// kernel_launch
// ---------------------------------------------------------------------------
extern "C" void kernel_launch(void* const* d_in, const int* in_sizes, int n_in,
                              void* d_out, int out_size)
{
    const float* x  = (const float*)d_in[0];
    const float* Wq = (const float*)d_in[1];
    const float* bq = (const float*)d_in[2];
    const float* Wk = (const float*)d_in[3];
    const float* bk = (const float*)d_in[4];
    const float* Wv = (const float*)d_in[5];
    const float* bv = (const float*)d_in[6];
    const float* Wo = (const float*)d_in[7];
    float* out = (float*)d_out;

    __half *pxh, *pqkv, *pwc;
    __nv_bfloat16 *poh, *pol, *pwoh, *pwol;
    float* pbias;
    cudaGetSymbolAddress((void**)&pxh,  g_xh);
    cudaGetSymbolAddress((void**)&pqkv, g_qkv);
    cudaGetSymbolAddress((void**)&pwc,  g_wc);
    cudaGetSymbolAddress((void**)&poh,  g_ohi);
    cudaGetSymbolAddress((void**)&pol,  g_olo);
    cudaGetSymbolAddress((void**)&pwoh, g_woh);
    cudaGetSymbolAddress((void**)&pwol, g_wol);
    cudaGetSymbolAddress((void**)&pbias, g_bias);

    cudaFuncSetAttribute(gemm_f16_kernel,
                         cudaFuncAttributeMaxDynamicSharedMemorySize, GH_SMEM_BYTES);
    cudaFuncSetAttribute(gemm_mma_kernel,
                         cudaFuncAttributeMaxDynamicSharedMemorySize, GT_SMEM_BYTES);
    cudaFuncSetAttribute(flash_mma_kernel,
                         cudaFuncAttributeMaxDynamicSharedMemorySize, FA_SMEM_BYTES);

    const int nx = MROWS * EMB;
    // q pre-scale: log2(e) / sqrt(HD)  (softmax runs in log2 domain)
    const float qscale = 0.088388347648318447f * 1.4426950408889634f;

    // 1) x -> fp16
    to_half_kernel<<<nx / (4 * 256), 256>>>(x, pxh, nx);

    // 2) transpose weights: QKV -> concat fp16 [3072,2048]; Wo -> bf16 hi/lo
    dim3 tb(32, 8);
    transpose_half_kernel<<<dim3(EMB / 32, EMB / 32), tb>>>(Wq, pwc, EMB, EMB);
    transpose_half_kernel<<<dim3(KVW / 32, EMB / 32), tb>>>(
        Wk, pwc + (size_t)EMB * EMB, EMB, KVW);
    transpose_half_kernel<<<dim3(KVW / 32, EMB / 32), tb>>>(
        Wv, pwc + (size_t)(EMB + KVW) * EMB, EMB, KVW);
    transpose_split_kernel<<<dim3(EMB / 32, EMB / 32), tb>>>(
        Wo, pwoh, pwol, EMB, EMB);
    cudaMemcpyAsync(pbias,             bq, EMB * sizeof(float), cudaMemcpyDeviceToDevice);
    cudaMemcpyAsync(pbias + EMB,       bk, KVW * sizeof(float), cudaMemcpyDeviceToDevice);
    cudaMemcpyAsync(pbias + EMB + KVW, bv, KVW * sizeof(float), cudaMemcpyDeviceToDevice);

    // 3) fused QKV projection, single-product fp16 (Q cols pre-scaled)
    gemm_f16_kernel<<<dim3(QKVW / 128, MROWS / 128), 256, GH_SMEM_BYTES>>>(
        pxh, pwc, pbias, pqkv, qscale, EMB, MROWS, QKVW, EMB);

    // 4) flash attention (fp16 single-product, log2-domain softmax)
    flash_mma_kernel<<<dim3(SEQ / 128, HQ, BATCH), 256, FA_SMEM_BYTES>>>(
        pqkv, poh, pol);

    // 5) output projection (bf16 hi/lo, 3 products) -> fp32
    gemm_mma_kernel<<<dim3(EMB / 128, MROWS / 128), 256, GT_SMEM_BYTES>>>(
        poh, pol, pwoh, pwol, out, MROWS, EMB, EMB);
}

// round 10
// speedup vs baseline: 7.6141x; 1.0093x over previous
#include <cuda_runtime.h>
#include <cuda_bf16.h>
#include <cuda_fp16.h>
#include <cstdint>

#define BATCH 2
#define SEQ   2048
#define EMB   2048
#define HQ    16
#define HKV   4
#define HD    128
#define KVW   (HKV * HD)        // 512
#define MROWS (BATCH * SEQ)     // 4096
#define QKVW  (EMB + 2 * KVW)   // 3072

// ---------------------------------------------------------------------------
// PTX helpers — ONLY non-arch-suffixed instructions (compute_103-safe)
// ---------------------------------------------------------------------------
__device__ __forceinline__ uint32_t smem_u32(const void* p) {
    uint32_t a;
    asm("{ .reg .u64 t; cvta.to.shared.u64 t, %1; cvt.u32.u64 %0, t; }"
        : "=r"(a) : "l"(p));
    return a;
}

__device__ __forceinline__ void cp16(uint32_t saddr, const void* gaddr) {
    asm volatile("cp.async.cg.shared.global [%0], [%1], 16;"
                 :: "r"(saddr), "l"(gaddr));
}

__device__ __forceinline__ void ldmx4(uint32_t* r, uint32_t addr) {
    asm volatile("ldmatrix.sync.aligned.m8n8.x4.shared.b16 {%0,%1,%2,%3}, [%4];"
                 : "=r"(r[0]), "=r"(r[1]), "=r"(r[2]), "=r"(r[3]) : "r"(addr));
}

__device__ __forceinline__ void ldmx4t(uint32_t* r, uint32_t addr) {
    asm volatile("ldmatrix.sync.aligned.m8n8.x4.trans.shared.b16 {%0,%1,%2,%3}, [%4];"
                 : "=r"(r[0]), "=r"(r[1]), "=r"(r[2]), "=r"(r[3]) : "r"(addr));
}

// bf16 mma
__device__ __forceinline__ void mma16816(float* c, const uint32_t* a,
                                         const uint32_t* b) {
    asm volatile(
        "mma.sync.aligned.m16n8k16.row.col.f32.bf16.bf16.f32 "
        "{%0,%1,%2,%3}, {%4,%5,%6,%7}, {%8,%9}, {%0,%1,%2,%3};"
        : "+f"(c[0]), "+f"(c[1]), "+f"(c[2]), "+f"(c[3])
        : "r"(a[0]), "r"(a[1]), "r"(a[2]), "r"(a[3]), "r"(b[0]), "r"(b[1]));
}

// fp16 mma
__device__ __forceinline__ void mma16816h(float* c, const uint32_t* a,
                                          const uint32_t* b) {
    asm volatile(
        "mma.sync.aligned.m16n8k16.row.col.f32.f16.f16.f32 "
        "{%0,%1,%2,%3}, {%4,%5,%6,%7}, {%8,%9}, {%0,%1,%2,%3};"
        : "+f"(c[0]), "+f"(c[1]), "+f"(c[2]), "+f"(c[3])
        : "r"(a[0]), "r"(a[1]), "r"(a[2]), "r"(a[3]), "r"(b[0]), "r"(b[1]));
}

__device__ __forceinline__ float ex2(float x) {
    float y;
    asm("ex2.approx.f32 %0, %1;" : "=f"(y) : "f"(x));
    return y;
}

__device__ __forceinline__ uint32_t pack_bf16(float a, float b) {
    __nv_bfloat162 t = __floats2bfloat162_rn(a, b);
    return *(uint32_t*)&t;
}

// ---------------------------------------------------------------------------
// Device scratch (no cudaMalloc allowed)
// ---------------------------------------------------------------------------
__device__ __half        g_xh[(size_t)MROWS * EMB];       // x fp16
__device__ __half        g_qkv[(size_t)MROWS * QKVW];     // fused q|k|v fp16
__device__ __nv_bfloat16 g_ohi[(size_t)MROWS * EMB];
__device__ __nv_bfloat16 g_olo[(size_t)MROWS * EMB];
__device__ __half        g_wc[(size_t)QKVW * EMB];        // concat Wq|Wk|Wv ^T fp16
__device__ __nv_bfloat16 g_woh[(size_t)EMB * EMB];
__device__ __nv_bfloat16 g_wol[(size_t)EMB * EMB];
__device__ float         g_bias[QKVW];                     // concat bq|bk|bv

// ---------------------------------------------------------------------------
// fp32 -> fp16 convert (elementwise)
// ---------------------------------------------------------------------------
__global__ __launch_bounds__(256) void to_half_kernel(
    const float* __restrict__ x, __half* __restrict__ y, int n)
{
    int i = (blockIdx.x * 256 + threadIdx.x) * 4;
    if (i >= n) return;
    float4 v = *(const float4*)(x + i);
    __half2 h0 = __floats2half2_rn(v.x, v.y);
    __half2 h1 = __floats2half2_rn(v.z, v.w);
    uint2 o = make_uint2(*(uint32_t*)&h0, *(uint32_t*)&h1);
    *(uint2*)(y + i) = o;
}

// ---------------------------------------------------------------------------
// Transpose: W [K,N] fp32 -> T [N,K] fp16
// ---------------------------------------------------------------------------
__global__ __launch_bounds__(256) void transpose_half_kernel(
    const float* __restrict__ W, __half* __restrict__ T, int K, int N)
{
    __shared__ float tile[32][33];
    const int tx = threadIdx.x, ty = threadIdx.y;
    const int nBase = blockIdx.x * 32, kBase = blockIdx.y * 32;
#pragma unroll
    for (int i = 0; i < 4; i++)
        tile[ty + 8 * i][tx] = W[(size_t)(kBase + ty + 8 * i) * N + nBase + tx];
    __syncthreads();
#pragma unroll
    for (int i = 0; i < 4; i++) {
        float v = tile[tx][ty + 8 * i];
        T[(size_t)(nBase + ty + 8 * i) * K + kBase + tx] = __float2half(v);
    }
}

// ---------------------------------------------------------------------------
// Transpose + split: W [K,N] fp32 -> Thi/Tlo [N,K] bf16
// ---------------------------------------------------------------------------
__global__ __launch_bounds__(256) void transpose_split_kernel(
    const float* __restrict__ W, __nv_bfloat16* __restrict__ Thi,
    __nv_bfloat16* __restrict__ Tlo, int K, int N)
{
    __shared__ float tile[32][33];
    const int tx = threadIdx.x, ty = threadIdx.y;
    const int nBase = blockIdx.x * 32, kBase = blockIdx.y * 32;
#pragma unroll
    for (int i = 0; i < 4; i++)
        tile[ty + 8 * i][tx] = W[(size_t)(kBase + ty + 8 * i) * N + nBase + tx];
    __syncthreads();
#pragma unroll
    for (int i = 0; i < 4; i++) {
        float v = tile[tx][ty + 8 * i];
        __nv_bfloat16 h = __float2bfloat16(v);
        __nv_bfloat16 l = __float2bfloat16(v - __bfloat162float(h));
        size_t idx = (size_t)(nBase + ty + 8 * i) * K + kBase + tx;
        Thi[idx] = h;
        Tlo[idx] = l;
    }
}

// ---------------------------------------------------------------------------
// Single-product fp16 GEMM (QKV projection), 3-stage cp.async pipeline.
// ---------------------------------------------------------------------------
#define GH_STAGE_BYTES 32768                 // A 16KB + B 16KB
#define GH_SMEM_BYTES  (3 * GH_STAGE_BYTES)  // 98304

__global__ __launch_bounds__(256) void gemm_f16_kernel(
    const __half* __restrict__ A, const __half* __restrict__ B,
    const float* __restrict__ bias, __half* __restrict__ C,
    float qsc, int qcols, int M, int N, int K)
{
    extern __shared__ char gsm[];
    const uint32_t sb = smem_u32(gsm);

    const int tid   = threadIdx.x;
    const int wid   = tid >> 5;
    const int lane  = tid & 31;
    const int warpM = wid & 1;
    const int warpN = wid >> 1;
    const int mBase = blockIdx.y * 128;
    const int nBase = blockIdx.x * 128;
    const int nCh   = K >> 6;

    const int aRowOff = lane & 15;
    const int aKOff   = (lane >> 4) << 4;
    const int bRowOff = (lane & 7) + ((lane >> 4) << 3);
    const int bKOff   = ((lane >> 3) & 1) << 4;

    auto swz = [](uint32_t off) { return off ^ ((off >> 3) & 0x70); };

    auto load_chunk = [&](int ci, int buf) {
        const int k0 = ci << 6;
        const uint32_t sbase = sb + (uint32_t)buf * GH_STAGE_BYTES;
#pragma unroll
        for (int t = 0; t < 8; t++) {
            int idx = tid + t * 256;
            int ab  = idx >> 10;
            int row = (idx >> 3) & 127;
            int gr  = idx & 7;
            uint32_t off = (uint32_t)(row * 128 + gr * 16);
            uint32_t sw  = off ^ ((off >> 3) & 0x70);
            if (ab == 0)
                cp16(sbase + sw, A + (size_t)(mBase + row) * K + k0 + gr * 8);
            else
                cp16(sbase + 16384 + sw,
                     B + (size_t)(nBase + row) * K + k0 + gr * 8);
        }
        asm volatile("cp.async.commit_group;" ::: "memory");
    };

    float acc[4][4][4];
#pragma unroll
    for (int mt = 0; mt < 4; mt++)
#pragma unroll
        for (int nt = 0; nt < 4; nt++)
#pragma unroll
            for (int i = 0; i < 4; i++) acc[mt][nt][i] = 0.f;

    load_chunk(0, 0);
    load_chunk(1, 1);
    load_chunk(2, 2);

    for (int ci = 0; ci < nCh; ci++) {
        const int buf = ci % 3;
        const int rem = nCh - 1 - ci;
        if (rem >= 2)
            asm volatile("cp.async.wait_group 2;" ::: "memory");
        else if (rem == 1)
            asm volatile("cp.async.wait_group 1;" ::: "memory");
        else
            asm volatile("cp.async.wait_group 0;" ::: "memory");
        __syncthreads();

        const uint32_t sbase = sb + (uint32_t)buf * GH_STAGE_BYTES;
        const uint32_t aB = sbase;
        const uint32_t bB = sbase + 16384;

#pragma unroll
        for (int ks = 0; ks < 4; ks++) {
            const int kByte = ks * 32;
            uint32_t af[4][4];
#pragma unroll
            for (int mt = 0; mt < 4; mt++) {
                uint32_t off = (uint32_t)((warpM * 64 + mt * 16 + aRowOff) * 128
                                          + kByte + aKOff);
                ldmx4(af[mt], aB + swz(off));
            }
            uint32_t bf[2][4];
#pragma unroll
            for (int p = 0; p < 2; p++) {
                uint32_t off = (uint32_t)((warpN * 32 + p * 16 + bRowOff) * 128
                                          + kByte + bKOff);
                ldmx4(bf[p], bB + swz(off));
            }
#pragma unroll
            for (int mt = 0; mt < 4; mt++)
#pragma unroll
                for (int nt = 0; nt < 4; nt++)
                    mma16816h(acc[mt][nt], af[mt], &bf[nt >> 1][(nt & 1) * 2]);
        }
        __syncthreads();
        if (ci + 3 < nCh) load_chunk(ci + 3, buf);
    }

    const int mW = mBase + warpM * 64;
    const int nW = nBase + warpN * 32;
#pragma unroll
    for (int mt = 0; mt < 4; mt++) {
#pragma unroll
        for (int nt = 0; nt < 4; nt++) {
            int r0 = mW + mt * 16 + (lane >> 2);
            int c  = nW + nt * 8 + (lane & 3) * 2;
            float2 bv = *(const float2*)(bias + c);
            float sc = (c < qcols) ? qsc : 1.f;
            float v0 = (acc[mt][nt][0] + bv.x) * sc;
            float v1 = (acc[mt][nt][1] + bv.y) * sc;
            float v2 = (acc[mt][nt][2] + bv.x) * sc;
            float v3 = (acc[mt][nt][3] + bv.y) * sc;
            __half2 h01 = __floats2half2_rn(v0, v1);
            __half2 h23 = __floats2half2_rn(v2, v3);
            *(uint32_t*)(C + (size_t)r0 * N + c)       = *(uint32_t*)&h01;
            *(uint32_t*)(C + (size_t)(r0 + 8) * N + c) = *(uint32_t*)&h23;
        }
    }
}

// ---------------------------------------------------------------------------
// Out projection: HMMA bf16 hi/lo (3 products), fp32 out, 3-stage pipeline.
// ---------------------------------------------------------------------------
#define GT_STAGE_BYTES 65536
#define GT_SMEM_BYTES  (3 * GT_STAGE_BYTES)   // 196608

__global__ __launch_bounds__(256) void gemm_mma_kernel(
    const __nv_bfloat16* __restrict__ Ahi, const __nv_bfloat16* __restrict__ Alo,
    const __nv_bfloat16* __restrict__ Bhi, const __nv_bfloat16* __restrict__ Blo,
    float* __restrict__ Cf, int M, int N, int K)
{
    extern __shared__ char gsm[];
    const uint32_t sb = smem_u32(gsm);

    const int tid   = threadIdx.x;
    const int wid   = tid >> 5;
    const int lane  = tid & 31;
    const int warpM = wid & 1;
    const int warpN = wid >> 1;
    const int mBase = blockIdx.y * 128;
    const int nBase = blockIdx.x * 128;
    const int nCh   = K >> 6;

    const int aRowOff = lane & 15;
    const int aKOff   = (lane >> 4) << 4;
    const int bRowOff = (lane & 7) + ((lane >> 4) << 3);
    const int bKOff   = ((lane >> 3) & 1) << 4;

    auto swz = [](uint32_t off) { return off ^ ((off >> 3) & 0x70); };

    auto load_chunk = [&](int ci, int buf) {
        const int k0 = ci << 6;
        const uint32_t sbase = sb + (uint32_t)buf * GT_STAGE_BYTES;
#pragma unroll
        for (int t = 0; t < 4; t++) {
            int idx = tid + t * 256;
            int row = idx >> 3;
            int gr  = idx & 7;
            uint32_t off = (uint32_t)(row * 128 + gr * 16);
            uint32_t sw  = off ^ ((off >> 3) & 0x70);
            size_t aoff = (size_t)(mBase + row) * K + k0 + gr * 8;
            size_t boff = (size_t)(nBase + row) * K + k0 + gr * 8;
            cp16(sbase +         sw, Ahi + aoff);
            cp16(sbase + 16384 + sw, Alo + aoff);
            cp16(sbase + 32768 + sw, Bhi + boff);
            cp16(sbase + 49152 + sw, Blo + boff);
        }
        asm volatile("cp.async.commit_group;" ::: "memory");
    };

    float acc[4][4][4];
#pragma unroll
    for (int mt = 0; mt < 4; mt++)
#pragma unroll
        for (int nt = 0; nt < 4; nt++)
#pragma unroll
            for (int i = 0; i < 4; i++) acc[mt][nt][i] = 0.f;

    load_chunk(0, 0);
    load_chunk(1, 1);
    load_chunk(2, 2);

    for (int ci = 0; ci < nCh; ci++) {
        const int buf = ci % 3;
        const int rem = nCh - 1 - ci;
        if (rem >= 2)
            asm volatile("cp.async.wait_group 2;" ::: "memory");
        else if (rem == 1)
            asm volatile("cp.async.wait_group 1;" ::: "memory");
        else
            asm volatile("cp.async.wait_group 0;" ::: "memory");
        __syncthreads();

        const uint32_t sbase = sb + (uint32_t)buf * GT_STAGE_BYTES;
        const uint32_t ahB = sbase;
        const uint32_t alB = sbase + 16384;
        const uint32_t bhB = sbase + 32768;
        const uint32_t blB = sbase + 49152;

#pragma unroll
        for (int ks = 0; ks < 4; ks++) {
            const int kByte = ks * 32;
            uint32_t ah[4][4], al[4][4];
#pragma unroll
            for (int mt = 0; mt < 4; mt++) {
                uint32_t off = (uint32_t)((warpM * 64 + mt * 16 + aRowOff) * 128
                                          + kByte + aKOff);
                uint32_t s = swz(off);
                ldmx4(ah[mt], ahB + s);
                ldmx4(al[mt], alB + s);
            }
            uint32_t bh[2][4], bl[2][4];
#pragma unroll
            for (int p = 0; p < 2; p++) {
                uint32_t off = (uint32_t)((warpN * 32 + p * 16 + bRowOff) * 128
                                          + kByte + bKOff);
                uint32_t s = swz(off);
                ldmx4(bh[p], bhB + s);
                ldmx4(bl[p], blB + s);
            }
#pragma unroll
            for (int mt = 0; mt < 4; mt++)
#pragma unroll
                for (int nt = 0; nt < 4; nt++) {
                    const uint32_t* bhf = &bh[nt >> 1][(nt & 1) * 2];
                    const uint32_t* blf = &bl[nt >> 1][(nt & 1) * 2];
                    mma16816(acc[mt][nt], ah[mt], bhf);
                    mma16816(acc[mt][nt], ah[mt], blf);
                    mma16816(acc[mt][nt], al[mt], bhf);
                }
        }
        __syncthreads();
        if (ci + 3 < nCh) load_chunk(ci + 3, buf);
    }

    const int mW = mBase + warpM * 64;
    const int nW = nBase + warpN * 32;
#pragma unroll
    for (int mt = 0; mt < 4; mt++) {
#pragma unroll
        for (int nt = 0; nt < 4; nt++) {
            int r0 = mW + mt * 16 + (lane >> 2);
            int c  = nW + nt * 8 + (lane & 3) * 2;
            *(float2*)(Cf + (size_t)r0 * N + c) =
                make_float2(acc[mt][nt][0], acc[mt][nt][1]);
            *(float2*)(Cf + (size_t)(r0 + 8) * N + c) =
                make_float2(acc[mt][nt][2], acc[mt][nt][3]);
        }
    }
}

// ---------------------------------------------------------------------------
// Flash attention, fp16 single-product mma.
// BM=64, 128 threads (4 warps), 2 CTAs/SM — co-resident CTAs overlap
// softmax (ALU/MUFU) with mma (tensor). Q fragments hoisted to registers;
// 3-stage K/V pipeline (32KB/stage) aliasing the Q smem region.
// q pre-scaled by log2e/sqrt(HD); softmax in log2 domain (ex2).
// ---------------------------------------------------------------------------
#define FA_SMEM_BYTES (3 * 32768)   // 98304; 2 CTAs/SM -> 192KB

__global__ __launch_bounds__(128, 2) void flash_mma_kernel(
    const __half* __restrict__ qkv,
    __nv_bfloat16* __restrict__ oh, __nv_bfloat16* __restrict__ ol)
{
    extern __shared__ char fsm[];
    const uint32_t sb  = smem_u32(fsm);
    const int tid  = threadIdx.x;
    const int wid  = tid >> 5;        // 0..3
    const int lane = tid & 31;
    const int q0 = blockIdx.x * 64;
    const int h  = blockIdx.y;
    const int b  = blockIdx.z;
    const int g  = h >> 2;

    const size_t qrow0 = (size_t)b * SEQ + q0;
    const int qcol = h * HD;
    const int kcol = EMB + g * HD;
    const int vcol = EMB + KVW + g * HD;

    // --- Q (64 rows x 256B) into [sb, sb+16KB): 2 blocks of [64 x 128B] ---
#pragma unroll
    for (int t = 0; t < 8; t++) {
        int idx = tid + t * 128;        // 0..1023
        int row = idx >> 4;             // 0..63
        int gr  = idx & 15;
        int blk = gr >> 3;
        uint32_t off = (uint32_t)(row * 128 + (gr & 7) * 16);
        uint32_t sw  = off ^ ((off >> 3) & 0x70);
        size_t go = (qrow0 + row) * QKVW + qcol + gr * 8;
        cp16(sb + blk * 8192 + sw, qkv + go);
    }
    asm volatile("cp.async.commit_group;" ::: "memory");

    auto stage_base = [&](int s) -> uint32_t {
        return sb + (uint32_t)(((s + 1) % 3) * 32768);
    };

    auto load_stage = [&](int ci) {
        const uint32_t s0 = stage_base(ci);
        const int kr0 = ci * 64;
#pragma unroll
        for (int t = 0; t < 16; t++) {
            int arr = t >> 3;                   // 0=K, 1=V
            int idx = tid + (t & 7) * 128;      // 0..1023
            int row = idx >> 4;                 // 0..63
            int gr  = idx & 15;
            int blk = gr >> 3;
            uint32_t off = (uint32_t)(row * 128 + (gr & 7) * 16);
            uint32_t sw  = off ^ ((off >> 3) & 0x70);
            uint32_t dst = s0 + (uint32_t)arr * 16384u + (uint32_t)blk * 8192u + sw;
            int col = (arr == 0) ? kcol : vcol;
            size_t go = (size_t)(b * SEQ + kr0 + row) * QKVW + col + gr * 8;
            cp16(dst, qkv + go);
        }
        asm volatile("cp.async.commit_group;" ::: "memory");
    };

    load_stage(0);      // -> sb+32KB
    load_stage(1);      // -> sb+64KB

    const int gid = lane >> 2, tig = lane & 3;
    const int qrw = wid * 16;           // 0..48

    const int aRow = lane & 15;
    const int aCol = (lane >> 4) << 4;
    const int bRow = (lane & 7) + ((lane >> 4) << 3);
    const int bCol = ((lane >> 3) & 1) << 4;
    const int vRow = (lane & 7) + (((lane >> 3) & 1) << 3);
    const int vCol = (lane >> 4) << 4;

    // --- hoist Q fragments to registers (wait Q group only) ---
    asm volatile("cp.async.wait_group 2;" ::: "memory");
    __syncthreads();
    uint32_t qreg[8][4];
#pragma unroll
    for (int ks = 0; ks < 8; ks++) {
        const int blk = ks >> 2;
        const int kb  = (ks & 3) * 32;
        uint32_t offq = (uint32_t)((qrw + aRow) * 128 + kb + aCol);
        uint32_t swq  = offq ^ ((offq >> 3) & 0x70);
        ldmx4(qreg[ks], sb + blk * 8192 + swq);
    }
    __syncthreads();    // all warps done reading Q smem
    load_stage(2);      // -> sb (aliases freed Q region)

    float m0 = -1e30f, m1 = -1e30f, l0 = 0.f, l1 = 0.f;
    float o[16][4];
#pragma unroll
    for (int t = 0; t < 16; t++)
#pragma unroll
        for (int i = 0; i < 4; i++) o[t][i] = 0.f;

    for (int ci = 0; ci < SEQ / 64; ci++) {
        if (ci < SEQ / 64 - 2)
            asm volatile("cp.async.wait_group 2;" ::: "memory");
        else if (ci == SEQ / 64 - 2)
            asm volatile("cp.async.wait_group 1;" ::: "memory");
        else
            asm volatile("cp.async.wait_group 0;" ::: "memory");
        __syncthreads();

        const uint32_t s0 = stage_base(ci);
        const uint32_t KB = s0, VB = s0 + 16384;

        // ---- S = Q @ K^T (Q from registers) ----
        float s[8][4];
#pragma unroll
        for (int t = 0; t < 8; t++)
#pragma unroll
            for (int i = 0; i < 4; i++) s[t][i] = 0.f;

#pragma unroll
        for (int ks = 0; ks < 8; ks++) {
            const int blk = ks >> 2;
            const int kb  = (ks & 3) * 32;
#pragma unroll
            for (int nb = 0; nb < 4; nb++) {
                uint32_t kf[4];
                uint32_t offk = (uint32_t)((nb * 16 + bRow) * 128 + kb + bCol);
                uint32_t swk  = offk ^ ((offk >> 3) & 0x70);
                ldmx4(kf, KB + blk * 8192 + swk);
                mma16816h(s[2 * nb],     qreg[ks], &kf[0]);
                mma16816h(s[2 * nb + 1], qreg[ks], &kf[2]);
            }
        }

        // ---- online softmax (log2 domain) ----
        float mx0 = -1e30f, mx1 = -1e30f;
#pragma unroll
        for (int t = 0; t < 8; t++) {
            mx0 = fmaxf(mx0, fmaxf(s[t][0], s[t][1]));
            mx1 = fmaxf(mx1, fmaxf(s[t][2], s[t][3]));
        }
        mx0 = fmaxf(mx0, __shfl_xor_sync(0xffffffffu, mx0, 1));
        mx0 = fmaxf(mx0, __shfl_xor_sync(0xffffffffu, mx0, 2));
        mx1 = fmaxf(mx1, __shfl_xor_sync(0xffffffffu, mx1, 1));
        mx1 = fmaxf(mx1, __shfl_xor_sync(0xffffffffu, mx1, 2));

        float mn0 = fmaxf(m0, mx0), mn1 = fmaxf(m1, mx1);
        float a0 = ex2(m0 - mn0), a1 = ex2(m1 - mn1);
        m0 = mn0; m1 = mn1;

        float rs0 = 0.f, rs1 = 0.f;
        uint32_t pa[4][4];
#pragma unroll
        for (int t = 0; t < 8; t++) {
            __half2 h01 = h2exp2(__floats2half2_rn(s[t][0] - mn0, s[t][1] - mn0));
            __half2 h23 = h2exp2(__floats2half2_rn(s[t][2] - mn1, s[t][3] - mn1));
            float2 f01 = __half22float2(h01);
            float2 f23 = __half22float2(h23);
            rs0 += f01.x + f01.y;
            rs1 += f23.x + f23.y;
            int j = t >> 1, sl = (t & 1) * 2;
            pa[j][sl]     = *(uint32_t*)&h01;
            pa[j][sl + 1] = *(uint32_t*)&h23;
        }
        rs0 += __shfl_xor_sync(0xffffffffu, rs0, 1);
        rs0 += __shfl_xor_sync(0xffffffffu, rs0, 2);
        rs1 += __shfl_xor_sync(0xffffffffu, rs1, 1);
        rs1 += __shfl_xor_sync(0xffffffffu, rs1, 2);
        l0 = l0 * a0 + rs0;
        l1 = l1 * a1 + rs1;

        // rescale O only when the running max actually moved
        if (a0 != 1.f || a1 != 1.f) {
#pragma unroll
            for (int t = 0; t < 16; t++) {
                o[t][0] *= a0; o[t][1] *= a0;
                o[t][2] *= a1; o[t][3] *= a1;
            }
        }

        // ---- O += P @ V ----
#pragma unroll
        for (int j = 0; j < 4; j++) {
#pragma unroll
            for (int tp = 0; tp < 8; tp++) {
                const int blk = tp >> 2;
                const int cb  = (tp & 3) * 32 + vCol;
                uint32_t offv = (uint32_t)((j * 16 + vRow) * 128 + cb);
                uint32_t swv  = offv ^ ((offv >> 3) & 0x70);
                uint32_t vf[4];
                ldmx4t(vf, VB + blk * 8192 + swv);
                mma16816h(o[2 * tp],     pa[j], &vf[0]);
                mma16816h(o[2 * tp + 1], pa[j], &vf[2]);
            }
        }

        __syncthreads();
        if (ci + 3 < SEQ / 64) load_stage(ci + 3);
    }

    // ---- epilogue: normalize, split hi/lo, store bf16 ----
    float i0 = 1.0f / l0, i1 = 1.0f / l1;
    size_t r0 = (qrow0 + qrw + gid) * EMB + (size_t)h * HD;
    size_t r1 = (qrow0 + qrw + gid + 8) * EMB + (size_t)h * HD;
#pragma unroll
    for (int t = 0; t < 16; t++) {
        int c = t * 8 + tig * 2;
        float v0 = o[t][0] * i0, v1 = o[t][1] * i0;
        float v2 = o[t][2] * i1, v3 = o[t][3] * i1;
        float h0 = __bfloat162float(__float2bfloat16(v0));
        float h1 = __bfloat162float(__float2bfloat16(v1));
        float h2 = __bfloat162float(__float2bfloat16(v2));
        float h3 = __bfloat162float(__float2bfloat16(v3));
        *(uint32_t*)(oh + r0 + c) = pack_bf16(h0, h1);
        *(uint32_t*)(oh + r1 + c) = pack_bf16(h2, h3);
        *(uint32_t*)(ol + r0 + c) = pack_bf16(v0 - h0, v1 - h1);
        *(uint32_t*)(ol + r1 + c) = pack_bf16(v2 - h2, v3 - h3);
    }
}

// ---------------------------------------------------------------------------
// kernel_launch
// ---------------------------------------------------------------------------
extern "C" void kernel_launch(void* const* d_in, const int* in_sizes, int n_in,
                              void* d_out, int out_size)
{
    const float* x  = (const float*)d_in[0];
    const float* Wq = (const float*)d_in[1];
    const float* bq = (const float*)d_in[2];
    const float* Wk = (const float*)d_in[3];
    const float* bk = (const float*)d_in[4];
    const float* Wv = (const float*)d_in[5];
    const float* bv = (const float*)d_in[6];
    const float* Wo = (const float*)d_in[7];
    float* out = (float*)d_out;

    __half *pxh, *pqkv, *pwc;
    __nv_bfloat16 *poh, *pol, *pwoh, *pwol;
    float* pbias;
    cudaGetSymbolAddress((void**)&pxh,  g_xh);
    cudaGetSymbolAddress((void**)&pqkv, g_qkv);
    cudaGetSymbolAddress((void**)&pwc,  g_wc);
    cudaGetSymbolAddress((void**)&poh,  g_ohi);
    cudaGetSymbolAddress((void**)&pol,  g_olo);
    cudaGetSymbolAddress((void**)&pwoh, g_woh);
    cudaGetSymbolAddress((void**)&pwol, g_wol);
    cudaGetSymbolAddress((void**)&pbias, g_bias);

    cudaFuncSetAttribute(gemm_f16_kernel,
                         cudaFuncAttributeMaxDynamicSharedMemorySize, GH_SMEM_BYTES);
    cudaFuncSetAttribute(gemm_mma_kernel,
                         cudaFuncAttributeMaxDynamicSharedMemorySize, GT_SMEM_BYTES);
    cudaFuncSetAttribute(flash_mma_kernel,
                         cudaFuncAttributeMaxDynamicSharedMemorySize, FA_SMEM_BYTES);

    const int nx = MROWS * EMB;
    // q pre-scale: log2(e) / sqrt(HD)  (softmax runs in log2 domain)
    const float qscale = 0.088388347648318447f * 1.4426950408889634f;

    // 1) x -> fp16
    to_half_kernel<<<nx / (4 * 256), 256>>>(x, pxh, nx);

    // 2) transpose weights: QKV -> concat fp16 [3072,2048]; Wo -> bf16 hi/lo
    dim3 tb(32, 8);
    transpose_half_kernel<<<dim3(EMB / 32, EMB / 32), tb>>>(Wq, pwc, EMB, EMB);
    transpose_half_kernel<<<dim3(KVW / 32, EMB / 32), tb>>>(
        Wk, pwc + (size_t)EMB * EMB, EMB, KVW);
    transpose_half_kernel<<<dim3(KVW / 32, EMB / 32), tb>>>(
        Wv, pwc + (size_t)(EMB + KVW) * EMB, EMB, KVW);
    transpose_split_kernel<<<dim3(EMB / 32, EMB / 32), tb>>>(
        Wo, pwoh, pwol, EMB, EMB);
    cudaMemcpyAsync(pbias,             bq, EMB * sizeof(float), cudaMemcpyDeviceToDevice);
    cudaMemcpyAsync(pbias + EMB,       bk, KVW * sizeof(float), cudaMemcpyDeviceToDevice);
    cudaMemcpyAsync(pbias + EMB + KVW, bv, KVW * sizeof(float), cudaMemcpyDeviceToDevice);

    // 3) fused QKV projection, single-product fp16 (Q cols pre-scaled)
    gemm_f16_kernel<<<dim3(QKVW / 128, MROWS / 128), 256, GH_SMEM_BYTES>>>(
        pxh, pwc, pbias, pqkv, qscale, EMB, MROWS, QKVW, EMB);

    // 4) flash attention (fp16, BM=64, 2 CTAs/SM) -> bf16 hi/lo output
    flash_mma_kernel<<<dim3(SEQ / 64, HQ, BATCH), 128, FA_SMEM_BYTES>>>(
        pqkv, poh, pol);

    // 5) output projection (bf16 hi/lo, 3 products) -> fp32
    gemm_mma_kernel<<<dim3(EMB / 128, MROWS / 128), 256, GT_SMEM_BYTES>>>(
        poh, pol, pwoh, pwol, out, MROWS, EMB, EMB);
}

// round 11
// speedup vs baseline: 8.7051x; 1.1433x over previous
#include <cuda_runtime.h>
#include <cuda_bf16.h>
#include <cuda_fp16.h>
#include <cstdint>

#define BATCH 2
#define SEQ   2048
#define EMB   2048
#define HQ    16
#define HKV   4
#define HD    128
#define KVW   (HKV * HD)        // 512
#define MROWS (BATCH * SEQ)     // 4096
#define QKVW  (EMB + 2 * KVW)   // 3072

// ---------------------------------------------------------------------------
// PTX helpers — ONLY non-arch-suffixed instructions (compute_103-safe)
// ---------------------------------------------------------------------------
__device__ __forceinline__ uint32_t smem_u32(const void* p) {
    uint32_t a;
    asm("{ .reg .u64 t; cvta.to.shared.u64 t, %1; cvt.u32.u64 %0, t; }"
        : "=r"(a) : "l"(p));
    return a;
}

__device__ __forceinline__ void cp16(uint32_t saddr, const void* gaddr) {
    asm volatile("cp.async.cg.shared.global [%0], [%1], 16;"
                 :: "r"(saddr), "l"(gaddr));
}

__device__ __forceinline__ void ldmx4(uint32_t* r, uint32_t addr) {
    asm volatile("ldmatrix.sync.aligned.m8n8.x4.shared.b16 {%0,%1,%2,%3}, [%4];"
                 : "=r"(r[0]), "=r"(r[1]), "=r"(r[2]), "=r"(r[3]) : "r"(addr));
}

__device__ __forceinline__ void ldmx4t(uint32_t* r, uint32_t addr) {
    asm volatile("ldmatrix.sync.aligned.m8n8.x4.trans.shared.b16 {%0,%1,%2,%3}, [%4];"
                 : "=r"(r[0]), "=r"(r[1]), "=r"(r[2]), "=r"(r[3]) : "r"(addr));
}

// fp16 mma
__device__ __forceinline__ void mma16816h(float* c, const uint32_t* a,
                                          const uint32_t* b) {
    asm volatile(
        "mma.sync.aligned.m16n8k16.row.col.f32.f16.f16.f32 "
        "{%0,%1,%2,%3}, {%4,%5,%6,%7}, {%8,%9}, {%0,%1,%2,%3};"
        : "+f"(c[0]), "+f"(c[1]), "+f"(c[2]), "+f"(c[3])
        : "r"(a[0]), "r"(a[1]), "r"(a[2]), "r"(a[3]), "r"(b[0]), "r"(b[1]));
}

__device__ __forceinline__ float ex2(float x) {
    float y;
    asm("ex2.approx.f32 %0, %1;" : "=f"(y) : "f"(x));
    return y;
}

// ---------------------------------------------------------------------------
// Device scratch (no cudaMalloc allowed)
// ---------------------------------------------------------------------------
__device__ __half g_xh[(size_t)MROWS * EMB];       // x fp16
__device__ __half g_qkv[(size_t)MROWS * QKVW];     // fused q|k|v fp16
__device__ __half g_oh[(size_t)MROWS * EMB];       // attn out fp16
__device__ __half g_wc[(size_t)QKVW * EMB];        // concat Wq|Wk|Wv ^T fp16
__device__ __half g_woh[(size_t)EMB * EMB];        // Wo^T fp16 hi
__device__ __half g_wol[(size_t)EMB * EMB];        // Wo^T fp16 lo (residual)
__device__ float  g_bias[QKVW];                    // concat bq|bk|bv

// ---------------------------------------------------------------------------
// fp32 -> fp16 convert (elementwise)
// ---------------------------------------------------------------------------
__global__ __launch_bounds__(256) void to_half_kernel(
    const float* __restrict__ x, __half* __restrict__ y, int n)
{
    int i = (blockIdx.x * 256 + threadIdx.x) * 4;
    if (i >= n) return;
    float4 v = *(const float4*)(x + i);
    __half2 h0 = __floats2half2_rn(v.x, v.y);
    __half2 h1 = __floats2half2_rn(v.z, v.w);
    uint2 o = make_uint2(*(uint32_t*)&h0, *(uint32_t*)&h1);
    *(uint2*)(y + i) = o;
}

// ---------------------------------------------------------------------------
// Merged transpose of Wq|Wk|Wv into the concat fp16 buffer [QKVW, EMB]
// ---------------------------------------------------------------------------
__global__ __launch_bounds__(256) void transpose_qkv_kernel(
    const float* __restrict__ Wq, const float* __restrict__ Wk,
    const float* __restrict__ Wv, __half* __restrict__ T)
{
    __shared__ float tile[32][33];
    const int tx = threadIdx.x, ty = threadIdx.y;
    const int nBase = blockIdx.x * 32;   // 0..QKVW-32
    const int kBase = blockIdx.y * 32;   // 0..EMB-32

    const float* W;
    int srcN, ln;
    if (nBase < EMB)            { W = Wq; srcN = EMB; ln = nBase; }
    else if (nBase < EMB + KVW) { W = Wk; srcN = KVW; ln = nBase - EMB; }
    else                        { W = Wv; srcN = KVW; ln = nBase - EMB - KVW; }

#pragma unroll
    for (int i = 0; i < 4; i++)
        tile[ty + 8 * i][tx] = W[(size_t)(kBase + ty + 8 * i) * srcN + ln + tx];
    __syncthreads();
#pragma unroll
    for (int i = 0; i < 4; i++) {
        float v = tile[tx][ty + 8 * i];
        T[(size_t)(nBase + ty + 8 * i) * EMB + kBase + tx] = __float2half(v);
    }
}

// ---------------------------------------------------------------------------
// Transpose + fp16 hi/lo split: W [K,N] fp32 -> Thi/Tlo [N,K] fp16
// ---------------------------------------------------------------------------
__global__ __launch_bounds__(256) void transpose_split_h_kernel(
    const float* __restrict__ W, __half* __restrict__ Thi,
    __half* __restrict__ Tlo, int K, int N)
{
    __shared__ float tile[32][33];
    const int tx = threadIdx.x, ty = threadIdx.y;
    const int nBase = blockIdx.x * 32, kBase = blockIdx.y * 32;
#pragma unroll
    for (int i = 0; i < 4; i++)
        tile[ty + 8 * i][tx] = W[(size_t)(kBase + ty + 8 * i) * N + nBase + tx];
    __syncthreads();
#pragma unroll
    for (int i = 0; i < 4; i++) {
        float v = tile[tx][ty + 8 * i];
        __half h = __float2half(v);
        __half l = __float2half(v - __half2float(h));
        size_t idx = (size_t)(nBase + ty + 8 * i) * K + kBase + tx;
        Thi[idx] = h;
        Tlo[idx] = l;
    }
}

// ---------------------------------------------------------------------------
// Single-product fp16 GEMM (QKV projection), 3-stage cp.async pipeline.
// ---------------------------------------------------------------------------
#define GH_STAGE_BYTES 32768                 // A 16KB + B 16KB
#define GH_SMEM_BYTES  (3 * GH_STAGE_BYTES)  // 98304

__global__ __launch_bounds__(256) void gemm_f16_kernel(
    const __half* __restrict__ A, const __half* __restrict__ B,
    const float* __restrict__ bias, __half* __restrict__ C,
    float qsc, int qcols, int M, int N, int K)
{
    extern __shared__ char gsm[];
    const uint32_t sb = smem_u32(gsm);

    const int tid   = threadIdx.x;
    const int wid   = tid >> 5;
    const int lane  = tid & 31;
    const int warpM = wid & 1;
    const int warpN = wid >> 1;
    const int mBase = blockIdx.y * 128;
    const int nBase = blockIdx.x * 128;
    const int nCh   = K >> 6;

    const int aRowOff = lane & 15;
    const int aKOff   = (lane >> 4) << 4;
    const int bRowOff = (lane & 7) + ((lane >> 4) << 3);
    const int bKOff   = ((lane >> 3) & 1) << 4;

    auto swz = [](uint32_t off) { return off ^ ((off >> 3) & 0x70); };

    auto load_chunk = [&](int ci, int buf) {
        const int k0 = ci << 6;
        const uint32_t sbase = sb + (uint32_t)buf * GH_STAGE_BYTES;
#pragma unroll
        for (int t = 0; t < 8; t++) {
            int idx = tid + t * 256;
            int ab  = idx >> 10;
            int row = (idx >> 3) & 127;
            int gr  = idx & 7;
            uint32_t off = (uint32_t)(row * 128 + gr * 16);
            uint32_t sw  = off ^ ((off >> 3) & 0x70);
            if (ab == 0)
                cp16(sbase + sw, A + (size_t)(mBase + row) * K + k0 + gr * 8);
            else
                cp16(sbase + 16384 + sw,
                     B + (size_t)(nBase + row) * K + k0 + gr * 8);
        }
        asm volatile("cp.async.commit_group;" ::: "memory");
    };

    float acc[4][4][4];
#pragma unroll
    for (int mt = 0; mt < 4; mt++)
#pragma unroll
        for (int nt = 0; nt < 4; nt++)
#pragma unroll
            for (int i = 0; i < 4; i++) acc[mt][nt][i] = 0.f;

    load_chunk(0, 0);
    load_chunk(1, 1);
    load_chunk(2, 2);

    for (int ci = 0; ci < nCh; ci++) {
        const int buf = ci % 3;
        const int rem = nCh - 1 - ci;
        if (rem >= 2)
            asm volatile("cp.async.wait_group 2;" ::: "memory");
        else if (rem == 1)
            asm volatile("cp.async.wait_group 1;" ::: "memory");
        else
            asm volatile("cp.async.wait_group 0;" ::: "memory");
        __syncthreads();

        const uint32_t sbase = sb + (uint32_t)buf * GH_STAGE_BYTES;
        const uint32_t aB = sbase;
        const uint32_t bB = sbase + 16384;

#pragma unroll
        for (int ks = 0; ks < 4; ks++) {
            const int kByte = ks * 32;
            uint32_t af[4][4];
#pragma unroll
            for (int mt = 0; mt < 4; mt++) {
                uint32_t off = (uint32_t)((warpM * 64 + mt * 16 + aRowOff) * 128
                                          + kByte + aKOff);
                ldmx4(af[mt], aB + swz(off));
            }
            uint32_t bf[2][4];
#pragma unroll
            for (int p = 0; p < 2; p++) {
                uint32_t off = (uint32_t)((warpN * 32 + p * 16 + bRowOff) * 128
                                          + kByte + bKOff);
                ldmx4(bf[p], bB + swz(off));
            }
#pragma unroll
            for (int mt = 0; mt < 4; mt++)
#pragma unroll
                for (int nt = 0; nt < 4; nt++)
                    mma16816h(acc[mt][nt], af[mt], &bf[nt >> 1][(nt & 1) * 2]);
        }
        __syncthreads();
        if (ci + 3 < nCh) load_chunk(ci + 3, buf);
    }

    const int mW = mBase + warpM * 64;
    const int nW = nBase + warpN * 32;
#pragma unroll
    for (int mt = 0; mt < 4; mt++) {
#pragma unroll
        for (int nt = 0; nt < 4; nt++) {
            int r0 = mW + mt * 16 + (lane >> 2);
            int c  = nW + nt * 8 + (lane & 3) * 2;
            float2 bv = *(const float2*)(bias + c);
            float sc = (c < qcols) ? qsc : 1.f;
            float v0 = (acc[mt][nt][0] + bv.x) * sc;
            float v1 = (acc[mt][nt][1] + bv.y) * sc;
            float v2 = (acc[mt][nt][2] + bv.x) * sc;
            float v3 = (acc[mt][nt][3] + bv.y) * sc;
            __half2 h01 = __floats2half2_rn(v0, v1);
            __half2 h23 = __floats2half2_rn(v2, v3);
            *(uint32_t*)(C + (size_t)r0 * N + c)       = *(uint32_t*)&h01;
            *(uint32_t*)(C + (size_t)(r0 + 8) * N + c) = *(uint32_t*)&h23;
        }
    }
}

// ---------------------------------------------------------------------------
// Out projection: 2-product fp16 (A fp16 single, B = Wo^T fp16 hi/lo),
// fp32 out, 3-stage cp.async pipeline.
// ---------------------------------------------------------------------------
#define GO_STAGE_BYTES 49152                  // A 16KB + Bh 16KB + Bl 16KB
#define GO_SMEM_BYTES  (3 * GO_STAGE_BYTES)   // 147456

__global__ __launch_bounds__(256) void gemm_out_kernel(
    const __half* __restrict__ A, const __half* __restrict__ Bh,
    const __half* __restrict__ Bl, float* __restrict__ Cf,
    int M, int N, int K)
{
    extern __shared__ char gsm[];
    const uint32_t sb = smem_u32(gsm);

    const int tid   = threadIdx.x;
    const int wid   = tid >> 5;
    const int lane  = tid & 31;
    const int warpM = wid & 1;
    const int warpN = wid >> 1;
    const int mBase = blockIdx.y * 128;
    const int nBase = blockIdx.x * 128;
    const int nCh   = K >> 6;

    const int aRowOff = lane & 15;
    const int aKOff   = (lane >> 4) << 4;
    const int bRowOff = (lane & 7) + ((lane >> 4) << 3);
    const int bKOff   = ((lane >> 3) & 1) << 4;

    auto swz = [](uint32_t off) { return off ^ ((off >> 3) & 0x70); };

    auto load_chunk = [&](int ci, int buf) {
        const int k0 = ci << 6;
        const uint32_t sbase = sb + (uint32_t)buf * GO_STAGE_BYTES;
#pragma unroll
        for (int t = 0; t < 12; t++) {
            int idx = tid + t * 256;            // 0..3071
            int sel = idx >> 10;                // 0=A, 1=Bh, 2=Bl
            int rem = idx & 1023;
            int row = rem >> 3;                 // 0..127
            int gr  = rem & 7;
            uint32_t off = (uint32_t)(row * 128 + gr * 16);
            uint32_t sw  = off ^ ((off >> 3) & 0x70);
            if (sel == 0)
                cp16(sbase + sw, A + (size_t)(mBase + row) * K + k0 + gr * 8);
            else if (sel == 1)
                cp16(sbase + 16384 + sw,
                     Bh + (size_t)(nBase + row) * K + k0 + gr * 8);
            else
                cp16(sbase + 32768 + sw,
                     Bl + (size_t)(nBase + row) * K + k0 + gr * 8);
        }
        asm volatile("cp.async.commit_group;" ::: "memory");
    };

    float acc[4][4][4];
#pragma unroll
    for (int mt = 0; mt < 4; mt++)
#pragma unroll
        for (int nt = 0; nt < 4; nt++)
#pragma unroll
            for (int i = 0; i < 4; i++) acc[mt][nt][i] = 0.f;

    load_chunk(0, 0);
    load_chunk(1, 1);
    load_chunk(2, 2);

    for (int ci = 0; ci < nCh; ci++) {
        const int buf = ci % 3;
        const int rem = nCh - 1 - ci;
        if (rem >= 2)
            asm volatile("cp.async.wait_group 2;" ::: "memory");
        else if (rem == 1)
            asm volatile("cp.async.wait_group 1;" ::: "memory");
        else
            asm volatile("cp.async.wait_group 0;" ::: "memory");
        __syncthreads();

        const uint32_t sbase = sb + (uint32_t)buf * GO_STAGE_BYTES;
        const uint32_t aB  = sbase;
        const uint32_t bhB = sbase + 16384;
        const uint32_t blB = sbase + 32768;

#pragma unroll
        for (int ks = 0; ks < 4; ks++) {
            const int kByte = ks * 32;
            uint32_t af[4][4];
#pragma unroll
            for (int mt = 0; mt < 4; mt++) {
                uint32_t off = (uint32_t)((warpM * 64 + mt * 16 + aRowOff) * 128
                                          + kByte + aKOff);
                ldmx4(af[mt], aB + swz(off));
            }
            uint32_t bh[2][4], bl[2][4];
#pragma unroll
            for (int p = 0; p < 2; p++) {
                uint32_t off = (uint32_t)((warpN * 32 + p * 16 + bRowOff) * 128
                                          + kByte + bKOff);
                uint32_t s = swz(off);
                ldmx4(bh[p], bhB + s);
                ldmx4(bl[p], blB + s);
            }
#pragma unroll
            for (int mt = 0; mt < 4; mt++)
#pragma unroll
                for (int nt = 0; nt < 4; nt++) {
                    const uint32_t* bhf = &bh[nt >> 1][(nt & 1) * 2];
                    const uint32_t* blf = &bl[nt >> 1][(nt & 1) * 2];
                    mma16816h(acc[mt][nt], af[mt], bhf);
                    mma16816h(acc[mt][nt], af[mt], blf);
                }
        }
        __syncthreads();
        if (ci + 3 < nCh) load_chunk(ci + 3, buf);
    }

    const int mW = mBase + warpM * 64;
    const int nW = nBase + warpN * 32;
#pragma unroll
    for (int mt = 0; mt < 4; mt++) {
#pragma unroll
        for (int nt = 0; nt < 4; nt++) {
            int r0 = mW + mt * 16 + (lane >> 2);
            int c  = nW + nt * 8 + (lane & 3) * 2;
            *(float2*)(Cf + (size_t)r0 * N + c) =
                make_float2(acc[mt][nt][0], acc[mt][nt][1]);
            *(float2*)(Cf + (size_t)(r0 + 8) * N + c) =
                make_float2(acc[mt][nt][2], acc[mt][nt][3]);
        }
    }
}

// ---------------------------------------------------------------------------
// Flash attention, fp16 single-product mma.
// BM=64, 128 threads (4 warps), 2 CTAs/SM. Q fragments in registers;
// 3-stage K/V pipeline aliasing the Q smem region. log2-domain softmax.
// Output: single fp16 (feeds 2-product out-GEMM).
// ---------------------------------------------------------------------------
#define FA_SMEM_BYTES (3 * 32768)   // 98304; 2 CTAs/SM -> 192KB

__global__ __launch_bounds__(128, 2) void flash_mma_kernel(
    const __half* __restrict__ qkv, __half* __restrict__ oh)
{
    extern __shared__ char fsm[];
    const uint32_t sb  = smem_u32(fsm);
    const int tid  = threadIdx.x;
    const int wid  = tid >> 5;        // 0..3
    const int lane = tid & 31;
    const int q0 = blockIdx.x * 64;
    const int h  = blockIdx.y;
    const int b  = blockIdx.z;
    const int g  = h >> 2;

    const size_t qrow0 = (size_t)b * SEQ + q0;
    const int qcol = h * HD;
    const int kcol = EMB + g * HD;
    const int vcol = EMB + KVW + g * HD;

    // --- Q (64 rows x 256B) into [sb, sb+16KB): 2 blocks of [64 x 128B] ---
#pragma unroll
    for (int t = 0; t < 8; t++) {
        int idx = tid + t * 128;        // 0..1023
        int row = idx >> 4;             // 0..63
        int gr  = idx & 15;
        int blk = gr >> 3;
        uint32_t off = (uint32_t)(row * 128 + (gr & 7) * 16);
        uint32_t sw  = off ^ ((off >> 3) & 0x70);
        size_t go = (qrow0 + row) * QKVW + qcol + gr * 8;
        cp16(sb + blk * 8192 + sw, qkv + go);
    }
    asm volatile("cp.async.commit_group;" ::: "memory");

    auto stage_base = [&](int s) -> uint32_t {
        return sb + (uint32_t)(((s + 1) % 3) * 32768);
    };

    auto load_stage = [&](int ci) {
        const uint32_t s0 = stage_base(ci);
        const int kr0 = ci * 64;
#pragma unroll
        for (int t = 0; t < 16; t++) {
            int arr = t >> 3;                   // 0=K, 1=V
            int idx = tid + (t & 7) * 128;      // 0..1023
            int row = idx >> 4;                 // 0..63
            int gr  = idx & 15;
            int blk = gr >> 3;
            uint32_t off = (uint32_t)(row * 128 + (gr & 7) * 16);
            uint32_t sw  = off ^ ((off >> 3) & 0x70);
            uint32_t dst = s0 + (uint32_t)arr * 16384u + (uint32_t)blk * 8192u + sw;
            int col = (arr == 0) ? kcol : vcol;
            size_t go = (size_t)(b * SEQ + kr0 + row) * QKVW + col + gr * 8;
            cp16(dst, qkv + go);
        }
        asm volatile("cp.async.commit_group;" ::: "memory");
    };

    load_stage(0);      // -> sb+32KB
    load_stage(1);      // -> sb+64KB

    const int gid = lane >> 2, tig = lane & 3;
    const int qrw = wid * 16;           // 0..48

    const int aRow = lane & 15;
    const int aCol = (lane >> 4) << 4;
    const int bRow = (lane & 7) + ((lane >> 4) << 3);
    const int bCol = ((lane >> 3) & 1) << 4;
    const int vRow = (lane & 7) + (((lane >> 3) & 1) << 3);
    const int vCol = (lane >> 4) << 4;

    // --- hoist Q fragments to registers (wait Q group only) ---
    asm volatile("cp.async.wait_group 2;" ::: "memory");
    __syncthreads();
    uint32_t qreg[8][4];
#pragma unroll
    for (int ks = 0; ks < 8; ks++) {
        const int blk = ks >> 2;
        const int kb  = (ks & 3) * 32;
        uint32_t offq = (uint32_t)((qrw + aRow) * 128 + kb + aCol);
        uint32_t swq  = offq ^ ((offq >> 3) & 0x70);
        ldmx4(qreg[ks], sb + blk * 8192 + swq);
    }
    __syncthreads();    // all warps done reading Q smem
    load_stage(2);      // -> sb (aliases freed Q region)

    float m0 = -1e30f, m1 = -1e30f, l0 = 0.f, l1 = 0.f;
    float o[16][4];
#pragma unroll
    for (int t = 0; t < 16; t++)
#pragma unroll
        for (int i = 0; i < 4; i++) o[t][i] = 0.f;

    for (int ci = 0; ci < SEQ / 64; ci++) {
        if (ci < SEQ / 64 - 2)
            asm volatile("cp.async.wait_group 2;" ::: "memory");
        else if (ci == SEQ / 64 - 2)
            asm volatile("cp.async.wait_group 1;" ::: "memory");
        else
            asm volatile("cp.async.wait_group 0;" ::: "memory");
        __syncthreads();

        const uint32_t s0 = stage_base(ci);
        const uint32_t KB = s0, VB = s0 + 16384;

        // ---- S = Q @ K^T (Q from registers) ----
        float s[8][4];
#pragma unroll
        for (int t = 0; t < 8; t++)
#pragma unroll
            for (int i = 0; i < 4; i++) s[t][i] = 0.f;

#pragma unroll
        for (int ks = 0; ks < 8; ks++) {
            const int blk = ks >> 2;
            const int kb  = (ks & 3) * 32;
#pragma unroll
            for (int nb = 0; nb < 4; nb++) {
                uint32_t kf[4];
                uint32_t offk = (uint32_t)((nb * 16 + bRow) * 128 + kb + bCol);
                uint32_t swk  = offk ^ ((offk >> 3) & 0x70);
                ldmx4(kf, KB + blk * 8192 + swk);
                mma16816h(s[2 * nb],     qreg[ks], &kf[0]);
                mma16816h(s[2 * nb + 1], qreg[ks], &kf[2]);
            }
        }

        // ---- online softmax (log2 domain) ----
        float mx0 = -1e30f, mx1 = -1e30f;
#pragma unroll
        for (int t = 0; t < 8; t++) {
            mx0 = fmaxf(mx0, fmaxf(s[t][0], s[t][1]));
            mx1 = fmaxf(mx1, fmaxf(s[t][2], s[t][3]));
        }
        mx0 = fmaxf(mx0, __shfl_xor_sync(0xffffffffu, mx0, 1));
        mx0 = fmaxf(mx0, __shfl_xor_sync(0xffffffffu, mx0, 2));
        mx1 = fmaxf(mx1, __shfl_xor_sync(0xffffffffu, mx1, 1));
        mx1 = fmaxf(mx1, __shfl_xor_sync(0xffffffffu, mx1, 2));

        float mn0 = fmaxf(m0, mx0), mn1 = fmaxf(m1, mx1);
        float a0 = ex2(m0 - mn0), a1 = ex2(m1 - mn1);
        m0 = mn0; m1 = mn1;

        float rs0 = 0.f, rs1 = 0.f;
        uint32_t pa[4][4];
#pragma unroll
        for (int t = 0; t < 8; t++) {
            __half2 h01 = h2exp2(__floats2half2_rn(s[t][0] - mn0, s[t][1] - mn0));
            __half2 h23 = h2exp2(__floats2half2_rn(s[t][2] - mn1, s[t][3] - mn1));
            float2 f01 = __half22float2(h01);
            float2 f23 = __half22float2(h23);
            rs0 += f01.x + f01.y;
            rs1 += f23.x + f23.y;
            int j = t >> 1, sl = (t & 1) * 2;
            pa[j][sl]     = *(uint32_t*)&h01;
            pa[j][sl + 1] = *(uint32_t*)&h23;
        }
        rs0 += __shfl_xor_sync(0xffffffffu, rs0, 1);
        rs0 += __shfl_xor_sync(0xffffffffu, rs0, 2);
        rs1 += __shfl_xor_sync(0xffffffffu, rs1, 1);
        rs1 += __shfl_xor_sync(0xffffffffu, rs1, 2);
        l0 = l0 * a0 + rs0;
        l1 = l1 * a1 + rs1;

        // rescale O only when the running max actually moved
        if (a0 != 1.f || a1 != 1.f) {
#pragma unroll
            for (int t = 0; t < 16; t++) {
                o[t][0] *= a0; o[t][1] *= a0;
                o[t][2] *= a1; o[t][3] *= a1;
            }
        }

        // ---- O += P @ V ----
#pragma unroll
        for (int j = 0; j < 4; j++) {
#pragma unroll
            for (int tp = 0; tp < 8; tp++) {
                const int blk = tp >> 2;
                const int cb  = (tp & 3) * 32 + vCol;
                uint32_t offv = (uint32_t)((j * 16 + vRow) * 128 + cb);
                uint32_t swv  = offv ^ ((offv >> 3) & 0x70);
                uint32_t vf[4];
                ldmx4t(vf, VB + blk * 8192 + swv);
                mma16816h(o[2 * tp],     pa[j], &vf[0]);
                mma16816h(o[2 * tp + 1], pa[j], &vf[2]);
            }
        }

        __syncthreads();
        if (ci + 3 < SEQ / 64) load_stage(ci + 3);
    }

    // ---- epilogue: normalize, store single fp16 ----
    float i0 = 1.0f / l0, i1 = 1.0f / l1;
    size_t r0 = (qrow0 + qrw + gid) * EMB + (size_t)h * HD;
    size_t r1 = (qrow0 + qrw + gid + 8) * EMB + (size_t)h * HD;
#pragma unroll
    for (int t = 0; t < 16; t++) {
        int c = t * 8 + tig * 2;
        __half2 ha = __floats2half2_rn(o[t][0] * i0, o[t][1] * i0);
        __half2 hb = __floats2half2_rn(o[t][2] * i1, o[t][3] * i1);
        *(uint32_t*)(oh + r0 + c) = *(uint32_t*)&ha;
        *(uint32_t*)(oh + r1 + c) = *(uint32_t*)&hb;
    }
}

// ---------------------------------------------------------------------------
// kernel_launch
// ---------------------------------------------------------------------------
extern "C" void kernel_launch(void* const* d_in, const int* in_sizes, int n_in,
                              void* d_out, int out_size)
{
    const float* x  = (const float*)d_in[0];
    const float* Wq = (const float*)d_in[1];
    const float* bq = (const float*)d_in[2];
    const float* Wk = (const float*)d_in[3];
    const float* bk = (const float*)d_in[4];
    const float* Wv = (const float*)d_in[5];
    const float* bv = (const float*)d_in[6];
    const float* Wo = (const float*)d_in[7];
    float* out = (float*)d_out;

    __half *pxh, *pqkv, *pwc, *poh, *pwoh, *pwol;
    float* pbias;
    cudaGetSymbolAddress((void**)&pxh,  g_xh);
    cudaGetSymbolAddress((void**)&pqkv, g_qkv);
    cudaGetSymbolAddress((void**)&pwc,  g_wc);
    cudaGetSymbolAddress((void**)&poh,  g_oh);
    cudaGetSymbolAddress((void**)&pwoh, g_woh);
    cudaGetSymbolAddress((void**)&pwol, g_wol);
    cudaGetSymbolAddress((void**)&pbias, g_bias);

    cudaFuncSetAttribute(gemm_f16_kernel,
                         cudaFuncAttributeMaxDynamicSharedMemorySize, GH_SMEM_BYTES);
    cudaFuncSetAttribute(gemm_out_kernel,
                         cudaFuncAttributeMaxDynamicSharedMemorySize, GO_SMEM_BYTES);
    cudaFuncSetAttribute(flash_mma_kernel,
                         cudaFuncAttributeMaxDynamicSharedMemorySize, FA_SMEM_BYTES);

    const int nx = MROWS * EMB;
    // q pre-scale: log2(e) / sqrt(HD)  (softmax runs in log2 domain)
    const float qscale = 0.088388347648318447f * 1.4426950408889634f;

    // 1) x -> fp16
    to_half_kernel<<<nx / (4 * 256), 256>>>(x, pxh, nx);

    // 2) weights: QKV concat transpose (one launch); Wo -> fp16 hi/lo
    dim3 tb(32, 8);
    transpose_qkv_kernel<<<dim3(QKVW / 32, EMB / 32), tb>>>(Wq, Wk, Wv, pwc);
    transpose_split_h_kernel<<<dim3(EMB / 32, EMB / 32), tb>>>(
        Wo, pwoh, pwol, EMB, EMB);
    cudaMemcpyAsync(pbias,             bq, EMB * sizeof(float), cudaMemcpyDeviceToDevice);
    cudaMemcpyAsync(pbias + EMB,       bk, KVW * sizeof(float), cudaMemcpyDeviceToDevice);
    cudaMemcpyAsync(pbias + EMB + KVW, bv, KVW * sizeof(float), cudaMemcpyDeviceToDevice);

    // 3) fused QKV projection, single-product fp16 (Q cols pre-scaled)
    gemm_f16_kernel<<<dim3(QKVW / 128, MROWS / 128), 256, GH_SMEM_BYTES>>>(
        pxh, pwc, pbias, pqkv, qscale, EMB, MROWS, QKVW, EMB);

    // 4) flash attention (fp16, BM=64, 2 CTAs/SM) -> single fp16 output
    flash_mma_kernel<<<dim3(SEQ / 64, HQ, BATCH), 128, FA_SMEM_BYTES>>>(
        pqkv, poh);

    // 5) output projection: 2-product fp16 (A fp16, Wo fp16 hi/lo) -> fp32
    gemm_out_kernel<<<dim3(EMB / 128, MROWS / 128), 256, GO_SMEM_BYTES>>>(
        poh, pwoh, pwol, out, MROWS, EMB, EMB);
}

// round 12
// speedup vs baseline: 9.2423x; 1.0617x over previous
#include <cuda_runtime.h>
#include <cuda_bf16.h>
#include <cuda_fp16.h>
#include <cstdint>

#define BATCH 2
#define SEQ   2048
#define EMB   2048
#define HQ    16
#define HKV   4
#define HD    128
#define KVW   (HKV * HD)        // 512
#define MROWS (BATCH * SEQ)     // 4096
#define QKVW  (EMB + 2 * KVW)   // 3072

// ---------------------------------------------------------------------------
// PTX helpers — ONLY non-arch-suffixed instructions (compute_103-safe)
// ---------------------------------------------------------------------------
__device__ __forceinline__ uint32_t smem_u32(const void* p) {
    uint32_t a;
    asm("{ .reg .u64 t; cvta.to.shared.u64 t, %1; cvt.u32.u64 %0, t; }"
        : "=r"(a) : "l"(p));
    return a;
}

__device__ __forceinline__ void cp16(uint32_t saddr, const void* gaddr) {
    asm volatile("cp.async.cg.shared.global [%0], [%1], 16;"
                 :: "r"(saddr), "l"(gaddr));
}

__device__ __forceinline__ void ldmx4(uint32_t* r, uint32_t addr) {
    asm volatile("ldmatrix.sync.aligned.m8n8.x4.shared.b16 {%0,%1,%2,%3}, [%4];"
                 : "=r"(r[0]), "=r"(r[1]), "=r"(r[2]), "=r"(r[3]) : "r"(addr));
}

__device__ __forceinline__ void ldmx4t(uint32_t* r, uint32_t addr) {
    asm volatile("ldmatrix.sync.aligned.m8n8.x4.trans.shared.b16 {%0,%1,%2,%3}, [%4];"
                 : "=r"(r[0]), "=r"(r[1]), "=r"(r[2]), "=r"(r[3]) : "r"(addr));
}

// fp16 mma
__device__ __forceinline__ void mma16816h(float* c, const uint32_t* a,
                                          const uint32_t* b) {
    asm volatile(
        "mma.sync.aligned.m16n8k16.row.col.f32.f16.f16.f32 "
        "{%0,%1,%2,%3}, {%4,%5,%6,%7}, {%8,%9}, {%0,%1,%2,%3};"
        : "+f"(c[0]), "+f"(c[1]), "+f"(c[2]), "+f"(c[3])
        : "r"(a[0]), "r"(a[1]), "r"(a[2]), "r"(a[3]), "r"(b[0]), "r"(b[1]));
}

__device__ __forceinline__ float ex2(float x) {
    float y;
    asm("ex2.approx.f32 %0, %1;" : "=f"(y) : "f"(x));
    return y;
}

// ---------------------------------------------------------------------------
// Device scratch (no cudaMalloc allowed)
// ---------------------------------------------------------------------------
__device__ __half g_xh[(size_t)MROWS * EMB];       // x fp16
__device__ __half g_qkv[(size_t)MROWS * QKVW];     // fused q|k|v fp16
__device__ __half g_oh[(size_t)MROWS * EMB];       // attn out fp16
__device__ __half g_wc[(size_t)QKVW * EMB];        // concat Wq|Wk|Wv ^T fp16
__device__ __half g_woh[(size_t)EMB * EMB];        // Wo^T fp16 hi
__device__ __half g_wol[(size_t)EMB * EMB];        // Wo^T fp16 lo (residual)
__device__ float  g_bias[QKVW];                    // concat bq|bk|bv

// ---------------------------------------------------------------------------
// fp32 -> fp16 convert (elementwise)
// ---------------------------------------------------------------------------
__global__ __launch_bounds__(256) void to_half_kernel(
    const float* __restrict__ x, __half* __restrict__ y, int n)
{
    int i = (blockIdx.x * 256 + threadIdx.x) * 4;
    if (i >= n) return;
    float4 v = *(const float4*)(x + i);
    __half2 h0 = __floats2half2_rn(v.x, v.y);
    __half2 h1 = __floats2half2_rn(v.z, v.w);
    uint2 o = make_uint2(*(uint32_t*)&h0, *(uint32_t*)&h1);
    *(uint2*)(y + i) = o;
}

// ---------------------------------------------------------------------------
// Merged transpose of Wq|Wk|Wv into the concat fp16 buffer [QKVW, EMB]
// ---------------------------------------------------------------------------
__global__ __launch_bounds__(256) void transpose_qkv_kernel(
    const float* __restrict__ Wq, const float* __restrict__ Wk,
    const float* __restrict__ Wv, __half* __restrict__ T)
{
    __shared__ float tile[32][33];
    const int tx = threadIdx.x, ty = threadIdx.y;
    const int nBase = blockIdx.x * 32;   // 0..QKVW-32
    const int kBase = blockIdx.y * 32;   // 0..EMB-32

    const float* W;
    int srcN, ln;
    if (nBase < EMB)            { W = Wq; srcN = EMB; ln = nBase; }
    else if (nBase < EMB + KVW) { W = Wk; srcN = KVW; ln = nBase - EMB; }
    else                        { W = Wv; srcN = KVW; ln = nBase - EMB - KVW; }

#pragma unroll
    for (int i = 0; i < 4; i++)
        tile[ty + 8 * i][tx] = W[(size_t)(kBase + ty + 8 * i) * srcN + ln + tx];
    __syncthreads();
#pragma unroll
    for (int i = 0; i < 4; i++) {
        float v = tile[tx][ty + 8 * i];
        T[(size_t)(nBase + ty + 8 * i) * EMB + kBase + tx] = __float2half(v);
    }
}

// ---------------------------------------------------------------------------
// Transpose + fp16 hi/lo split: W [K,N] fp32 -> Thi/Tlo [N,K] fp16
// ---------------------------------------------------------------------------
__global__ __launch_bounds__(256) void transpose_split_h_kernel(
    const float* __restrict__ W, __half* __restrict__ Thi,
    __half* __restrict__ Tlo, int K, int N)
{
    __shared__ float tile[32][33];
    const int tx = threadIdx.x, ty = threadIdx.y;
    const int nBase = blockIdx.x * 32, kBase = blockIdx.y * 32;
#pragma unroll
    for (int i = 0; i < 4; i++)
        tile[ty + 8 * i][tx] = W[(size_t)(kBase + ty + 8 * i) * N + nBase + tx];
    __syncthreads();
#pragma unroll
    for (int i = 0; i < 4; i++) {
        float v = tile[tx][ty + 8 * i];
        __half h = __float2half(v);
        __half l = __float2half(v - __half2float(h));
        size_t idx = (size_t)(nBase + ty + 8 * i) * K + kBase + tx;
        Thi[idx] = h;
        Tlo[idx] = l;
    }
}

// ---------------------------------------------------------------------------
// Single-product fp16 GEMM (QKV projection), 3-stage cp.async pipeline,
// 2 CTAs/SM (16 warps/SM) to cover ldmatrix->mma dependency gaps.
// ---------------------------------------------------------------------------
#define GH_STAGE_BYTES 32768                 // A 16KB + B 16KB
#define GH_SMEM_BYTES  (3 * GH_STAGE_BYTES)  // 98304; x2 CTAs = 192KB

__global__ __launch_bounds__(256, 2) void gemm_f16_kernel(
    const __half* __restrict__ A, const __half* __restrict__ B,
    const float* __restrict__ bias, __half* __restrict__ C,
    float qsc, int qcols, int M, int N, int K)
{
    extern __shared__ char gsm[];
    const uint32_t sb = smem_u32(gsm);

    const int tid   = threadIdx.x;
    const int wid   = tid >> 5;
    const int lane  = tid & 31;
    const int warpM = wid & 1;
    const int warpN = wid >> 1;
    const int mBase = blockIdx.y * 128;
    const int nBase = blockIdx.x * 128;
    const int nCh   = K >> 6;

    const int aRowOff = lane & 15;
    const int aKOff   = (lane >> 4) << 4;
    const int bRowOff = (lane & 7) + ((lane >> 4) << 3);
    const int bKOff   = ((lane >> 3) & 1) << 4;

    auto swz = [](uint32_t off) { return off ^ ((off >> 3) & 0x70); };

    auto load_chunk = [&](int ci, int buf) {
        const int k0 = ci << 6;
        const uint32_t sbase = sb + (uint32_t)buf * GH_STAGE_BYTES;
#pragma unroll
        for (int t = 0; t < 8; t++) {
            int idx = tid + t * 256;
            int ab  = idx >> 10;
            int row = (idx >> 3) & 127;
            int gr  = idx & 7;
            uint32_t off = (uint32_t)(row * 128 + gr * 16);
            uint32_t sw  = off ^ ((off >> 3) & 0x70);
            if (ab == 0)
                cp16(sbase + sw, A + (size_t)(mBase + row) * K + k0 + gr * 8);
            else
                cp16(sbase + 16384 + sw,
                     B + (size_t)(nBase + row) * K + k0 + gr * 8);
        }
        asm volatile("cp.async.commit_group;" ::: "memory");
    };

    float acc[4][4][4];
#pragma unroll
    for (int mt = 0; mt < 4; mt++)
#pragma unroll
        for (int nt = 0; nt < 4; nt++)
#pragma unroll
            for (int i = 0; i < 4; i++) acc[mt][nt][i] = 0.f;

    load_chunk(0, 0);
    load_chunk(1, 1);
    load_chunk(2, 2);

    for (int ci = 0; ci < nCh; ci++) {
        const int buf = ci % 3;
        const int rem = nCh - 1 - ci;
        if (rem >= 2)
            asm volatile("cp.async.wait_group 2;" ::: "memory");
        else if (rem == 1)
            asm volatile("cp.async.wait_group 1;" ::: "memory");
        else
            asm volatile("cp.async.wait_group 0;" ::: "memory");
        __syncthreads();

        const uint32_t sbase = sb + (uint32_t)buf * GH_STAGE_BYTES;
        const uint32_t aB = sbase;
        const uint32_t bB = sbase + 16384;

#pragma unroll
        for (int ks = 0; ks < 4; ks++) {
            const int kByte = ks * 32;
            uint32_t af[4][4];
#pragma unroll
            for (int mt = 0; mt < 4; mt++) {
                uint32_t off = (uint32_t)((warpM * 64 + mt * 16 + aRowOff) * 128
                                          + kByte + aKOff);
                ldmx4(af[mt], aB + swz(off));
            }
            uint32_t bf[2][4];
#pragma unroll
            for (int p = 0; p < 2; p++) {
                uint32_t off = (uint32_t)((warpN * 32 + p * 16 + bRowOff) * 128
                                          + kByte + bKOff);
                ldmx4(bf[p], bB + swz(off));
            }
#pragma unroll
            for (int mt = 0; mt < 4; mt++)
#pragma unroll
                for (int nt = 0; nt < 4; nt++)
                    mma16816h(acc[mt][nt], af[mt], &bf[nt >> 1][(nt & 1) * 2]);
        }
        __syncthreads();
        if (ci + 3 < nCh) load_chunk(ci + 3, buf);
    }

    const int mW = mBase + warpM * 64;
    const int nW = nBase + warpN * 32;
#pragma unroll
    for (int mt = 0; mt < 4; mt++) {
#pragma unroll
        for (int nt = 0; nt < 4; nt++) {
            int r0 = mW + mt * 16 + (lane >> 2);
            int c  = nW + nt * 8 + (lane & 3) * 2;
            float2 bv = *(const float2*)(bias + c);
            float sc = (c < qcols) ? qsc : 1.f;
            float v0 = (acc[mt][nt][0] + bv.x) * sc;
            float v1 = (acc[mt][nt][1] + bv.y) * sc;
            float v2 = (acc[mt][nt][2] + bv.x) * sc;
            float v3 = (acc[mt][nt][3] + bv.y) * sc;
            __half2 h01 = __floats2half2_rn(v0, v1);
            __half2 h23 = __floats2half2_rn(v2, v3);
            *(uint32_t*)(C + (size_t)r0 * N + c)       = *(uint32_t*)&h01;
            *(uint32_t*)(C + (size_t)(r0 + 8) * N + c) = *(uint32_t*)&h23;
        }
    }
}

// ---------------------------------------------------------------------------
// Out projection: 2-product fp16 (A fp16, B = Wo^T fp16 hi/lo), fp32 out.
// 2-stage cp.async pipeline, 2 CTAs/SM.
// ---------------------------------------------------------------------------
#define GO_STAGE_BYTES 49152                  // A 16KB + Bh 16KB + Bl 16KB
#define GO_SMEM_BYTES  (2 * GO_STAGE_BYTES)   // 98304; x2 CTAs = 192KB

__global__ __launch_bounds__(256, 2) void gemm_out_kernel(
    const __half* __restrict__ A, const __half* __restrict__ Bh,
    const __half* __restrict__ Bl, float* __restrict__ Cf,
    int M, int N, int K)
{
    extern __shared__ char gsm[];
    const uint32_t sb = smem_u32(gsm);

    const int tid   = threadIdx.x;
    const int wid   = tid >> 5;
    const int lane  = tid & 31;
    const int warpM = wid & 1;
    const int warpN = wid >> 1;
    const int mBase = blockIdx.y * 128;
    const int nBase = blockIdx.x * 128;
    const int nCh   = K >> 6;

    const int aRowOff = lane & 15;
    const int aKOff   = (lane >> 4) << 4;
    const int bRowOff = (lane & 7) + ((lane >> 4) << 3);
    const int bKOff   = ((lane >> 3) & 1) << 4;

    auto swz = [](uint32_t off) { return off ^ ((off >> 3) & 0x70); };

    auto load_chunk = [&](int ci, int buf) {
        const int k0 = ci << 6;
        const uint32_t sbase = sb + (uint32_t)buf * GO_STAGE_BYTES;
#pragma unroll
        for (int t = 0; t < 12; t++) {
            int idx = tid + t * 256;            // 0..3071
            int sel = idx >> 10;                // 0=A, 1=Bh, 2=Bl
            int rem = idx & 1023;
            int row = rem >> 3;                 // 0..127
            int gr  = rem & 7;
            uint32_t off = (uint32_t)(row * 128 + gr * 16);
            uint32_t sw  = off ^ ((off >> 3) & 0x70);
            if (sel == 0)
                cp16(sbase + sw, A + (size_t)(mBase + row) * K + k0 + gr * 8);
            else if (sel == 1)
                cp16(sbase + 16384 + sw,
                     Bh + (size_t)(nBase + row) * K + k0 + gr * 8);
            else
                cp16(sbase + 32768 + sw,
                     Bl + (size_t)(nBase + row) * K + k0 + gr * 8);
        }
        asm volatile("cp.async.commit_group;" ::: "memory");
    };

    float acc[4][4][4];
#pragma unroll
    for (int mt = 0; mt < 4; mt++)
#pragma unroll
        for (int nt = 0; nt < 4; nt++)
#pragma unroll
            for (int i = 0; i < 4; i++) acc[mt][nt][i] = 0.f;

    load_chunk(0, 0);
    load_chunk(1, 1);

    for (int ci = 0; ci < nCh; ci++) {
        const int buf = ci & 1;
        if (ci + 1 < nCh)
            asm volatile("cp.async.wait_group 1;" ::: "memory");
        else
            asm volatile("cp.async.wait_group 0;" ::: "memory");
        __syncthreads();

        const uint32_t sbase = sb + (uint32_t)buf * GO_STAGE_BYTES;
        const uint32_t aB  = sbase;
        const uint32_t bhB = sbase + 16384;
        const uint32_t blB = sbase + 32768;

#pragma unroll
        for (int ks = 0; ks < 4; ks++) {
            const int kByte = ks * 32;
            uint32_t af[4][4];
#pragma unroll
            for (int mt = 0; mt < 4; mt++) {
                uint32_t off = (uint32_t)((warpM * 64 + mt * 16 + aRowOff) * 128
                                          + kByte + aKOff);
                ldmx4(af[mt], aB + swz(off));
            }
            uint32_t bh[2][4], bl[2][4];
#pragma unroll
            for (int p = 0; p < 2; p++) {
                uint32_t off = (uint32_t)((warpN * 32 + p * 16 + bRowOff) * 128
                                          + kByte + bKOff);
                uint32_t s = swz(off);
                ldmx4(bh[p], bhB + s);
                ldmx4(bl[p], blB + s);
            }
#pragma unroll
            for (int mt = 0; mt < 4; mt++)
#pragma unroll
                for (int nt = 0; nt < 4; nt++) {
                    const uint32_t* bhf = &bh[nt >> 1][(nt & 1) * 2];
                    const uint32_t* blf = &bl[nt >> 1][(nt & 1) * 2];
                    mma16816h(acc[mt][nt], af[mt], bhf);
                    mma16816h(acc[mt][nt], af[mt], blf);
                }
        }
        __syncthreads();
        if (ci + 2 < nCh) load_chunk(ci + 2, buf);
    }

    const int mW = mBase + warpM * 64;
    const int nW = nBase + warpN * 32;
#pragma unroll
    for (int mt = 0; mt < 4; mt++) {
#pragma unroll
        for (int nt = 0; nt < 4; nt++) {
            int r0 = mW + mt * 16 + (lane >> 2);
            int c  = nW + nt * 8 + (lane & 3) * 2;
            *(float2*)(Cf + (size_t)r0 * N + c) =
                make_float2(acc[mt][nt][0], acc[mt][nt][1]);
            *(float2*)(Cf + (size_t)(r0 + 8) * N + c) =
                make_float2(acc[mt][nt][2], acc[mt][nt][3]);
        }
    }
}

// ---------------------------------------------------------------------------
// Flash attention, fp16 single-product mma.
// BM=64, 128 threads (4 warps), 3 CTAs/SM (12 warps/SM).
// 2-stage K/V pipeline (64KB total); Q parked at sb, aliased by stage 1
// after the register hoist. log2-domain softmax; single fp16 output.
// ---------------------------------------------------------------------------
#define FA_SMEM_BYTES (2 * 32768)   // 65536; 3 CTAs/SM -> 192KB

__global__ __launch_bounds__(128, 3) void flash_mma_kernel(
    const __half* __restrict__ qkv, __half* __restrict__ oh)
{
    extern __shared__ char fsm[];
    const uint32_t sb  = smem_u32(fsm);
    const int tid  = threadIdx.x;
    const int wid  = tid >> 5;        // 0..3
    const int lane = tid & 31;
    const int q0 = blockIdx.x * 64;
    const int h  = blockIdx.y;
    const int b  = blockIdx.z;
    const int g  = h >> 2;

    const size_t qrow0 = (size_t)b * SEQ + q0;
    const int qcol = h * HD;
    const int kcol = EMB + g * HD;
    const int vcol = EMB + KVW + g * HD;

    // --- Q (64 rows x 256B) into [sb, sb+16KB): 2 blocks of [64 x 128B] ---
#pragma unroll
    for (int t = 0; t < 8; t++) {
        int idx = tid + t * 128;        // 0..1023
        int row = idx >> 4;             // 0..63
        int gr  = idx & 15;
        int blk = gr >> 3;
        uint32_t off = (uint32_t)(row * 128 + (gr & 7) * 16);
        uint32_t sw  = off ^ ((off >> 3) & 0x70);
        size_t go = (qrow0 + row) * QKVW + qcol + gr * 8;
        cp16(sb + blk * 8192 + sw, qkv + go);
    }
    asm volatile("cp.async.commit_group;" ::: "memory");

    // stage s lives at sb + ((s+1)&1)*32KB : s=0 -> +32KB, s=1 -> sb (aliases Q)
    auto stage_base = [&](int s) -> uint32_t {
        return sb + (uint32_t)(((s + 1) & 1) * 32768);
    };

    auto load_stage = [&](int ci) {
        const uint32_t s0 = stage_base(ci);
        const int kr0 = ci * 64;
#pragma unroll
        for (int t = 0; t < 16; t++) {
            int arr = t >> 3;                   // 0=K, 1=V
            int idx = tid + (t & 7) * 128;      // 0..1023
            int row = idx >> 4;                 // 0..63
            int gr  = idx & 15;
            int blk = gr >> 3;
            uint32_t off = (uint32_t)(row * 128 + (gr & 7) * 16);
            uint32_t sw  = off ^ ((off >> 3) & 0x70);
            uint32_t dst = s0 + (uint32_t)arr * 16384u + (uint32_t)blk * 8192u + sw;
            int col = (arr == 0) ? kcol : vcol;
            size_t go = (size_t)(b * SEQ + kr0 + row) * QKVW + col + gr * 8;
            cp16(dst, qkv + go);
        }
        asm volatile("cp.async.commit_group;" ::: "memory");
    };

    load_stage(0);      // -> sb+32KB (does not touch Q)

    const int gid = lane >> 2, tig = lane & 3;
    const int qrw = wid * 16;           // 0..48

    const int aRow = lane & 15;
    const int aCol = (lane >> 4) << 4;
    const int bRow = (lane & 7) + ((lane >> 4) << 3);
    const int bCol = ((lane >> 3) & 1) << 4;
    const int vRow = (lane & 7) + (((lane >> 3) & 1) << 3);
    const int vCol = (lane >> 4) << 4;

    // --- hoist Q fragments to registers (Q group done; S0 may be pending) ---
    asm volatile("cp.async.wait_group 1;" ::: "memory");
    __syncthreads();
    uint32_t qreg[8][4];
#pragma unroll
    for (int ks = 0; ks < 8; ks++) {
        const int blk = ks >> 2;
        const int kb  = (ks & 3) * 32;
        uint32_t offq = (uint32_t)((qrw + aRow) * 128 + kb + aCol);
        uint32_t swq  = offq ^ ((offq >> 3) & 0x70);
        ldmx4(qreg[ks], sb + blk * 8192 + swq);
    }
    __syncthreads();    // all warps done reading Q smem
    load_stage(1);      // -> sb (aliases freed Q region)

    float m0 = -1e30f, m1 = -1e30f, l0 = 0.f, l1 = 0.f;
    float o[16][4];
#pragma unroll
    for (int t = 0; t < 16; t++)
#pragma unroll
        for (int i = 0; i < 4; i++) o[t][i] = 0.f;

    const int NIT = SEQ / 64;
    for (int ci = 0; ci < NIT; ci++) {
        if (ci + 1 < NIT)
            asm volatile("cp.async.wait_group 1;" ::: "memory");
        else
            asm volatile("cp.async.wait_group 0;" ::: "memory");
        __syncthreads();

        const uint32_t s0 = stage_base(ci);
        const uint32_t KB = s0, VB = s0 + 16384;

        // ---- S = Q @ K^T (Q from registers) ----
        float s[8][4];
#pragma unroll
        for (int t = 0; t < 8; t++)
#pragma unroll
            for (int i = 0; i < 4; i++) s[t][i] = 0.f;

#pragma unroll
        for (int ks = 0; ks < 8; ks++) {
            const int blk = ks >> 2;
            const int kb  = (ks & 3) * 32;
#pragma unroll
            for (int nb = 0; nb < 4; nb++) {
                uint32_t kf[4];
                uint32_t offk = (uint32_t)((nb * 16 + bRow) * 128 + kb + bCol);
                uint32_t swk  = offk ^ ((offk >> 3) & 0x70);
                ldmx4(kf, KB + blk * 8192 + swk);
                mma16816h(s[2 * nb],     qreg[ks], &kf[0]);
                mma16816h(s[2 * nb + 1], qreg[ks], &kf[2]);
            }
        }

        // ---- online softmax (log2 domain) ----
        float mx0 = -1e30f, mx1 = -1e30f;
#pragma unroll
        for (int t = 0; t < 8; t++) {
            mx0 = fmaxf(mx0, fmaxf(s[t][0], s[t][1]));
            mx1 = fmaxf(mx1, fmaxf(s[t][2], s[t][3]));
        }
        mx0 = fmaxf(mx0, __shfl_xor_sync(0xffffffffu, mx0, 1));
        mx0 = fmaxf(mx0, __shfl_xor_sync(0xffffffffu, mx0, 2));
        mx1 = fmaxf(mx1, __shfl_xor_sync(0xffffffffu, mx1, 1));
        mx1 = fmaxf(mx1, __shfl_xor_sync(0xffffffffu, mx1, 2));

        float mn0 = fmaxf(m0, mx0), mn1 = fmaxf(m1, mx1);
        float a0 = ex2(m0 - mn0), a1 = ex2(m1 - mn1);
        m0 = mn0; m1 = mn1;

        float rs0 = 0.f, rs1 = 0.f;
        uint32_t pa[4][4];
#pragma unroll
        for (int t = 0; t < 8; t++) {
            __half2 h01 = h2exp2(__floats2half2_rn(s[t][0] - mn0, s[t][1] - mn0));
            __half2 h23 = h2exp2(__floats2half2_rn(s[t][2] - mn1, s[t][3] - mn1));
            float2 f01 = __half22float2(h01);
            float2 f23 = __half22float2(h23);
            rs0 += f01.x + f01.y;
            rs1 += f23.x + f23.y;
            int j = t >> 1, sl = (t & 1) * 2;
            pa[j][sl]     = *(uint32_t*)&h01;
            pa[j][sl + 1] = *(uint32_t*)&h23;
        }
        rs0 += __shfl_xor_sync(0xffffffffu, rs0, 1);
        rs0 += __shfl_xor_sync(0xffffffffu, rs0, 2);
        rs1 += __shfl_xor_sync(0xffffffffu, rs1, 1);
        rs1 += __shfl_xor_sync(0xffffffffu, rs1, 2);
        l0 = l0 * a0 + rs0;
        l1 = l1 * a1 + rs1;

        // rescale O only when the running max actually moved
        if (a0 != 1.f || a1 != 1.f) {
#pragma unroll
            for (int t = 0; t < 16; t++) {
                o[t][0] *= a0; o[t][1] *= a0;
                o[t][2] *= a1; o[t][3] *= a1;
            }
        }

        // ---- O += P @ V ----
#pragma unroll
        for (int j = 0; j < 4; j++) {
#pragma unroll
            for (int tp = 0; tp < 8; tp++) {
                const int blk = tp >> 2;
                const int cb  = (tp & 3) * 32 + vCol;
                uint32_t offv = (uint32_t)((j * 16 + vRow) * 128 + cb);
                uint32_t swv  = offv ^ ((offv >> 3) & 0x70);
                uint32_t vf[4];
                ldmx4t(vf, VB + blk * 8192 + swv);
                mma16816h(o[2 * tp],     pa[j], &vf[0]);
                mma16816h(o[2 * tp + 1], pa[j], &vf[2]);
            }
        }

        __syncthreads();
        if (ci + 2 < NIT) load_stage(ci + 2);
    }

    // ---- epilogue: normalize, store single fp16 ----
    float i0 = 1.0f / l0, i1 = 1.0f / l1;
    size_t r0 = (qrow0 + qrw + gid) * EMB + (size_t)h * HD;
    size_t r1 = (qrow0 + qrw + gid + 8) * EMB + (size_t)h * HD;
#pragma unroll
    for (int t = 0; t < 16; t++) {
        int c = t * 8 + tig * 2;
        __half2 ha = __floats2half2_rn(o[t][0] * i0, o[t][1] * i0);
        __half2 hb = __floats2half2_rn(o[t][2] * i1, o[t][3] * i1);
        *(uint32_t*)(oh + r0 + c) = *(uint32_t*)&ha;
        *(uint32_t*)(oh + r1 + c) = *(uint32_t*)&hb;
    }
}

// ---------------------------------------------------------------------------
// kernel_launch
// ---------------------------------------------------------------------------
extern "C" void kernel_launch(void* const* d_in, const int* in_sizes, int n_in,
                              void* d_out, int out_size)
{
    const float* x  = (const float*)d_in[0];
    const float* Wq = (const float*)d_in[1];
    const float* bq = (const float*)d_in[2];
    const float* Wk = (const float*)d_in[3];
    const float* bk = (const float*)d_in[4];
    const float* Wv = (const float*)d_in[5];
    const float* bv = (const float*)d_in[6];
    const float* Wo = (const float*)d_in[7];
    float* out = (float*)d_out;

    __half *pxh, *pqkv, *pwc, *poh, *pwoh, *pwol;
    float* pbias;
    cudaGetSymbolAddress((void**)&pxh,  g_xh);
    cudaGetSymbolAddress((void**)&pqkv, g_qkv);
    cudaGetSymbolAddress((void**)&pwc,  g_wc);
    cudaGetSymbolAddress((void**)&poh,  g_oh);
    cudaGetSymbolAddress((void**)&pwoh, g_woh);
    cudaGetSymbolAddress((void**)&pwol, g_wol);
    cudaGetSymbolAddress((void**)&pbias, g_bias);

    cudaFuncSetAttribute(gemm_f16_kernel,
                         cudaFuncAttributeMaxDynamicSharedMemorySize, GH_SMEM_BYTES);
    cudaFuncSetAttribute(gemm_out_kernel,
                         cudaFuncAttributeMaxDynamicSharedMemorySize, GO_SMEM_BYTES);
    cudaFuncSetAttribute(flash_mma_kernel,
                         cudaFuncAttributeMaxDynamicSharedMemorySize, FA_SMEM_BYTES);

    const int nx = MROWS * EMB;
    // q pre-scale: log2(e) / sqrt(HD)  (softmax runs in log2 domain)
    const float qscale = 0.088388347648318447f * 1.4426950408889634f;

    // 1) x -> fp16
    to_half_kernel<<<nx / (4 * 256), 256>>>(x, pxh, nx);

    // 2) weights: QKV concat transpose (one launch); Wo -> fp16 hi/lo
    dim3 tb(32, 8);
    transpose_qkv_kernel<<<dim3(QKVW / 32, EMB / 32), tb>>>(Wq, Wk, Wv, pwc);
    transpose_split_h_kernel<<<dim3(EMB / 32, EMB / 32), tb>>>(
        Wo, pwoh, pwol, EMB, EMB);
    cudaMemcpyAsync(pbias,             bq, EMB * sizeof(float), cudaMemcpyDeviceToDevice);
    cudaMemcpyAsync(pbias + EMB,       bk, KVW * sizeof(float), cudaMemcpyDeviceToDevice);
    cudaMemcpyAsync(pbias + EMB + KVW, bv, KVW * sizeof(float), cudaMemcpyDeviceToDevice);

    // 3) fused QKV projection, single-product fp16 (Q cols pre-scaled)
    gemm_f16_kernel<<<dim3(QKVW / 128, MROWS / 128), 256, GH_SMEM_BYTES>>>(
        pxh, pwc, pbias, pqkv, qscale, EMB, MROWS, QKVW, EMB);

    // 4) flash attention (fp16, BM=64, 3 CTAs/SM) -> single fp16 output
    flash_mma_kernel<<<dim3(SEQ / 64, HQ, BATCH), 128, FA_SMEM_BYTES>>>(
        pqkv, poh);

    // 5) output projection: 2-product fp16 (A fp16, Wo fp16 hi/lo) -> fp32
    gemm_out_kernel<<<dim3(EMB / 128, MROWS / 128), 256, GO_SMEM_BYTES>>>(
        poh, pwoh, pwol, out, MROWS, EMB, EMB);
}

// round 13
// speedup vs baseline: 10.8120x; 1.1698x over previous
#include <cuda_runtime.h>
#include <cuda_bf16.h>
#include <cuda_fp16.h>
#include <cstdint>

#define BATCH 2
#define SEQ   2048
#define EMB   2048
#define HQ    16
#define HKV   4
#define HD    128
#define KVW   (HKV * HD)        // 512
#define MROWS (BATCH * SEQ)     // 4096
#define QKVW  (EMB + 2 * KVW)   // 3072

// ---------------------------------------------------------------------------
// PTX helpers — ONLY non-arch-suffixed instructions (compute_103-safe)
// ---------------------------------------------------------------------------
__device__ __forceinline__ uint32_t smem_u32(const void* p) {
    uint32_t a;
    asm("{ .reg .u64 t; cvta.to.shared.u64 t, %1; cvt.u32.u64 %0, t; }"
        : "=r"(a) : "l"(p));
    return a;
}

__device__ __forceinline__ void cp16(uint32_t saddr, const void* gaddr) {
    asm volatile("cp.async.cg.shared.global [%0], [%1], 16;"
                 :: "r"(saddr), "l"(gaddr));
}

__device__ __forceinline__ void ldmx4(uint32_t* r, uint32_t addr) {
    asm volatile("ldmatrix.sync.aligned.m8n8.x4.shared.b16 {%0,%1,%2,%3}, [%4];"
                 : "=r"(r[0]), "=r"(r[1]), "=r"(r[2]), "=r"(r[3]) : "r"(addr));
}

__device__ __forceinline__ void ldmx4t(uint32_t* r, uint32_t addr) {
    asm volatile("ldmatrix.sync.aligned.m8n8.x4.trans.shared.b16 {%0,%1,%2,%3}, [%4];"
                 : "=r"(r[0]), "=r"(r[1]), "=r"(r[2]), "=r"(r[3]) : "r"(addr));
}

// fp16 mma
__device__ __forceinline__ void mma16816h(float* c, const uint32_t* a,
                                          const uint32_t* b) {
    asm volatile(
        "mma.sync.aligned.m16n8k16.row.col.f32.f16.f16.f32 "
        "{%0,%1,%2,%3}, {%4,%5,%6,%7}, {%8,%9}, {%0,%1,%2,%3};"
        : "+f"(c[0]), "+f"(c[1]), "+f"(c[2]), "+f"(c[3])
        : "r"(a[0]), "r"(a[1]), "r"(a[2]), "r"(a[3]), "r"(b[0]), "r"(b[1]));
}

__device__ __forceinline__ float ex2(float x) {
    float y;
    asm("ex2.approx.f32 %0, %1;" : "=f"(y) : "f"(x));
    return y;
}

// ---------------------------------------------------------------------------
// Device scratch (no cudaMalloc allowed)
// ---------------------------------------------------------------------------
__device__ __half g_xh[(size_t)MROWS * EMB];       // x fp16
__device__ __half g_qkv[(size_t)MROWS * QKVW];     // fused q|k|v fp16
__device__ __half g_oh[(size_t)MROWS * EMB];       // attn out fp16
__device__ __half g_wc[(size_t)QKVW * EMB];        // concat Wq|Wk|Wv ^T fp16
__device__ __half g_wo[(size_t)EMB * EMB];         // Wo^T fp16
__device__ float  g_bias[QKVW];                    // concat bq|bk|bv

// ---------------------------------------------------------------------------
// fp32 -> fp16 convert (elementwise)
// ---------------------------------------------------------------------------
__global__ __launch_bounds__(256) void to_half_kernel(
    const float* __restrict__ x, __half* __restrict__ y, int n)
{
    int i = (blockIdx.x * 256 + threadIdx.x) * 4;
    if (i >= n) return;
    float4 v = *(const float4*)(x + i);
    __half2 h0 = __floats2half2_rn(v.x, v.y);
    __half2 h1 = __floats2half2_rn(v.z, v.w);
    uint2 o = make_uint2(*(uint32_t*)&h0, *(uint32_t*)&h1);
    *(uint2*)(y + i) = o;
}

// ---------------------------------------------------------------------------
// Merged transpose of Wq|Wk|Wv into the concat fp16 buffer [QKVW, EMB]
// ---------------------------------------------------------------------------
__global__ __launch_bounds__(256) void transpose_qkv_kernel(
    const float* __restrict__ Wq, const float* __restrict__ Wk,
    const float* __restrict__ Wv, __half* __restrict__ T)
{
    __shared__ float tile[32][33];
    const int tx = threadIdx.x, ty = threadIdx.y;
    const int nBase = blockIdx.x * 32;   // 0..QKVW-32
    const int kBase = blockIdx.y * 32;   // 0..EMB-32

    const float* W;
    int srcN, ln;
    if (nBase < EMB)            { W = Wq; srcN = EMB; ln = nBase; }
    else if (nBase < EMB + KVW) { W = Wk; srcN = KVW; ln = nBase - EMB; }
    else                        { W = Wv; srcN = KVW; ln = nBase - EMB - KVW; }

#pragma unroll
    for (int i = 0; i < 4; i++)
        tile[ty + 8 * i][tx] = W[(size_t)(kBase + ty + 8 * i) * srcN + ln + tx];
    __syncthreads();
#pragma unroll
    for (int i = 0; i < 4; i++) {
        float v = tile[tx][ty + 8 * i];
        T[(size_t)(nBase + ty + 8 * i) * EMB + kBase + tx] = __float2half(v);
    }
}

// ---------------------------------------------------------------------------
// Transpose: W [K,N] fp32 -> T [N,K] fp16
// ---------------------------------------------------------------------------
__global__ __launch_bounds__(256) void transpose_half_kernel(
    const float* __restrict__ W, __half* __restrict__ T, int K, int N)
{
    __shared__ float tile[32][33];
    const int tx = threadIdx.x, ty = threadIdx.y;
    const int nBase = blockIdx.x * 32, kBase = blockIdx.y * 32;
#pragma unroll
    for (int i = 0; i < 4; i++)
        tile[ty + 8 * i][tx] = W[(size_t)(kBase + ty + 8 * i) * N + nBase + tx];
    __syncthreads();
#pragma unroll
    for (int i = 0; i < 4; i++) {
        float v = tile[tx][ty + 8 * i];
        T[(size_t)(nBase + ty + 8 * i) * K + kBase + tx] = __float2half(v);
    }
}

// ---------------------------------------------------------------------------
// Unified single-product fp16 GEMM. 3 smem buffers, 2 loads in flight,
// ONE __syncthreads per iteration (chunk ci+2 overwrites the buffer retired
// at iteration ci-1; the barrier proves all warps left it).
// OMODE 0: fp16 out, +bias, per-column qscale (QKV projection).
// OMODE 1: fp32 out, no bias (output projection).
// ---------------------------------------------------------------------------
#define GH_STAGE_BYTES 32768                 // A 16KB + B 16KB
#define GH_SMEM_BYTES  (3 * GH_STAGE_BYTES)  // 98304; x2 CTAs = 192KB

template <int OMODE>
__global__ __launch_bounds__(256, 2) void gemm_f16_kernel(
    const __half* __restrict__ A, const __half* __restrict__ B,
    const float* __restrict__ bias, __half* __restrict__ Ch,
    float* __restrict__ Cf, float qsc, int qcols, int M, int N, int K)
{
    extern __shared__ char gsm[];
    const uint32_t sb = smem_u32(gsm);

    const int tid   = threadIdx.x;
    const int wid   = tid >> 5;
    const int lane  = tid & 31;
    const int warpM = wid & 1;
    const int warpN = wid >> 1;
    const int mBase = blockIdx.y * 128;
    const int nBase = blockIdx.x * 128;
    const int nCh   = K >> 6;

    const int aRowOff = lane & 15;
    const int aKOff   = (lane >> 4) << 4;
    const int bRowOff = (lane & 7) + ((lane >> 4) << 3);
    const int bKOff   = ((lane >> 3) & 1) << 4;

    auto swz = [](uint32_t off) { return off ^ ((off >> 3) & 0x70); };

    auto load_chunk = [&](int ci) {
        const int k0 = ci << 6;
        const uint32_t sbase = sb + (uint32_t)(ci % 3) * GH_STAGE_BYTES;
#pragma unroll
        for (int t = 0; t < 8; t++) {
            int idx = tid + t * 256;
            int ab  = idx >> 10;
            int row = (idx >> 3) & 127;
            int gr  = idx & 7;
            uint32_t off = (uint32_t)(row * 128 + gr * 16);
            uint32_t sw  = off ^ ((off >> 3) & 0x70);
            if (ab == 0)
                cp16(sbase + sw, A + (size_t)(mBase + row) * K + k0 + gr * 8);
            else
                cp16(sbase + 16384 + sw,
                     B + (size_t)(nBase + row) * K + k0 + gr * 8);
        }
        asm volatile("cp.async.commit_group;" ::: "memory");
    };

    float acc[4][4][4];
#pragma unroll
    for (int mt = 0; mt < 4; mt++)
#pragma unroll
        for (int nt = 0; nt < 4; nt++)
#pragma unroll
            for (int i = 0; i < 4; i++) acc[mt][nt][i] = 0.f;

    load_chunk(0);
    load_chunk(1);

    for (int ci = 0; ci < nCh; ci++) {
        // chunk ci done; at most the one newer group (ci+1) may stay pending
        if (ci + 1 < nCh)
            asm volatile("cp.async.wait_group 1;" ::: "memory");
        else
            asm volatile("cp.async.wait_group 0;" ::: "memory");
        __syncthreads();   // ALSO retires reads of buf (ci+2)%3 from iter ci-1

        if (ci + 2 < nCh) load_chunk(ci + 2);

        const uint32_t sbase = sb + (uint32_t)(ci % 3) * GH_STAGE_BYTES;
        const uint32_t aB = sbase;
        const uint32_t bB = sbase + 16384;

#pragma unroll
        for (int ks = 0; ks < 4; ks++) {
            const int kByte = ks * 32;
            uint32_t af[4][4];
#pragma unroll
            for (int mt = 0; mt < 4; mt++) {
                uint32_t off = (uint32_t)((warpM * 64 + mt * 16 + aRowOff) * 128
                                          + kByte + aKOff);
                ldmx4(af[mt], aB + swz(off));
            }
            uint32_t bf[2][4];
#pragma unroll
            for (int p = 0; p < 2; p++) {
                uint32_t off = (uint32_t)((warpN * 32 + p * 16 + bRowOff) * 128
                                          + kByte + bKOff);
                ldmx4(bf[p], bB + swz(off));
            }
#pragma unroll
            for (int mt = 0; mt < 4; mt++)
#pragma unroll
                for (int nt = 0; nt < 4; nt++)
                    mma16816h(acc[mt][nt], af[mt], &bf[nt >> 1][(nt & 1) * 2]);
        }
        // no trailing sync — next iteration's barrier covers it
    }

    const int mW = mBase + warpM * 64;
    const int nW = nBase + warpN * 32;
#pragma unroll
    for (int mt = 0; mt < 4; mt++) {
#pragma unroll
        for (int nt = 0; nt < 4; nt++) {
            int r0 = mW + mt * 16 + (lane >> 2);
            int c  = nW + nt * 8 + (lane & 3) * 2;
            if (OMODE == 0) {
                float2 bv = *(const float2*)(bias + c);
                float sc = (c < qcols) ? qsc : 1.f;
                float v0 = (acc[mt][nt][0] + bv.x) * sc;
                float v1 = (acc[mt][nt][1] + bv.y) * sc;
                float v2 = (acc[mt][nt][2] + bv.x) * sc;
                float v3 = (acc[mt][nt][3] + bv.y) * sc;
                __half2 h01 = __floats2half2_rn(v0, v1);
                __half2 h23 = __floats2half2_rn(v2, v3);
                *(uint32_t*)(Ch + (size_t)r0 * N + c)       = *(uint32_t*)&h01;
                *(uint32_t*)(Ch + (size_t)(r0 + 8) * N + c) = *(uint32_t*)&h23;
            } else {
                *(float2*)(Cf + (size_t)r0 * N + c) =
                    make_float2(acc[mt][nt][0], acc[mt][nt][1]);
                *(float2*)(Cf + (size_t)(r0 + 8) * N + c) =
                    make_float2(acc[mt][nt][2], acc[mt][nt][3]);
            }
        }
    }
}

// ---------------------------------------------------------------------------
// Flash attention, fp16 single-product mma (byte-identical to R12).
// BM=64, 128 threads (4 warps), 3 CTAs/SM. 2-stage K/V pipeline; Q parked
// at sb, aliased by stage 1 after the register hoist. log2-domain softmax.
// ---------------------------------------------------------------------------
#define FA_SMEM_BYTES (2 * 32768)   // 65536; 3 CTAs/SM -> 192KB

__global__ __launch_bounds__(128, 3) void flash_mma_kernel(
    const __half* __restrict__ qkv, __half* __restrict__ oh)
{
    extern __shared__ char fsm[];
    const uint32_t sb  = smem_u32(fsm);
    const int tid  = threadIdx.x;
    const int wid  = tid >> 5;        // 0..3
    const int lane = tid & 31;
    const int q0 = blockIdx.x * 64;
    const int h  = blockIdx.y;
    const int b  = blockIdx.z;
    const int g  = h >> 2;

    const size_t qrow0 = (size_t)b * SEQ + q0;
    const int qcol = h * HD;
    const int kcol = EMB + g * HD;
    const int vcol = EMB + KVW + g * HD;

#pragma unroll
    for (int t = 0; t < 8; t++) {
        int idx = tid + t * 128;
        int row = idx >> 4;
        int gr  = idx & 15;
        int blk = gr >> 3;
        uint32_t off = (uint32_t)(row * 128 + (gr & 7) * 16);
        uint32_t sw  = off ^ ((off >> 3) & 0x70);
        size_t go = (qrow0 + row) * QKVW + qcol + gr * 8;
        cp16(sb + blk * 8192 + sw, qkv + go);
    }
    asm volatile("cp.async.commit_group;" ::: "memory");

    auto stage_base = [&](int s) -> uint32_t {
        return sb + (uint32_t)(((s + 1) & 1) * 32768);
    };

    auto load_stage = [&](int ci) {
        const uint32_t s0 = stage_base(ci);
        const int kr0 = ci * 64;
#pragma unroll
        for (int t = 0; t < 16; t++) {
            int arr = t >> 3;
            int idx = tid + (t & 7) * 128;
            int row = idx >> 4;
            int gr  = idx & 15;
            int blk = gr >> 3;
            uint32_t off = (uint32_t)(row * 128 + (gr & 7) * 16);
            uint32_t sw  = off ^ ((off >> 3) & 0x70);
            uint32_t dst = s0 + (uint32_t)arr * 16384u + (uint32_t)blk * 8192u + sw;
            int col = (arr == 0) ? kcol : vcol;
            size_t go = (size_t)(b * SEQ + kr0 + row) * QKVW + col + gr * 8;
            cp16(dst, qkv + go);
        }
        asm volatile("cp.async.commit_group;" ::: "memory");
    };

    load_stage(0);

    const int gid = lane >> 2, tig = lane & 3;
    const int qrw = wid * 16;

    const int aRow = lane & 15;
    const int aCol = (lane >> 4) << 4;
    const int bRow = (lane & 7) + ((lane >> 4) << 3);
    const int bCol = ((lane >> 3) & 1) << 4;
    const int vRow = (lane & 7) + (((lane >> 3) & 1) << 3);
    const int vCol = (lane >> 4) << 4;

    asm volatile("cp.async.wait_group 1;" ::: "memory");
    __syncthreads();
    uint32_t qreg[8][4];
#pragma unroll
    for (int ks = 0; ks < 8; ks++) {
        const int blk = ks >> 2;
        const int kb  = (ks & 3) * 32;
        uint32_t offq = (uint32_t)((qrw + aRow) * 128 + kb + aCol);
        uint32_t swq  = offq ^ ((offq >> 3) & 0x70);
        ldmx4(qreg[ks], sb + blk * 8192 + swq);
    }
    __syncthreads();
    load_stage(1);

    float m0 = -1e30f, m1 = -1e30f, l0 = 0.f, l1 = 0.f;
    float o[16][4];
#pragma unroll
    for (int t = 0; t < 16; t++)
#pragma unroll
        for (int i = 0; i < 4; i++) o[t][i] = 0.f;

    const int NIT = SEQ / 64;
    for (int ci = 0; ci < NIT; ci++) {
        if (ci + 1 < NIT)
            asm volatile("cp.async.wait_group 1;" ::: "memory");
        else
            asm volatile("cp.async.wait_group 0;" ::: "memory");
        __syncthreads();

        const uint32_t s0 = stage_base(ci);
        const uint32_t KB = s0, VB = s0 + 16384;

        float s[8][4];
#pragma unroll
        for (int t = 0; t < 8; t++)
#pragma unroll
            for (int i = 0; i < 4; i++) s[t][i] = 0.f;

#pragma unroll
        for (int ks = 0; ks < 8; ks++) {
            const int blk = ks >> 2;
            const int kb  = (ks & 3) * 32;
#pragma unroll
            for (int nb = 0; nb < 4; nb++) {
                uint32_t kf[4];
                uint32_t offk = (uint32_t)((nb * 16 + bRow) * 128 + kb + bCol);
                uint32_t swk  = offk ^ ((offk >> 3) & 0x70);
                ldmx4(kf, KB + blk * 8192 + swk);
                mma16816h(s[2 * nb],     qreg[ks], &kf[0]);
                mma16816h(s[2 * nb + 1], qreg[ks], &kf[2]);
            }
        }

        float mx0 = -1e30f, mx1 = -1e30f;
#pragma unroll
        for (int t = 0; t < 8; t++) {
            mx0 = fmaxf(mx0, fmaxf(s[t][0], s[t][1]));
            mx1 = fmaxf(mx1, fmaxf(s[t][2], s[t][3]));
        }
        mx0 = fmaxf(mx0, __shfl_xor_sync(0xffffffffu, mx0, 1));
        mx0 = fmaxf(mx0, __shfl_xor_sync(0xffffffffu, mx0, 2));
        mx1 = fmaxf(mx1, __shfl_xor_sync(0xffffffffu, mx1, 1));
        mx1 = fmaxf(mx1, __shfl_xor_sync(0xffffffffu, mx1, 2));

        float mn0 = fmaxf(m0, mx0), mn1 = fmaxf(m1, mx1);
        float a0 = ex2(m0 - mn0), a1 = ex2(m1 - mn1);
        m0 = mn0; m1 = mn1;

        float rs0 = 0.f, rs1 = 0.f;
        uint32_t pa[4][4];
#pragma unroll
        for (int t = 0; t < 8; t++) {
            __half2 h01 = h2exp2(__floats2half2_rn(s[t][0] - mn0, s[t][1] - mn0));
            __half2 h23 = h2exp2(__floats2half2_rn(s[t][2] - mn1, s[t][3] - mn1));
            float2 f01 = __half22float2(h01);
            float2 f23 = __half22float2(h23);
            rs0 += f01.x + f01.y;
            rs1 += f23.x + f23.y;
            int j = t >> 1, sl = (t & 1) * 2;
            pa[j][sl]     = *(uint32_t*)&h01;
            pa[j][sl + 1] = *(uint32_t*)&h23;
        }
        rs0 += __shfl_xor_sync(0xffffffffu, rs0, 1);
        rs0 += __shfl_xor_sync(0xffffffffu, rs0, 2);
        rs1 += __shfl_xor_sync(0xffffffffu, rs1, 1);
        rs1 += __shfl_xor_sync(0xffffffffu, rs1, 2);
        l0 = l0 * a0 + rs0;
        l1 = l1 * a1 + rs1;

        if (a0 != 1.f || a1 != 1.f) {
#pragma unroll
            for (int t = 0; t < 16; t++) {
                o[t][0] *= a0; o[t][1] *= a0;
                o[t][2] *= a1; o[t][3] *= a1;
            }
        }

#pragma unroll
        for (int j = 0; j < 4; j++) {
#pragma unroll
            for (int tp = 0; tp < 8; tp++) {
                const int blk = tp >> 2;
                const int cb  = (tp & 3) * 32 + vCol;
                uint32_t offv = (uint32_t)((j * 16 + vRow) * 128 + cb);
                uint32_t swv  = offv ^ ((offv >> 3) & 0x70);
                uint32_t vf[4];
                ldmx4t(vf, VB + blk * 8192 + swv);
                mma16816h(o[2 * tp],     pa[j], &vf[0]);
                mma16816h(o[2 * tp + 1], pa[j], &vf[2]);
            }
        }

        __syncthreads();
        if (ci + 2 < NIT) load_stage(ci + 2);
    }

    float i0 = 1.0f / l0, i1 = 1.0f / l1;
    size_t r0 = (qrow0 + qrw + gid) * EMB + (size_t)h * HD;
    size_t r1 = (qrow0 + qrw + gid + 8) * EMB + (size_t)h * HD;
#pragma unroll
    for (int t = 0; t < 16; t++) {
        int c = t * 8 + tig * 2;
        __half2 ha = __floats2half2_rn(o[t][0] * i0, o[t][1] * i0);
        __half2 hb = __floats2half2_rn(o[t][2] * i1, o[t][3] * i1);
        *(uint32_t*)(oh + r0 + c) = *(uint32_t*)&ha;
        *(uint32_t*)(oh + r1 + c) = *(uint32_t*)&hb;
    }
}

// ---------------------------------------------------------------------------
// kernel_launch
// ---------------------------------------------------------------------------
extern "C" void kernel_launch(void* const* d_in, const int* in_sizes, int n_in,
                              void* d_out, int out_size)
{
    const float* x  = (const float*)d_in[0];
    const float* Wq = (const float*)d_in[1];
    const float* bq = (const float*)d_in[2];
    const float* Wk = (const float*)d_in[3];
    const float* bk = (const float*)d_in[4];
    const float* Wv = (const float*)d_in[5];
    const float* bv = (const float*)d_in[6];
    const float* Wo = (const float*)d_in[7];
    float* out = (float*)d_out;

    __half *pxh, *pqkv, *pwc, *poh, *pwo;
    float* pbias;
    cudaGetSymbolAddress((void**)&pxh,  g_xh);
    cudaGetSymbolAddress((void**)&pqkv, g_qkv);
    cudaGetSymbolAddress((void**)&pwc,  g_wc);
    cudaGetSymbolAddress((void**)&poh,  g_oh);
    cudaGetSymbolAddress((void**)&pwo,  g_wo);
    cudaGetSymbolAddress((void**)&pbias, g_bias);

    cudaFuncSetAttribute(gemm_f16_kernel<0>,
                         cudaFuncAttributeMaxDynamicSharedMemorySize, GH_SMEM_BYTES);
    cudaFuncSetAttribute(gemm_f16_kernel<1>,
                         cudaFuncAttributeMaxDynamicSharedMemorySize, GH_SMEM_BYTES);
    cudaFuncSetAttribute(flash_mma_kernel,
                         cudaFuncAttributeMaxDynamicSharedMemorySize, FA_SMEM_BYTES);

    const int nx = MROWS * EMB;
    // q pre-scale: log2(e) / sqrt(HD)  (softmax runs in log2 domain)
    const float qscale = 0.088388347648318447f * 1.4426950408889634f;

    // 1) x -> fp16
    to_half_kernel<<<nx / (4 * 256), 256>>>(x, pxh, nx);

    // 2) weights: QKV concat transpose (one launch); Wo -> fp16
    dim3 tb(32, 8);
    transpose_qkv_kernel<<<dim3(QKVW / 32, EMB / 32), tb>>>(Wq, Wk, Wv, pwc);
    transpose_half_kernel<<<dim3(EMB / 32, EMB / 32), tb>>>(Wo, pwo, EMB, EMB);
    cudaMemcpyAsync(pbias,             bq, EMB * sizeof(float), cudaMemcpyDeviceToDevice);
    cudaMemcpyAsync(pbias + EMB,       bk, KVW * sizeof(float), cudaMemcpyDeviceToDevice);
    cudaMemcpyAsync(pbias + EMB + KVW, bv, KVW * sizeof(float), cudaMemcpyDeviceToDevice);

    // 3) fused QKV projection, single-product fp16 (Q cols pre-scaled)
    gemm_f16_kernel<0><<<dim3(QKVW / 128, MROWS / 128), 256, GH_SMEM_BYTES>>>(
        pxh, pwc, pbias, pqkv, nullptr, qscale, EMB, MROWS, QKVW, EMB);

    // 4) flash attention (fp16, BM=64, 3 CTAs/SM) -> single fp16 output
    flash_mma_kernel<<<dim3(SEQ / 64, HQ, BATCH), 128, FA_SMEM_BYTES>>>(
        pqkv, poh);

    // 5) output projection: single-product fp16 -> fp32
    gemm_f16_kernel<1><<<dim3(EMB / 128, MROWS / 128), 256, GH_SMEM_BYTES>>>(
        poh, pwo, (const float*)nullptr, nullptr, out, 1.0f, 0,
        MROWS, EMB, EMB);
}

// round 14
// speedup vs baseline: 11.1611x; 1.0323x over previous
#include <cuda_runtime.h>
#include <cuda_bf16.h>
#include <cuda_fp16.h>
#include <cstdint>

#define BATCH 2
#define SEQ   2048
#define EMB   2048
#define HQ    16
#define HKV   4
#define HD    128
#define KVW   (HKV * HD)        // 512
#define MROWS (BATCH * SEQ)     // 4096
#define QKVW  (EMB + 2 * KVW)   // 3072

// ---------------------------------------------------------------------------
// PTX helpers — ONLY non-arch-suffixed instructions (compute_103-safe)
// ---------------------------------------------------------------------------
__device__ __forceinline__ uint32_t smem_u32(const void* p) {
    uint32_t a;
    asm("{ .reg .u64 t; cvta.to.shared.u64 t, %1; cvt.u32.u64 %0, t; }"
        : "=r"(a) : "l"(p));
    return a;
}

__device__ __forceinline__ void cp16(uint32_t saddr, const void* gaddr) {
    asm volatile("cp.async.cg.shared.global [%0], [%1], 16;"
                 :: "r"(saddr), "l"(gaddr));
}

__device__ __forceinline__ void ldmx4(uint32_t* r, uint32_t addr) {
    asm volatile("ldmatrix.sync.aligned.m8n8.x4.shared.b16 {%0,%1,%2,%3}, [%4];"
                 : "=r"(r[0]), "=r"(r[1]), "=r"(r[2]), "=r"(r[3]) : "r"(addr));
}

__device__ __forceinline__ void ldmx4t(uint32_t* r, uint32_t addr) {
    asm volatile("ldmatrix.sync.aligned.m8n8.x4.trans.shared.b16 {%0,%1,%2,%3}, [%4];"
                 : "=r"(r[0]), "=r"(r[1]), "=r"(r[2]), "=r"(r[3]) : "r"(addr));
}

// fp16 mma
__device__ __forceinline__ void mma16816h(float* c, const uint32_t* a,
                                          const uint32_t* b) {
    asm volatile(
        "mma.sync.aligned.m16n8k16.row.col.f32.f16.f16.f32 "
        "{%0,%1,%2,%3}, {%4,%5,%6,%7}, {%8,%9}, {%0,%1,%2,%3};"
        : "+f"(c[0]), "+f"(c[1]), "+f"(c[2]), "+f"(c[3])
        : "r"(a[0]), "r"(a[1]), "r"(a[2]), "r"(a[3]), "r"(b[0]), "r"(b[1]));
}

__device__ __forceinline__ float ex2(float x) {
    float y;
    asm("ex2.approx.f32 %0, %1;" : "=f"(y) : "f"(x));
    return y;
}

// ---------------------------------------------------------------------------
// Device scratch (no cudaMalloc allowed)
// ---------------------------------------------------------------------------
__device__ __half g_xh[(size_t)MROWS * EMB];       // x fp16
__device__ __half g_qkv[(size_t)MROWS * QKVW];     // fused q|k|v fp16
__device__ __half g_oh[(size_t)MROWS * EMB];       // attn out fp16
__device__ __half g_wc[(size_t)QKVW * EMB];        // concat Wq|Wk|Wv ^T fp16
__device__ __half g_wo[(size_t)EMB * EMB];         // Wo^T fp16
__device__ float  g_bias[QKVW];                    // concat bq|bk|bv

// ---------------------------------------------------------------------------
// fp32 -> fp16 convert (elementwise)
// ---------------------------------------------------------------------------
__global__ __launch_bounds__(256) void to_half_kernel(
    const float* __restrict__ x, __half* __restrict__ y, int n)
{
    int i = (blockIdx.x * 256 + threadIdx.x) * 4;
    if (i >= n) return;
    float4 v = *(const float4*)(x + i);
    __half2 h0 = __floats2half2_rn(v.x, v.y);
    __half2 h1 = __floats2half2_rn(v.z, v.w);
    uint2 o = make_uint2(*(uint32_t*)&h0, *(uint32_t*)&h1);
    *(uint2*)(y + i) = o;
}

// ---------------------------------------------------------------------------
// Merged transpose of Wq|Wk|Wv into the concat fp16 buffer [QKVW, EMB],
// with the bias concat fused in (blocks at kBase==0 copy 32 bias values).
// ---------------------------------------------------------------------------
__global__ __launch_bounds__(256) void transpose_qkv_kernel(
    const float* __restrict__ Wq, const float* __restrict__ Wk,
    const float* __restrict__ Wv, __half* __restrict__ T,
    const float* __restrict__ bq, const float* __restrict__ bk,
    const float* __restrict__ bv, float* __restrict__ biasOut)
{
    __shared__ float tile[32][33];
    const int tx = threadIdx.x, ty = threadIdx.y;
    const int nBase = blockIdx.x * 32;   // 0..QKVW-32
    const int kBase = blockIdx.y * 32;   // 0..EMB-32

    const float* W;
    const float* bsrc;
    int srcN, ln;
    if (nBase < EMB)            { W = Wq; bsrc = bq; srcN = EMB; ln = nBase; }
    else if (nBase < EMB + KVW) { W = Wk; bsrc = bk; srcN = KVW; ln = nBase - EMB; }
    else                        { W = Wv; bsrc = bv; srcN = KVW; ln = nBase - EMB - KVW; }

    if (kBase == 0 && ty == 0)
        biasOut[nBase + tx] = bsrc[ln + tx];

#pragma unroll
    for (int i = 0; i < 4; i++)
        tile[ty + 8 * i][tx] = W[(size_t)(kBase + ty + 8 * i) * srcN + ln + tx];
    __syncthreads();
#pragma unroll
    for (int i = 0; i < 4; i++) {
        float v = tile[tx][ty + 8 * i];
        T[(size_t)(nBase + ty + 8 * i) * EMB + kBase + tx] = __float2half(v);
    }
}

// ---------------------------------------------------------------------------
// Transpose: W [K,N] fp32 -> T [N,K] fp16
// ---------------------------------------------------------------------------
__global__ __launch_bounds__(256) void transpose_half_kernel(
    const float* __restrict__ W, __half* __restrict__ T, int K, int N)
{
    __shared__ float tile[32][33];
    const int tx = threadIdx.x, ty = threadIdx.y;
    const int nBase = blockIdx.x * 32, kBase = blockIdx.y * 32;
#pragma unroll
    for (int i = 0; i < 4; i++)
        tile[ty + 8 * i][tx] = W[(size_t)(kBase + ty + 8 * i) * N + nBase + tx];
    __syncthreads();
#pragma unroll
    for (int i = 0; i < 4; i++) {
        float v = tile[tx][ty + 8 * i];
        T[(size_t)(nBase + ty + 8 * i) * K + kBase + tx] = __float2half(v);
    }
}

// ---------------------------------------------------------------------------
// Unified single-product fp16 GEMM, 3 CTAs/SM version:
// CTA tile 128x64, 256 threads, 8 warps (4M x 2N), warp tile 32x32.
// Stage = A 16KB + B 8KB = 24KB; 3 stages (72KB), single barrier per iter.
// OMODE 0: fp16 out, +bias, per-column qscale. OMODE 1: fp32 out, no bias.
// ---------------------------------------------------------------------------
#define G2_STAGE_BYTES 24576                 // A 16KB + B 8KB
#define G2_SMEM_BYTES  (3 * G2_STAGE_BYTES)  // 73728; x3 CTAs = 221184 <= 227KB

template <int OMODE>
__global__ __launch_bounds__(256, 3) void gemm_f16_kernel(
    const __half* __restrict__ A, const __half* __restrict__ B,
    const float* __restrict__ bias, __half* __restrict__ Ch,
    float* __restrict__ Cf, float qsc, int qcols, int M, int N, int K)
{
    extern __shared__ char gsm[];
    const uint32_t sb = smem_u32(gsm);

    const int tid   = threadIdx.x;
    const int wid   = tid >> 5;
    const int lane  = tid & 31;
    const int warpM = wid & 3;          // 0..3 -> 32 rows each
    const int warpN = wid >> 2;         // 0..1 -> 32 cols each
    const int mBase = blockIdx.y * 128;
    const int nBase = blockIdx.x * 64;
    const int nCh   = K >> 6;

    const int aRowOff = lane & 15;
    const int aKOff   = (lane >> 4) << 4;
    const int bRowOff = (lane & 7) + ((lane >> 4) << 3);
    const int bKOff   = ((lane >> 3) & 1) << 4;

    auto swz = [](uint32_t off) { return off ^ ((off >> 3) & 0x70); };

    auto load_chunk = [&](int ci) {
        const int k0 = ci << 6;
        const uint32_t sbase = sb + (uint32_t)(ci % 3) * G2_STAGE_BYTES;
#pragma unroll
        for (int t = 0; t < 6; t++) {
            int idx = tid + t * 256;            // 0..1535
            if (idx < 1024) {                   // A: 128 rows x 8 granules
                int row = idx >> 3;
                int gr  = idx & 7;
                uint32_t off = (uint32_t)(row * 128 + gr * 16);
                uint32_t sw  = off ^ ((off >> 3) & 0x70);
                cp16(sbase + sw, A + (size_t)(mBase + row) * K + k0 + gr * 8);
            } else {                            // B: 64 rows x 8 granules
                int idx2 = idx - 1024;
                int row  = idx2 >> 3;
                int gr   = idx2 & 7;
                uint32_t off = (uint32_t)(row * 128 + gr * 16);
                uint32_t sw  = off ^ ((off >> 3) & 0x70);
                cp16(sbase + 16384 + sw,
                     B + (size_t)(nBase + row) * K + k0 + gr * 8);
            }
        }
        asm volatile("cp.async.commit_group;" ::: "memory");
    };

    float acc[2][4][4];
#pragma unroll
    for (int mt = 0; mt < 2; mt++)
#pragma unroll
        for (int nt = 0; nt < 4; nt++)
#pragma unroll
            for (int i = 0; i < 4; i++) acc[mt][nt][i] = 0.f;

    load_chunk(0);
    load_chunk(1);

    for (int ci = 0; ci < nCh; ci++) {
        if (ci + 1 < nCh)
            asm volatile("cp.async.wait_group 1;" ::: "memory");
        else
            asm volatile("cp.async.wait_group 0;" ::: "memory");
        __syncthreads();   // also retires reads of buf (ci+2)%3 from iter ci-1

        if (ci + 2 < nCh) load_chunk(ci + 2);

        const uint32_t sbase = sb + (uint32_t)(ci % 3) * G2_STAGE_BYTES;
        const uint32_t aB = sbase;
        const uint32_t bB = sbase + 16384;

#pragma unroll
        for (int ks = 0; ks < 4; ks++) {
            const int kByte = ks * 32;
            uint32_t af[2][4];
#pragma unroll
            for (int mt = 0; mt < 2; mt++) {
                uint32_t off = (uint32_t)((warpM * 32 + mt * 16 + aRowOff) * 128
                                          + kByte + aKOff);
                ldmx4(af[mt], aB + swz(off));
            }
            uint32_t bf[2][4];
#pragma unroll
            for (int p = 0; p < 2; p++) {
                uint32_t off = (uint32_t)((warpN * 32 + p * 16 + bRowOff) * 128
                                          + kByte + bKOff);
                ldmx4(bf[p], bB + swz(off));
            }
#pragma unroll
            for (int mt = 0; mt < 2; mt++)
#pragma unroll
                for (int nt = 0; nt < 4; nt++)
                    mma16816h(acc[mt][nt], af[mt], &bf[nt >> 1][(nt & 1) * 2]);
        }
        // no trailing sync — next iteration's barrier covers it
    }

    const int mW = mBase + warpM * 32;
    const int nW = nBase + warpN * 32;
#pragma unroll
    for (int mt = 0; mt < 2; mt++) {
#pragma unroll
        for (int nt = 0; nt < 4; nt++) {
            int r0 = mW + mt * 16 + (lane >> 2);
            int c  = nW + nt * 8 + (lane & 3) * 2;
            if (OMODE == 0) {
                float2 bv = *(const float2*)(bias + c);
                float sc = (c < qcols) ? qsc : 1.f;
                float v0 = (acc[mt][nt][0] + bv.x) * sc;
                float v1 = (acc[mt][nt][1] + bv.y) * sc;
                float v2 = (acc[mt][nt][2] + bv.x) * sc;
                float v3 = (acc[mt][nt][3] + bv.y) * sc;
                __half2 h01 = __floats2half2_rn(v0, v1);
                __half2 h23 = __floats2half2_rn(v2, v3);
                *(uint32_t*)(Ch + (size_t)r0 * N + c)       = *(uint32_t*)&h01;
                *(uint32_t*)(Ch + (size_t)(r0 + 8) * N + c) = *(uint32_t*)&h23;
            } else {
                *(float2*)(Cf + (size_t)r0 * N + c) =
                    make_float2(acc[mt][nt][0], acc[mt][nt][1]);
                *(float2*)(Cf + (size_t)(r0 + 8) * N + c) =
                    make_float2(acc[mt][nt][2], acc[mt][nt][3]);
            }
        }
    }
}

// ---------------------------------------------------------------------------
// Flash attention, fp16 single-product mma (byte-identical to R13).
// BM=64, 128 threads (4 warps), 3 CTAs/SM. 2-stage K/V pipeline; Q parked
// at sb, aliased by stage 1 after the register hoist. log2-domain softmax.
// ---------------------------------------------------------------------------
#define FA_SMEM_BYTES (2 * 32768)   // 65536; 3 CTAs/SM -> 192KB

__global__ __launch_bounds__(128, 3) void flash_mma_kernel(
    const __half* __restrict__ qkv, __half* __restrict__ oh)
{
    extern __shared__ char fsm[];
    const uint32_t sb  = smem_u32(fsm);
    const int tid  = threadIdx.x;
    const int wid  = tid >> 5;        // 0..3
    const int lane = tid & 31;
    const int q0 = blockIdx.x * 64;
    const int h  = blockIdx.y;
    const int b  = blockIdx.z;
    const int g  = h >> 2;

    const size_t qrow0 = (size_t)b * SEQ + q0;
    const int qcol = h * HD;
    const int kcol = EMB + g * HD;
    const int vcol = EMB + KVW + g * HD;

#pragma unroll
    for (int t = 0; t < 8; t++) {
        int idx = tid + t * 128;
        int row = idx >> 4;
        int gr  = idx & 15;
        int blk = gr >> 3;
        uint32_t off = (uint32_t)(row * 128 + (gr & 7) * 16);
        uint32_t sw  = off ^ ((off >> 3) & 0x70);
        size_t go = (qrow0 + row) * QKVW + qcol + gr * 8;
        cp16(sb + blk * 8192 + sw, qkv + go);
    }
    asm volatile("cp.async.commit_group;" ::: "memory");

    auto stage_base = [&](int s) -> uint32_t {
        return sb + (uint32_t)(((s + 1) & 1) * 32768);
    };

    auto load_stage = [&](int ci) {
        const uint32_t s0 = stage_base(ci);
        const int kr0 = ci * 64;
#pragma unroll
        for (int t = 0; t < 16; t++) {
            int arr = t >> 3;
            int idx = tid + (t & 7) * 128;
            int row = idx >> 4;
            int gr  = idx & 15;
            int blk = gr >> 3;
            uint32_t off = (uint32_t)(row * 128 + (gr & 7) * 16);
            uint32_t sw  = off ^ ((off >> 3) & 0x70);
            uint32_t dst = s0 + (uint32_t)arr * 16384u + (uint32_t)blk * 8192u + sw;
            int col = (arr == 0) ? kcol : vcol;
            size_t go = (size_t)(b * SEQ + kr0 + row) * QKVW + col + gr * 8;
            cp16(dst, qkv + go);
        }
        asm volatile("cp.async.commit_group;" ::: "memory");
    };

    load_stage(0);

    const int gid = lane >> 2, tig = lane & 3;
    const int qrw = wid * 16;

    const int aRow = lane & 15;
    const int aCol = (lane >> 4) << 4;
    const int bRow = (lane & 7) + ((lane >> 4) << 3);
    const int bCol = ((lane >> 3) & 1) << 4;
    const int vRow = (lane & 7) + (((lane >> 3) & 1) << 3);
    const int vCol = (lane >> 4) << 4;

    asm volatile("cp.async.wait_group 1;" ::: "memory");
    __syncthreads();
    uint32_t qreg[8][4];
#pragma unroll
    for (int ks = 0; ks < 8; ks++) {
        const int blk = ks >> 2;
        const int kb  = (ks & 3) * 32;
        uint32_t offq = (uint32_t)((qrw + aRow) * 128 + kb + aCol);
        uint32_t swq  = offq ^ ((offq >> 3) & 0x70);
        ldmx4(qreg[ks], sb + blk * 8192 + swq);
    }
    __syncthreads();
    load_stage(1);

    float m0 = -1e30f, m1 = -1e30f, l0 = 0.f, l1 = 0.f;
    float o[16][4];
#pragma unroll
    for (int t = 0; t < 16; t++)
#pragma unroll
        for (int i = 0; i < 4; i++) o[t][i] = 0.f;

    const int NIT = SEQ / 64;
    for (int ci = 0; ci < NIT; ci++) {
        if (ci + 1 < NIT)
            asm volatile("cp.async.wait_group 1;" ::: "memory");
        else
            asm volatile("cp.async.wait_group 0;" ::: "memory");
        __syncthreads();

        const uint32_t s0 = stage_base(ci);
        const uint32_t KB = s0, VB = s0 + 16384;

        float s[8][4];
#pragma unroll
        for (int t = 0; t < 8; t++)
#pragma unroll
            for (int i = 0; i < 4; i++) s[t][i] = 0.f;

#pragma unroll
        for (int ks = 0; ks < 8; ks++) {
            const int blk = ks >> 2;
            const int kb  = (ks & 3) * 32;
#pragma unroll
            for (int nb = 0; nb < 4; nb++) {
                uint32_t kf[4];
                uint32_t offk = (uint32_t)((nb * 16 + bRow) * 128 + kb + bCol);
                uint32_t swk  = offk ^ ((offk >> 3) & 0x70);
                ldmx4(kf, KB + blk * 8192 + swk);
                mma16816h(s[2 * nb],     qreg[ks], &kf[0]);
                mma16816h(s[2 * nb + 1], qreg[ks], &kf[2]);
            }
        }

        float mx0 = -1e30f, mx1 = -1e30f;
#pragma unroll
        for (int t = 0; t < 8; t++) {
            mx0 = fmaxf(mx0, fmaxf(s[t][0], s[t][1]));
            mx1 = fmaxf(mx1, fmaxf(s[t][2], s[t][3]));
        }
        mx0 = fmaxf(mx0, __shfl_xor_sync(0xffffffffu, mx0, 1));
        mx0 = fmaxf(mx0, __shfl_xor_sync(0xffffffffu, mx0, 2));
        mx1 = fmaxf(mx1, __shfl_xor_sync(0xffffffffu, mx1, 1));
        mx1 = fmaxf(mx1, __shfl_xor_sync(0xffffffffu, mx1, 2));

        float mn0 = fmaxf(m0, mx0), mn1 = fmaxf(m1, mx1);
        float a0 = ex2(m0 - mn0), a1 = ex2(m1 - mn1);
        m0 = mn0; m1 = mn1;

        float rs0 = 0.f, rs1 = 0.f;
        uint32_t pa[4][4];
#pragma unroll
        for (int t = 0; t < 8; t++) {
            __half2 h01 = h2exp2(__floats2half2_rn(s[t][0] - mn0, s[t][1] - mn0));
            __half2 h23 = h2exp2(__floats2half2_rn(s[t][2] - mn1, s[t][3] - mn1));
            float2 f01 = __half22float2(h01);
            float2 f23 = __half22float2(h23);
            rs0 += f01.x + f01.y;
            rs1 += f23.x + f23.y;
            int j = t >> 1, sl = (t & 1) * 2;
            pa[j][sl]     = *(uint32_t*)&h01;
            pa[j][sl + 1] = *(uint32_t*)&h23;
        }
        rs0 += __shfl_xor_sync(0xffffffffu, rs0, 1);
        rs0 += __shfl_xor_sync(0xffffffffu, rs0, 2);
        rs1 += __shfl_xor_sync(0xffffffffu, rs1, 1);
        rs1 += __shfl_xor_sync(0xffffffffu, rs1, 2);
        l0 = l0 * a0 + rs0;
        l1 = l1 * a1 + rs1;

        if (a0 != 1.f || a1 != 1.f) {
#pragma unroll
            for (int t = 0; t < 16; t++) {
                o[t][0] *= a0; o[t][1] *= a0;
                o[t][2] *= a1; o[t][3] *= a1;
            }
        }

#pragma unroll
        for (int j = 0; j < 4; j++) {
#pragma unroll
            for (int tp = 0; tp < 8; tp++) {
                const int blk = tp >> 2;
                const int cb  = (tp & 3) * 32 + vCol;
                uint32_t offv = (uint32_t)((j * 16 + vRow) * 128 + cb);
                uint32_t swv  = offv ^ ((offv >> 3) & 0x70);
                uint32_t vf[4];
                ldmx4t(vf, VB + blk * 8192 + swv);
                mma16816h(o[2 * tp],     pa[j], &vf[0]);
                mma16816h(o[2 * tp + 1], pa[j], &vf[2]);
            }
        }

        __syncthreads();
        if (ci + 2 < NIT) load_stage(ci + 2);
    }

    float i0 = 1.0f / l0, i1 = 1.0f / l1;
    size_t r0 = (qrow0 + qrw + gid) * EMB + (size_t)h * HD;
    size_t r1 = (qrow0 + qrw + gid + 8) * EMB + (size_t)h * HD;
#pragma unroll
    for (int t = 0; t < 16; t++) {
        int c = t * 8 + tig * 2;
        __half2 ha = __floats2half2_rn(o[t][0] * i0, o[t][1] * i0);
        __half2 hb = __floats2half2_rn(o[t][2] * i1, o[t][3] * i1);
        *(uint32_t*)(oh + r0 + c) = *(uint32_t*)&ha;
        *(uint32_t*)(oh + r1 + c) = *(uint32_t*)&hb;
    }
}

// ---------------------------------------------------------------------------
// kernel_launch
// ---------------------------------------------------------------------------
extern "C" void kernel_launch(void* const* d_in, const int* in_sizes, int n_in,
                              void* d_out, int out_size)
{
    const float* x  = (const float*)d_in[0];
    const float* Wq = (const float*)d_in[1];
    const float* bq = (const float*)d_in[2];
    const float* Wk = (const float*)d_in[3];
    const float* bk = (const float*)d_in[4];
    const float* Wv = (const float*)d_in[5];
    const float* bv = (const float*)d_in[6];
    const float* Wo = (const float*)d_in[7];
    float* out = (float*)d_out;

    __half *pxh, *pqkv, *pwc, *poh, *pwo;
    float* pbias;
    cudaGetSymbolAddress((void**)&pxh,  g_xh);
    cudaGetSymbolAddress((void**)&pqkv, g_qkv);
    cudaGetSymbolAddress((void**)&pwc,  g_wc);
    cudaGetSymbolAddress((void**)&poh,  g_oh);
    cudaGetSymbolAddress((void**)&pwo,  g_wo);
    cudaGetSymbolAddress((void**)&pbias, g_bias);

    cudaFuncSetAttribute(gemm_f16_kernel<0>,
                         cudaFuncAttributeMaxDynamicSharedMemorySize, G2_SMEM_BYTES);
    cudaFuncSetAttribute(gemm_f16_kernel<1>,
                         cudaFuncAttributeMaxDynamicSharedMemorySize, G2_SMEM_BYTES);
    cudaFuncSetAttribute(flash_mma_kernel,
                         cudaFuncAttributeMaxDynamicSharedMemorySize, FA_SMEM_BYTES);

    const int nx = MROWS * EMB;
    // q pre-scale: log2(e) / sqrt(HD)  (softmax runs in log2 domain)
    const float qscale = 0.088388347648318447f * 1.4426950408889634f;

    // 1) x -> fp16
    to_half_kernel<<<nx / (4 * 256), 256>>>(x, pxh, nx);

    // 2) weights: QKV concat transpose (+fused bias concat); Wo -> fp16
    dim3 tb(32, 8);
    transpose_qkv_kernel<<<dim3(QKVW / 32, EMB / 32), tb>>>(
        Wq, Wk, Wv, pwc, bq, bk, bv, pbias);
    transpose_half_kernel<<<dim3(EMB / 32, EMB / 32), tb>>>(Wo, pwo, EMB, EMB);

    // 3) fused QKV projection, single-product fp16 (Q cols pre-scaled)
    gemm_f16_kernel<0><<<dim3(QKVW / 64, MROWS / 128), 256, G2_SMEM_BYTES>>>(
        pxh, pwc, pbias, pqkv, nullptr, qscale, EMB, MROWS, QKVW, EMB);

    // 4) flash attention (fp16, BM=64, 3 CTAs/SM) -> single fp16 output
    flash_mma_kernel<<<dim3(SEQ / 64, HQ, BATCH), 128, FA_SMEM_BYTES>>>(
        pqkv, poh);

    // 5) output projection: single-product fp16 -> fp32
    gemm_f16_kernel<1><<<dim3(EMB / 64, MROWS / 128), 256, G2_SMEM_BYTES>>>(
        poh, pwo, (const float*)nullptr, nullptr, out, 1.0f, 0,
        MROWS, EMB, EMB);
}